// round 1
// baseline (speedup 1.0000x reference)
#include <cuda_runtime.h>
#include <cuda_bf16.h>
#include <math.h>

// RWKV-4 forward, restructured layer-by-layer:
//   - token-shift + LN computed for the whole sequence per layer
//   - all projections as dense [B*T, D] GEMMs (fp32, tiled)
//   - only the WKV state recurrence is sequential (3072 channels x 256 steps)
//
// Constants
#define Vv 50277
#define Ll 12
#define Dd 768
#define Bb 4
#define Tt 256
#define Ff 3072
#define MM (Bb*Tt)   // 1024

// ---------------- scratch (device globals; no allocation allowed) ----------
__device__ float g_x[MM*Dd];        // residual stream
__device__ float g_xn[MM*Dd];       // LN output (for token shift)
__device__ float g_mix[3*MM*Dd];    // xk/xv/xr (or xk2/xr2)
__device__ float g_kvr[3*MM*Dd];    // k/v/r
__device__ float g_rwkv[MM*Dd];     // sigmoid(r)*wkv
__device__ float g_h[MM*Ff];        // ffn hidden (sq-relu)
__device__ float g_r2[MM*Dd];       // ffn gate

// ---------------- block reduce ----------------
__device__ __forceinline__ float blockReduceSum(float v, float* sh) {
    int lane = threadIdx.x & 31, w = threadIdx.x >> 5;
    #pragma unroll
    for (int o = 16; o; o >>= 1) v += __shfl_xor_sync(0xffffffffu, v, o);
    if (lane == 0) sh[w] = v;
    __syncthreads();
    float r;
    if (threadIdx.x < 8) {
        r = sh[threadIdx.x];
        #pragma unroll
        for (int o = 4; o; o >>= 1) r += __shfl_xor_sync(0x000000ffu, r, o);
        if (threadIdx.x == 0) sh[0] = r;
    }
    __syncthreads();
    r = sh[0];
    __syncthreads();
    return r;
}

// ---------------- LN over rows of D=768, 256 threads/row ----------------
__global__ void ln_kernel(const float* __restrict__ X,
                          const float* __restrict__ w,
                          const float* __restrict__ b,
                          float* __restrict__ Y) {
    __shared__ float sh[8];
    int m = blockIdx.x;
    const float* xr = X + (size_t)m * Dd;
    int i0 = threadIdx.x, i1 = i0 + 256, i2 = i0 + 512;
    float v0 = xr[i0], v1 = xr[i1], v2 = xr[i2];
    float s = blockReduceSum(v0 + v1 + v2, sh);
    float mu = s * (1.0f / 768.0f);
    float c0 = v0 - mu, c1 = v1 - mu, c2 = v2 - mu;
    float ss = blockReduceSum(c0*c0 + c1*c1 + c2*c2, sh);
    float inv = rsqrtf(ss * (1.0f / 768.0f) + 1e-5f);
    float* yr = Y + (size_t)m * Dd;
    yr[i0] = c0 * inv * w[i0] + b[i0];
    yr[i1] = c1 * inv * w[i1] + b[i1];
    yr[i2] = c2 * inv * w[i2] + b[i2];
}

// ---------------- embedding gather + LN (ln0) ----------------
__global__ void embed_ln_kernel(const int* __restrict__ tokens,
                                const float* __restrict__ emb,
                                const float* __restrict__ w,
                                const float* __restrict__ b,
                                float* __restrict__ Y) {
    __shared__ float sh[8];
    int m = blockIdx.x;
    int tok = tokens[m];
    const float* xr = emb + (size_t)tok * Dd;
    int i0 = threadIdx.x, i1 = i0 + 256, i2 = i0 + 512;
    float v0 = xr[i0], v1 = xr[i1], v2 = xr[i2];
    float s = blockReduceSum(v0 + v1 + v2, sh);
    float mu = s * (1.0f / 768.0f);
    float c0 = v0 - mu, c1 = v1 - mu, c2 = v2 - mu;
    float ss = blockReduceSum(c0*c0 + c1*c1 + c2*c2, sh);
    float inv = rsqrtf(ss * (1.0f / 768.0f) + 1e-5f);
    float* yr = Y + (size_t)m * Dd;
    yr[i0] = c0 * inv * w[i0] + b[i0];
    yr[i1] = c1 * inv * w[i1] + b[i1];
    yr[i2] = c2 * inv * w[i2] + b[i2];
}

// ---------------- token-shift mixes ----------------
__global__ void mix3_kernel(const float* __restrict__ xn,
                            const float* __restrict__ mk,
                            const float* __restrict__ mv,
                            const float* __restrict__ mr,
                            float* __restrict__ xk,
                            float* __restrict__ xv,
                            float* __restrict__ xr) {
    int idx = blockIdx.x * 256 + threadIdx.x;   // < MM*Dd
    int d = idx % Dd;
    int m = idx / Dd;
    int t = m % Tt;
    float cur = xn[idx];
    float prev = (t > 0) ? xn[idx - Dd] : 0.0f;
    float a = mk[d], c = mv[d], e = mr[d];
    xk[idx] = cur * a + prev * (1.0f - a);
    xv[idx] = cur * c + prev * (1.0f - c);
    xr[idx] = cur * e + prev * (1.0f - e);
}

__global__ void mix2_kernel(const float* __restrict__ xn,
                            const float* __restrict__ mk,
                            const float* __restrict__ mr,
                            float* __restrict__ xk,
                            float* __restrict__ xr) {
    int idx = blockIdx.x * 256 + threadIdx.x;
    int d = idx % Dd;
    int m = idx / Dd;
    int t = m % Tt;
    float cur = xn[idx];
    float prev = (t > 0) ? xn[idx - Dd] : 0.0f;
    float a = mk[d], e = mr[d];
    xk[idx] = cur * a + prev * (1.0f - a);
    xr[idx] = cur * e + prev * (1.0f - e);
}

// ---------------- WKV sequential recurrence (per-channel) ----------------
__global__ void wkv_kernel(const float* __restrict__ k,
                           const float* __restrict__ v,
                           const float* __restrict__ r,
                           const float* __restrict__ tf,
                           const float* __restrict__ td,
                           float* __restrict__ out) {
    int ch = blockIdx.x * blockDim.x + threadIdx.x;   // < Bb*Dd
    if (ch >= Bb * Dd) return;
    int b = ch / Dd, d = ch % Dd;
    float tfd = tf[d], tdd = td[d];
    float aa = 0.0f, bb = 0.0f, pp = -1e30f;
    size_t base = (size_t)b * Tt * Dd + d;
    // software-pipelined loads (hide L2 latency)
    float kc = k[base], vc = v[base], rc = r[base];
    for (int t = 0; t < Tt; t++) {
        float kn = 0.f, vn = 0.f, rn = 0.f;
        if (t + 1 < Tt) {
            size_t nb = base + (size_t)(t + 1) * Dd;
            kn = k[nb]; vn = v[nb]; rn = r[nb];
        }
        float ww = tfd + kc;
        float p  = fmaxf(pp, ww);
        float e1 = expf(pp - p);
        float e2 = expf(ww - p);
        float wkv = (e1 * aa + e2 * vc) / (e1 * bb + e2);
        float sr = 1.0f / (1.0f + expf(-rc));
        out[base + (size_t)t * Dd] = sr * wkv;
        float ww2 = pp + tdd;
        float p2  = fmaxf(ww2, kc);
        float e1b = expf(ww2 - p2);
        float e2b = expf(kc - p2);
        aa = e1b * aa + e2b * vc;
        bb = e1b * bb + e2b;
        pp = p2;
        kc = kn; vc = vn; rc = rn;
    }
}

// ---------------- tiled SGEMM: C(opt epilogue) = A[M,K] @ W[K,N] ----------
// BM=128, BN=64, BK=16, 256 threads, 8x4 outputs per thread.
// Epilogues: 0=store, 1=C+=acc, 2=sqrelu, 3=sigmoid, 4=C+=G*acc
struct GPtrs {
    const float* A[3];
    const float* W[3];
    float*       C[3];
    const float* G;
};

#define GBM 128
#define GBN 64
#define GBK 16

template<int EPI>
__global__ __launch_bounds__(256)
void sgemm_kernel(GPtrs p, int Mg, int Ng, int Kg) {
    const float* __restrict__ A = p.A[blockIdx.z];
    const float* __restrict__ W = p.W[blockIdx.z];
    float* __restrict__       C = p.C[blockIdx.z];
    const float* __restrict__ G = p.G;

    __shared__ float As[GBK][GBM + 8];   // stride 136 floats (16B-aligned rows)
    __shared__ float Bs[GBK][GBN + 8];   // stride 72 floats

    int tid = threadIdx.x;
    int tx = tid & 15;       // n-dir group (4 cols each)
    int ty = tid >> 4;       // m-dir group (8 rows each)
    int m0 = blockIdx.y * GBM;
    int n0 = blockIdx.x * GBN;

    int arow = tid >> 2;           // 0..63
    int acol = (tid & 3) << 2;     // 0,4,8,12
    int brow = tid >> 4;           // 0..15
    int bcol = (tid & 15) << 2;    // 0..60

    float acc[8][4] = {};

    for (int k0 = 0; k0 < Kg; k0 += GBK) {
        float4 a0 = *(const float4*)(A + (size_t)(m0 + arow)      * Kg + k0 + acol);
        float4 a1 = *(const float4*)(A + (size_t)(m0 + arow + 64) * Kg + k0 + acol);
        float4 b0 = *(const float4*)(W + (size_t)(k0 + brow)      * Ng + n0 + bcol);
        As[acol + 0][arow] = a0.x;
        As[acol + 1][arow] = a0.y;
        As[acol + 2][arow] = a0.z;
        As[acol + 3][arow] = a0.w;
        As[acol + 0][arow + 64] = a1.x;
        As[acol + 1][arow + 64] = a1.y;
        As[acol + 2][arow + 64] = a1.z;
        As[acol + 3][arow + 64] = a1.w;
        *(float4*)&Bs[brow][bcol] = b0;
        __syncthreads();

        #pragma unroll
        for (int kk = 0; kk < GBK; kk++) {
            float4 aA = *(const float4*)&As[kk][ty * 8];
            float4 aB = *(const float4*)&As[kk][ty * 8 + 4];
            float4 bb4 = *(const float4*)&Bs[kk][tx * 4];
            float av[8] = {aA.x, aA.y, aA.z, aA.w, aB.x, aB.y, aB.z, aB.w};
            float bv[4] = {bb4.x, bb4.y, bb4.z, bb4.w};
            #pragma unroll
            for (int i = 0; i < 8; i++)
                #pragma unroll
                for (int j = 0; j < 4; j++)
                    acc[i][j] = fmaf(av[i], bv[j], acc[i][j]);
        }
        __syncthreads();
    }

    #pragma unroll
    for (int i = 0; i < 8; i++) {
        int m = m0 + ty * 8 + i;
        #pragma unroll
        for (int j = 0; j < 4; j++) {
            int n = n0 + tx * 4 + j;
            size_t idx = (size_t)m * Ng + n;
            float val = acc[i][j];
            if (EPI == 0) {
                C[idx] = val;
            } else if (EPI == 1) {
                C[idx] += val;
            } else if (EPI == 2) {
                float t0 = fmaxf(val, 0.0f);
                C[idx] = t0 * t0;
            } else if (EPI == 3) {
                C[idx] = 1.0f / (1.0f + expf(-val));
            } else if (EPI == 4) {
                C[idx] += G[idx] * val;
            }
        }
    }
}

// ---------------- host launcher ----------------
extern "C" void kernel_launch(void* const* d_in, const int* in_sizes, int n_in,
                              void* d_out, int out_size) {
    const int*   tokens     = (const int*)  d_in[0];
    const float* emb        = (const float*)d_in[1];
    const float* ln0_w      = (const float*)d_in[2];
    const float* ln0_b      = (const float*)d_in[3];
    const float* ln1_w      = (const float*)d_in[4];
    const float* ln1_b      = (const float*)d_in[5];
    const float* ln2_w      = (const float*)d_in[6];
    const float* ln2_b      = (const float*)d_in[7];
    const float* att_mix_k  = (const float*)d_in[8];
    const float* att_mix_v  = (const float*)d_in[9];
    const float* att_mix_r  = (const float*)d_in[10];
    const float* time_first = (const float*)d_in[11];
    const float* time_decay = (const float*)d_in[12];
    const float* att_Wk     = (const float*)d_in[13];
    const float* att_Wv     = (const float*)d_in[14];
    const float* att_Wr     = (const float*)d_in[15];
    const float* att_Wo     = (const float*)d_in[16];
    const float* ffn_mix_k  = (const float*)d_in[17];
    const float* ffn_mix_r  = (const float*)d_in[18];
    const float* ffn_Wk     = (const float*)d_in[19];
    const float* ffn_Wv     = (const float*)d_in[20];
    const float* ffn_Wr     = (const float*)d_in[21];
    const float* lnout_w    = (const float*)d_in[22];
    const float* lnout_b    = (const float*)d_in[23];
    float* out = (float*)d_out;

    float *x, *xn, *mix, *kvr, *rwkv, *h, *r2;
    cudaGetSymbolAddress((void**)&x,    g_x);
    cudaGetSymbolAddress((void**)&xn,   g_xn);
    cudaGetSymbolAddress((void**)&mix,  g_mix);
    cudaGetSymbolAddress((void**)&kvr,  g_kvr);
    cudaGetSymbolAddress((void**)&rwkv, g_rwkv);
    cudaGetSymbolAddress((void**)&h,    g_h);
    cudaGetSymbolAddress((void**)&r2,   g_r2);

    const int MD = MM * Dd;

    // x = LN0(emb[tokens])
    embed_ln_kernel<<<MM, 256>>>(tokens, emb, ln0_w, ln0_b, x);

    for (int l = 0; l < Ll; l++) {
        const float* l1w = ln1_w + l * Dd;
        const float* l1b = ln1_b + l * Dd;
        const float* l2w = ln2_w + l * Dd;
        const float* l2b = ln2_b + l * Dd;

        // ---- time mixing ----
        ln_kernel<<<MM, 256>>>(x, l1w, l1b, xn);
        mix3_kernel<<<MD / 256, 256>>>(xn,
            att_mix_k + l * Dd, att_mix_v + l * Dd, att_mix_r + l * Dd,
            mix, mix + MD, mix + 2 * MD);

        // k/v/r = mix @ {Wk,Wv,Wr}   (batched over blockIdx.z)
        {
            GPtrs p{};
            p.A[0] = mix;           p.W[0] = att_Wk + (size_t)l * Dd * Dd; p.C[0] = kvr;
            p.A[1] = mix + MD;      p.W[1] = att_Wv + (size_t)l * Dd * Dd; p.C[1] = kvr + MD;
            p.A[2] = mix + 2 * MD;  p.W[2] = att_Wr + (size_t)l * Dd * Dd; p.C[2] = kvr + 2 * MD;
            p.G = nullptr;
            dim3 grid(Dd / GBN, MM / GBM, 3);
            sgemm_kernel<0><<<grid, 256>>>(p, MM, Dd, Dd);
        }

        // sequential WKV over T, gated by sigmoid(r)
        wkv_kernel<<<(Bb * Dd) / 256, 256>>>(kvr, kvr + MD, kvr + 2 * MD,
                                             time_first + l * Dd, time_decay + l * Dd,
                                             rwkv);

        // x += rwkv @ Wo
        {
            GPtrs p{};
            p.A[0] = rwkv; p.W[0] = att_Wo + (size_t)l * Dd * Dd; p.C[0] = x; p.G = nullptr;
            dim3 grid(Dd / GBN, MM / GBM, 1);
            sgemm_kernel<1><<<grid, 256>>>(p, MM, Dd, Dd);
        }

        // ---- channel mixing ----
        ln_kernel<<<MM, 256>>>(x, l2w, l2b, xn);
        mix2_kernel<<<MD / 256, 256>>>(xn,
            ffn_mix_k + l * Dd, ffn_mix_r + l * Dd,
            mix, mix + MD);

        // h = sqrelu(xk2 @ ffn_Wk)   [1024,768]x[768,3072]
        {
            GPtrs p{};
            p.A[0] = mix; p.W[0] = ffn_Wk + (size_t)l * Dd * Ff; p.C[0] = h; p.G = nullptr;
            dim3 grid(Ff / GBN, MM / GBM, 1);
            sgemm_kernel<2><<<grid, 256>>>(p, MM, Ff, Dd);
        }
        // r2 = sigmoid(xr2 @ ffn_Wr)
        {
            GPtrs p{};
            p.A[0] = mix + MD; p.W[0] = ffn_Wr + (size_t)l * Dd * Dd; p.C[0] = r2; p.G = nullptr;
            dim3 grid(Dd / GBN, MM / GBM, 1);
            sgemm_kernel<3><<<grid, 256>>>(p, MM, Dd, Dd);
        }
        // x += r2 * (h @ ffn_Wv)   [1024,3072]x[3072,768]
        {
            GPtrs p{};
            p.A[0] = h; p.W[0] = ffn_Wv + (size_t)l * Ff * Dd; p.C[0] = x; p.G = r2;
            dim3 grid(Dd / GBN, MM / GBM, 1);
            sgemm_kernel<4><<<grid, 256>>>(p, MM, Dd, Ff);
        }
    }

    // out = LN_out(x)
    ln_kernel<<<MM, 256>>>(x, lnout_w, lnout_b, out);
}

// round 2
// speedup vs baseline: 1.1068x; 1.1068x over previous
#include <cuda_runtime.h>
#include <cuda_bf16.h>
#include <mma.h>
#include <math.h>

using namespace nvcuda;

// Constants
#define Vv 50277
#define Ll 12
#define Dd 768
#define Bb 4
#define Tt 256
#define Ff 3072
#define MM (Bb*Tt)   // 1024

// ---------------- scratch (device globals; no allocation allowed) ----------
__device__ __align__(256) float g_x[MM*Dd];        // residual stream
__device__ __align__(256) float g_xn[MM*Dd];       // LN output (token-shift source)
__device__ __align__(256) float g_kvr[3*MM*Dd];    // k/v/r
__device__ __align__(256) float g_rwkv[MM*Dd];     // sigmoid(r)*wkv
__device__ __align__(256) float g_h[MM*Ff];        // ffn hidden (sq-relu)
__device__ __align__(256) float g_r2[MM*Dd];       // ffn gate

// ---------------- block reduce ----------------
__device__ __forceinline__ float blockReduceSum(float v, float* sh) {
    int lane = threadIdx.x & 31, w = threadIdx.x >> 5;
    #pragma unroll
    for (int o = 16; o; o >>= 1) v += __shfl_xor_sync(0xffffffffu, v, o);
    if (lane == 0) sh[w] = v;
    __syncthreads();
    float r;
    if (threadIdx.x < 8) {
        r = sh[threadIdx.x];
        #pragma unroll
        for (int o = 4; o; o >>= 1) r += __shfl_xor_sync(0x000000ffu, r, o);
        if (threadIdx.x == 0) sh[0] = r;
    }
    __syncthreads();
    r = sh[0];
    __syncthreads();
    return r;
}

// ---------------- LN over rows of D=768, 256 threads/row ----------------
__global__ void ln_kernel(const float* __restrict__ X,
                          const float* __restrict__ w,
                          const float* __restrict__ b,
                          float* __restrict__ Y) {
    __shared__ float sh[8];
    int m = blockIdx.x;
    const float* xr = X + (size_t)m * Dd;
    int i0 = threadIdx.x, i1 = i0 + 256, i2 = i0 + 512;
    float v0 = xr[i0], v1 = xr[i1], v2 = xr[i2];
    float s = blockReduceSum(v0 + v1 + v2, sh);
    float mu = s * (1.0f / 768.0f);
    float c0 = v0 - mu, c1 = v1 - mu, c2 = v2 - mu;
    float ss = blockReduceSum(c0*c0 + c1*c1 + c2*c2, sh);
    float inv = rsqrtf(ss * (1.0f / 768.0f) + 1e-5f);
    float* yr = Y + (size_t)m * Dd;
    yr[i0] = c0 * inv * w[i0] + b[i0];
    yr[i1] = c1 * inv * w[i1] + b[i1];
    yr[i2] = c2 * inv * w[i2] + b[i2];
}

// ---------------- embedding gather + LN (ln0) ----------------
__global__ void embed_ln_kernel(const int* __restrict__ tokens,
                                const float* __restrict__ emb,
                                const float* __restrict__ w,
                                const float* __restrict__ b,
                                float* __restrict__ Y) {
    __shared__ float sh[8];
    int m = blockIdx.x;
    int tok = tokens[m];
    const float* xr = emb + (size_t)tok * Dd;
    int i0 = threadIdx.x, i1 = i0 + 256, i2 = i0 + 512;
    float v0 = xr[i0], v1 = xr[i1], v2 = xr[i2];
    float s = blockReduceSum(v0 + v1 + v2, sh);
    float mu = s * (1.0f / 768.0f);
    float c0 = v0 - mu, c1 = v1 - mu, c2 = v2 - mu;
    float ss = blockReduceSum(c0*c0 + c1*c1 + c2*c2, sh);
    float inv = rsqrtf(ss * (1.0f / 768.0f) + 1e-5f);
    float* yr = Y + (size_t)m * Dd;
    yr[i0] = c0 * inv * w[i0] + b[i0];
    yr[i1] = c1 * inv * w[i1] + b[i1];
    yr[i2] = c2 * inv * w[i2] + b[i2];
}

// ---------------- WKV sequential recurrence (per-channel) ----------------
__global__ void wkv_kernel(const float* __restrict__ k,
                           const float* __restrict__ v,
                           const float* __restrict__ r,
                           const float* __restrict__ tf,
                           const float* __restrict__ td,
                           float* __restrict__ out) {
    int ch = blockIdx.x * blockDim.x + threadIdx.x;   // < Bb*Dd
    if (ch >= Bb * Dd) return;
    int b = ch / Dd, d = ch % Dd;
    float tfd = tf[d], tdd = td[d];
    float aa = 0.0f, bb = 0.0f, pp = -1e30f;
    size_t base = (size_t)b * Tt * Dd + d;
    float kc = k[base], vc = v[base], rc = r[base];
    for (int t = 0; t < Tt; t++) {
        float kn = 0.f, vn = 0.f, rn = 0.f;
        if (t + 1 < Tt) {
            size_t nb = base + (size_t)(t + 1) * Dd;
            kn = k[nb]; vn = v[nb]; rn = r[nb];
        }
        float ww = tfd + kc;
        float p  = fmaxf(pp, ww);
        float e1 = expf(pp - p);
        float e2 = expf(ww - p);
        float wkv = (e1 * aa + e2 * vc) / (e1 * bb + e2);
        float sr = 1.0f / (1.0f + expf(-rc));
        out[base + (size_t)t * Dd] = sr * wkv;
        float ww2 = pp + tdd;
        float p2  = fmaxf(ww2, kc);
        float e1b = expf(ww2 - p2);
        float e2b = expf(kc - p2);
        aa = e1b * aa + e2b * vc;
        bb = e1b * bb + e2b;
        pp = p2;
        kc = kn; vc = vn; rc = rn;
    }
}

// ---------------- tensor-core GEMM (bf16 2-term split, fp32 acc) ---------
// C[M,N] = A[M,K] @ W[K,N] with near-fp32 precision:
//   a = ah + al (bf16 split), b = bh + bl;  acc += ah*bh + ah*bl + al*bh
// BM=128, BN=64, BK=32, 256 threads = 8 warps (4m x 2n), warp tile 32x32.
// MIXA: A-tile computed on the fly as token-shift mix of xn rows.
// Epilogues: 0=store, 1=C+=acc, 2=sqrelu, 3=sigmoid, 4=C+=G*acc
struct GPtrs {
    const float* A[3];
    const float* W[3];
    float*       C[3];
    const float* Mx[3];
    const float* G;
};

#define GBM 128
#define GBN 64
#define GBK 32
#define APAD 8   // A smem row stride 40 halves (80B): conflict-free ldmatrix
#define BPAD 8   // B smem row stride 72 halves (144B)

union SmemU {
    struct {
        __nv_bfloat16 Ah[GBM][GBK + APAD];
        __nv_bfloat16 Al[GBM][GBK + APAD];
        __nv_bfloat16 Bh[GBK][GBN + BPAD];
        __nv_bfloat16 Bl[GBK][GBN + BPAD];
    } s;
    float C[GBM][GBN + 4];
};

__device__ __forceinline__ void split_bf16(float x, __nv_bfloat16& h, __nv_bfloat16& l) {
    h = __float2bfloat16(x);
    l = __float2bfloat16(x - __bfloat162float(h));
}

template<int EPI, bool MIXA>
__global__ __launch_bounds__(256)
void gemm_tc_kernel(GPtrs p, int Ng, int Kg) {
    const int bz = blockIdx.z;
    const float* __restrict__ A  = p.A[bz];
    const float* __restrict__ W  = p.W[bz];
    float* __restrict__       C  = p.C[bz];
    const float* __restrict__ Mx = p.Mx[bz];
    const float* __restrict__ G  = p.G;

    __shared__ __align__(32) SmemU sm;

    const int tid = threadIdx.x;
    const int wid = tid >> 5;
    const int wm  = wid >> 1;        // 0..3
    const int wn  = wid & 1;         // 0..1
    const int m0  = blockIdx.y * GBM;
    const int n0  = blockIdx.x * GBN;

    wmma::fragment<wmma::accumulator, 16, 16, 16, float> acc[2][2];
    #pragma unroll
    for (int i = 0; i < 2; i++)
        #pragma unroll
        for (int j = 0; j < 2; j++)
            wmma::fill_fragment(acc[i][j], 0.0f);

    const int arow_ = tid >> 3;          // 0..31 (per pass of 32 rows)
    const int acol  = (tid & 7) << 2;    // 0..28 step 4
    const int brow_ = tid >> 4;          // 0..15 (per pass of 16 rows)
    const int bcol  = (tid & 15) << 2;   // 0..60 step 4

    for (int k0 = 0; k0 < Kg; k0 += GBK) {
        // ---- load + convert A tile (optionally fused token-shift mix) ----
        float4 mx4;
        if (MIXA) mx4 = *(const float4*)(Mx + k0 + acol);
        #pragma unroll
        for (int pp = 0; pp < 4; pp++) {
            int r = pp * 32 + arow_;
            int m = m0 + r;
            float4 av = *(const float4*)(A + (size_t)m * Kg + k0 + acol);
            float4 xv;
            if (MIXA) {
                float4 pv = make_float4(0.f, 0.f, 0.f, 0.f);
                if ((m & (Tt - 1)) != 0)
                    pv = *(const float4*)(A + (size_t)(m - 1) * Kg + k0 + acol);
                xv.x = av.x * mx4.x + pv.x * (1.0f - mx4.x);
                xv.y = av.y * mx4.y + pv.y * (1.0f - mx4.y);
                xv.z = av.z * mx4.z + pv.z * (1.0f - mx4.z);
                xv.w = av.w * mx4.w + pv.w * (1.0f - mx4.w);
            } else {
                xv = av;
            }
            split_bf16(xv.x, sm.s.Ah[r][acol + 0], sm.s.Al[r][acol + 0]);
            split_bf16(xv.y, sm.s.Ah[r][acol + 1], sm.s.Al[r][acol + 1]);
            split_bf16(xv.z, sm.s.Ah[r][acol + 2], sm.s.Al[r][acol + 2]);
            split_bf16(xv.w, sm.s.Ah[r][acol + 3], sm.s.Al[r][acol + 3]);
        }
        // ---- load + convert B tile ----
        #pragma unroll
        for (int pp = 0; pp < 2; pp++) {
            int r = pp * 16 + brow_;
            float4 bv = *(const float4*)(W + (size_t)(k0 + r) * Ng + n0 + bcol);
            split_bf16(bv.x, sm.s.Bh[r][bcol + 0], sm.s.Bl[r][bcol + 0]);
            split_bf16(bv.y, sm.s.Bh[r][bcol + 1], sm.s.Bl[r][bcol + 1]);
            split_bf16(bv.z, sm.s.Bh[r][bcol + 2], sm.s.Bl[r][bcol + 2]);
            split_bf16(bv.w, sm.s.Bh[r][bcol + 3], sm.s.Bl[r][bcol + 3]);
        }
        __syncthreads();

        // ---- MMA over the two k16 sub-steps ----
        #pragma unroll
        for (int kk = 0; kk < GBK; kk += 16) {
            wmma::fragment<wmma::matrix_a, 16, 16, 16, __nv_bfloat16, wmma::row_major> ah[2], al[2];
            wmma::fragment<wmma::matrix_b, 16, 16, 16, __nv_bfloat16, wmma::row_major> bh[2], bl[2];
            #pragma unroll
            for (int i = 0; i < 2; i++) {
                wmma::load_matrix_sync(ah[i], &sm.s.Ah[wm * 32 + i * 16][kk], GBK + APAD);
                wmma::load_matrix_sync(al[i], &sm.s.Al[wm * 32 + i * 16][kk], GBK + APAD);
            }
            #pragma unroll
            for (int j = 0; j < 2; j++) {
                wmma::load_matrix_sync(bh[j], &sm.s.Bh[kk][wn * 32 + j * 16], GBN + BPAD);
                wmma::load_matrix_sync(bl[j], &sm.s.Bl[kk][wn * 32 + j * 16], GBN + BPAD);
            }
            #pragma unroll
            for (int i = 0; i < 2; i++)
                #pragma unroll
                for (int j = 0; j < 2; j++) {
                    wmma::mma_sync(acc[i][j], ah[i], bh[j], acc[i][j]);
                    wmma::mma_sync(acc[i][j], ah[i], bl[j], acc[i][j]);
                    wmma::mma_sync(acc[i][j], al[i], bh[j], acc[i][j]);
                }
        }
        __syncthreads();
    }

    // ---- epilogue via smem ----
    #pragma unroll
    for (int i = 0; i < 2; i++)
        #pragma unroll
        for (int j = 0; j < 2; j++)
            wmma::store_matrix_sync(&sm.C[wm * 32 + i * 16][wn * 32 + j * 16],
                                    acc[i][j], GBN + 4, wmma::mem_row_major);
    __syncthreads();

    const int ecol = tid & 63;
    const int erow0 = tid >> 6;   // 0..3
    #pragma unroll
    for (int i = 0; i < 32; i++) {
        int r = i * 4 + erow0;
        int m = m0 + r;
        int n = n0 + ecol;
        size_t idx = (size_t)m * Ng + n;
        float val = sm.C[r][ecol];
        if (EPI == 0) {
            C[idx] = val;
        } else if (EPI == 1) {
            C[idx] += val;
        } else if (EPI == 2) {
            float t0 = fmaxf(val, 0.0f);
            C[idx] = t0 * t0;
        } else if (EPI == 3) {
            C[idx] = 1.0f / (1.0f + expf(-val));
        } else if (EPI == 4) {
            C[idx] += G[idx] * val;
        }
    }
}

// ---------------- host launcher ----------------
extern "C" void kernel_launch(void* const* d_in, const int* in_sizes, int n_in,
                              void* d_out, int out_size) {
    const int*   tokens     = (const int*)  d_in[0];
    const float* emb        = (const float*)d_in[1];
    const float* ln0_w      = (const float*)d_in[2];
    const float* ln0_b      = (const float*)d_in[3];
    const float* ln1_w      = (const float*)d_in[4];
    const float* ln1_b      = (const float*)d_in[5];
    const float* ln2_w      = (const float*)d_in[6];
    const float* ln2_b      = (const float*)d_in[7];
    const float* att_mix_k  = (const float*)d_in[8];
    const float* att_mix_v  = (const float*)d_in[9];
    const float* att_mix_r  = (const float*)d_in[10];
    const float* time_first = (const float*)d_in[11];
    const float* time_decay = (const float*)d_in[12];
    const float* att_Wk     = (const float*)d_in[13];
    const float* att_Wv     = (const float*)d_in[14];
    const float* att_Wr     = (const float*)d_in[15];
    const float* att_Wo     = (const float*)d_in[16];
    const float* ffn_mix_k  = (const float*)d_in[17];
    const float* ffn_mix_r  = (const float*)d_in[18];
    const float* ffn_Wk     = (const float*)d_in[19];
    const float* ffn_Wv     = (const float*)d_in[20];
    const float* ffn_Wr     = (const float*)d_in[21];
    const float* lnout_w    = (const float*)d_in[22];
    const float* lnout_b    = (const float*)d_in[23];
    float* out = (float*)d_out;

    float *x, *xn, *kvr, *rwkv, *h, *r2;
    cudaGetSymbolAddress((void**)&x,    g_x);
    cudaGetSymbolAddress((void**)&xn,   g_xn);
    cudaGetSymbolAddress((void**)&kvr,  g_kvr);
    cudaGetSymbolAddress((void**)&rwkv, g_rwkv);
    cudaGetSymbolAddress((void**)&h,    g_h);
    cudaGetSymbolAddress((void**)&r2,   g_r2);

    const int MD = MM * Dd;

    // x = LN0(emb[tokens])
    embed_ln_kernel<<<MM, 256>>>(tokens, emb, ln0_w, ln0_b, x);

    for (int l = 0; l < Ll; l++) {
        // ---- time mixing ----
        ln_kernel<<<MM, 256>>>(x, ln1_w + l * Dd, ln1_b + l * Dd, xn);

        // k/v/r = mix(xn) @ {Wk,Wv,Wr}   (fused token-shift mix; batched z)
        {
            GPtrs p{};
            p.A[0] = xn; p.W[0] = att_Wk + (size_t)l * Dd * Dd; p.C[0] = kvr;          p.Mx[0] = att_mix_k + l * Dd;
            p.A[1] = xn; p.W[1] = att_Wv + (size_t)l * Dd * Dd; p.C[1] = kvr + MD;     p.Mx[1] = att_mix_v + l * Dd;
            p.A[2] = xn; p.W[2] = att_Wr + (size_t)l * Dd * Dd; p.C[2] = kvr + 2 * MD; p.Mx[2] = att_mix_r + l * Dd;
            dim3 grid(Dd / GBN, MM / GBM, 3);
            gemm_tc_kernel<0, true><<<grid, 256>>>(p, Dd, Dd);
        }

        // sequential WKV over T, gated by sigmoid(r)
        wkv_kernel<<<(Bb * Dd) / 256, 256>>>(kvr, kvr + MD, kvr + 2 * MD,
                                             time_first + l * Dd, time_decay + l * Dd,
                                             rwkv);

        // x += rwkv @ Wo
        {
            GPtrs p{};
            p.A[0] = rwkv; p.W[0] = att_Wo + (size_t)l * Dd * Dd; p.C[0] = x;
            dim3 grid(Dd / GBN, MM / GBM, 1);
            gemm_tc_kernel<1, false><<<grid, 256>>>(p, Dd, Dd);
        }

        // ---- channel mixing ----
        ln_kernel<<<MM, 256>>>(x, ln2_w + l * Dd, ln2_b + l * Dd, xn);

        // h = sqrelu(mix_k(xn) @ ffn_Wk)   [1024,768]x[768,3072]
        {
            GPtrs p{};
            p.A[0] = xn; p.W[0] = ffn_Wk + (size_t)l * Dd * Ff; p.C[0] = h; p.Mx[0] = ffn_mix_k + l * Dd;
            dim3 grid(Ff / GBN, MM / GBM, 1);
            gemm_tc_kernel<2, true><<<grid, 256>>>(p, Ff, Dd);
        }
        // r2 = sigmoid(mix_r(xn) @ ffn_Wr)
        {
            GPtrs p{};
            p.A[0] = xn; p.W[0] = ffn_Wr + (size_t)l * Dd * Dd; p.C[0] = r2; p.Mx[0] = ffn_mix_r + l * Dd;
            dim3 grid(Dd / GBN, MM / GBM, 1);
            gemm_tc_kernel<3, true><<<grid, 256>>>(p, Dd, Dd);
        }
        // x += r2 * (h @ ffn_Wv)   [1024,3072]x[3072,768]
        {
            GPtrs p{};
            p.A[0] = h; p.W[0] = ffn_Wv + (size_t)l * Ff * Dd; p.C[0] = x; p.G = r2;
            dim3 grid(Dd / GBN, MM / GBM, 1);
            gemm_tc_kernel<4, false><<<grid, 256>>>(p, Dd, Ff);
        }
    }

    // out = LN_out(x)
    ln_kernel<<<MM, 256>>>(x, lnout_w, lnout_b, out);
}

// round 4
// speedup vs baseline: 1.9195x; 1.7344x over previous
#include <cuda_runtime.h>
#include <cuda_bf16.h>
#include <mma.h>
#include <math.h>
#include <cstdint>

using namespace nvcuda;

// Constants
#define Vv 50277
#define Ll 12
#define Dd 768
#define Bb 4
#define Tt 256
#define Ff 3072
#define MM (Bb*Tt)   // 1024
#define MD (MM*Dd)

// converted-weight offsets (elements)
#define NDD (Ll*Dd*Dd)      // 7077888
#define NDF (Ll*Dd*Ff)      // 28311552
#define OFF_WK 0
#define OFF_WV (NDD)
#define OFF_WR (2*NDD)
#define OFF_WO (3*NDD)
#define OFF_FK (4*NDD)
#define OFF_FV (4*NDD + NDF)
#define OFF_FR (4*NDD + 2*NDF)
#define NWTOT  (4*NDD + 2*NDF + NDD)   // 92012544

// ---------------- scratch (device globals; no allocation allowed) ----------
__device__ __align__(256) float g_x[MD];                 // residual stream
__device__ __align__(256) float g_xn[MD];                // LN output
__device__ __align__(256) float g_kvr[3*MD];             // k/v/r fp32
__device__ __align__(256) float g_r2[MD];                // ffn gate fp32
__device__ __align__(256) __nv_bfloat16 g_mixh[3*MD];    // mixed activations hi
__device__ __align__(256) __nv_bfloat16 g_mixl[3*MD];    // mixed activations lo
__device__ __align__(256) __nv_bfloat16 g_rwkvh[MD];
__device__ __align__(256) __nv_bfloat16 g_rwkvl[MD];
__device__ __align__(256) __nv_bfloat16 g_hh[MM*Ff];
__device__ __align__(256) __nv_bfloat16 g_hl[MM*Ff];
__device__ __align__(256) __nv_bfloat16 g_wh[NWTOT];     // weights hi
__device__ __align__(256) __nv_bfloat16 g_wl[NWTOT];     // weights lo

__device__ __forceinline__ void split_bf16(float x, __nv_bfloat16& h, __nv_bfloat16& l) {
    h = __float2bfloat16(x);
    l = __float2bfloat16(x - __bfloat162float(h));
}

// ---------------- cp.async helpers ----------------
__device__ __forceinline__ void cpa16(void* dst, const void* src) {
    unsigned d = (unsigned)__cvta_generic_to_shared(dst);
    asm volatile("cp.async.cg.shared.global [%0], [%1], 16;" :: "r"(d), "l"(src));
}
__device__ __forceinline__ void cp_commit() { asm volatile("cp.async.commit_group;"); }
template<int N> __device__ __forceinline__ void cp_wait() {
    asm volatile("cp.async.wait_group %0;" :: "n"(N));
}

// ---------------- weight split preconversion ----------------
__global__ void split_w_kernel(const float4* __restrict__ W,
                               __nv_bfloat162* __restrict__ hi,
                               __nv_bfloat162* __restrict__ lo, int n4) {
    int i = blockIdx.x * 256 + threadIdx.x;
    if (i >= n4) return;
    float4 w = W[i];
    __nv_bfloat16 h0, h1, h2, h3, l0, l1, l2, l3;
    split_bf16(w.x, h0, l0);
    split_bf16(w.y, h1, l1);
    split_bf16(w.z, h2, l2);
    split_bf16(w.w, h3, l3);
    hi[2*i]   = __halves2bfloat162(h0, h1);
    hi[2*i+1] = __halves2bfloat162(h2, h3);
    lo[2*i]   = __halves2bfloat162(l0, l1);
    lo[2*i+1] = __halves2bfloat162(l2, l3);
}

// ---------------- block reduce ----------------
__device__ __forceinline__ float blockReduceSum(float v, float* sh) {
    int lane = threadIdx.x & 31, w = threadIdx.x >> 5;
    #pragma unroll
    for (int o = 16; o; o >>= 1) v += __shfl_xor_sync(0xffffffffu, v, o);
    if (lane == 0) sh[w] = v;
    __syncthreads();
    float r;
    if (threadIdx.x < 8) {
        r = sh[threadIdx.x];
        #pragma unroll
        for (int o = 4; o; o >>= 1) r += __shfl_xor_sync(0x000000ffu, r, o);
        if (threadIdx.x == 0) sh[0] = r;
    }
    __syncthreads();
    r = sh[0];
    __syncthreads();
    return r;
}

// ---------------- LN over rows of D=768, 256 threads/row ----------------
__global__ void ln_kernel(const float* __restrict__ X,
                          const float* __restrict__ w,
                          const float* __restrict__ b,
                          float* __restrict__ Y) {
    __shared__ float sh[8];
    int m = blockIdx.x;
    const float* xr = X + (size_t)m * Dd;
    int i0 = threadIdx.x, i1 = i0 + 256, i2 = i0 + 512;
    float v0 = xr[i0], v1 = xr[i1], v2 = xr[i2];
    float s = blockReduceSum(v0 + v1 + v2, sh);
    float mu = s * (1.0f / 768.0f);
    float c0 = v0 - mu, c1 = v1 - mu, c2 = v2 - mu;
    float ss = blockReduceSum(c0*c0 + c1*c1 + c2*c2, sh);
    float inv = rsqrtf(ss * (1.0f / 768.0f) + 1e-5f);
    float* yr = Y + (size_t)m * Dd;
    yr[i0] = c0 * inv * w[i0] + b[i0];
    yr[i1] = c1 * inv * w[i1] + b[i1];
    yr[i2] = c2 * inv * w[i2] + b[i2];
}

// ---------------- embedding gather + LN (ln0) ----------------
__global__ void embed_ln_kernel(const int* __restrict__ tokens,
                                const float* __restrict__ emb,
                                const float* __restrict__ w,
                                const float* __restrict__ b,
                                float* __restrict__ Y) {
    __shared__ float sh[8];
    int m = blockIdx.x;
    int tok = tokens[m];
    const float* xr = emb + (size_t)tok * Dd;
    int i0 = threadIdx.x, i1 = i0 + 256, i2 = i0 + 512;
    float v0 = xr[i0], v1 = xr[i1], v2 = xr[i2];
    float s = blockReduceSum(v0 + v1 + v2, sh);
    float mu = s * (1.0f / 768.0f);
    float c0 = v0 - mu, c1 = v1 - mu, c2 = v2 - mu;
    float ss = blockReduceSum(c0*c0 + c1*c1 + c2*c2, sh);
    float inv = rsqrtf(ss * (1.0f / 768.0f) + 1e-5f);
    float* yr = Y + (size_t)m * Dd;
    yr[i0] = c0 * inv * w[i0] + b[i0];
    yr[i1] = c1 * inv * w[i1] + b[i1];
    yr[i2] = c2 * inv * w[i2] + b[i2];
}

// ---------------- token-shift mixes -> bf16 hi/lo ----------------
__global__ void mix3b_kernel(const float* __restrict__ xn,
                             const float* __restrict__ mk,
                             const float* __restrict__ mv,
                             const float* __restrict__ mr,
                             __nv_bfloat16* __restrict__ kh, __nv_bfloat16* __restrict__ kl,
                             __nv_bfloat16* __restrict__ vh, __nv_bfloat16* __restrict__ vl,
                             __nv_bfloat16* __restrict__ rh, __nv_bfloat16* __restrict__ rl) {
    int idx = blockIdx.x * 256 + threadIdx.x;
    int d = idx % Dd;
    int m = idx / Dd;
    int t = m & (Tt - 1);
    float cur = xn[idx];
    float prev = t ? xn[idx - Dd] : 0.0f;
    float a = mk[d], c = mv[d], e = mr[d];
    float xk = cur * a + prev * (1.0f - a);
    float xv = cur * c + prev * (1.0f - c);
    float xr = cur * e + prev * (1.0f - e);
    split_bf16(xk, kh[idx], kl[idx]);
    split_bf16(xv, vh[idx], vl[idx]);
    split_bf16(xr, rh[idx], rl[idx]);
}

__global__ void mix2b_kernel(const float* __restrict__ xn,
                             const float* __restrict__ mk,
                             const float* __restrict__ mr,
                             __nv_bfloat16* __restrict__ kh, __nv_bfloat16* __restrict__ kl,
                             __nv_bfloat16* __restrict__ rh, __nv_bfloat16* __restrict__ rl) {
    int idx = blockIdx.x * 256 + threadIdx.x;
    int d = idx % Dd;
    int m = idx / Dd;
    int t = m & (Tt - 1);
    float cur = xn[idx];
    float prev = t ? xn[idx - Dd] : 0.0f;
    float a = mk[d], e = mr[d];
    float xk = cur * a + prev * (1.0f - a);
    float xr = cur * e + prev * (1.0f - e);
    split_bf16(xk, kh[idx], kl[idx]);
    split_bf16(xr, rh[idx], rl[idx]);
}

// ---------------- WKV sequential recurrence (per-channel) ----------------
// 64 threads/block, 48 blocks; prefetch distance 2; fast exp/div; bf16 out.
__global__ void wkv_kernel(const float* __restrict__ k,
                           const float* __restrict__ v,
                           const float* __restrict__ r,
                           const float* __restrict__ tf,
                           const float* __restrict__ td,
                           __nv_bfloat16* __restrict__ oh,
                           __nv_bfloat16* __restrict__ ol) {
    int ch = blockIdx.x * 64 + threadIdx.x;   // < Bb*Dd
    int b = ch / Dd, d = ch % Dd;
    float tfd = tf[d], tdd = td[d];
    float aa = 0.0f, bb = 0.0f, pp = -1e30f;
    size_t base = (size_t)b * Tt * Dd + d;
    float kb[2], vb[2], rb[2];
    kb[0] = k[base];        vb[0] = v[base];        rb[0] = r[base];
    kb[1] = k[base + Dd];   vb[1] = v[base + Dd];   rb[1] = r[base + Dd];
    for (int t = 0; t < Tt; t++) {
        float kc = kb[t & 1], vc = vb[t & 1], rc = rb[t & 1];
        if (t + 2 < Tt) {
            size_t nb = base + (size_t)(t + 2) * Dd;
            kb[t & 1] = k[nb]; vb[t & 1] = v[nb]; rb[t & 1] = r[nb];
        }
        float ww = tfd + kc;
        float p  = fmaxf(pp, ww);
        float e1 = __expf(pp - p);
        float e2 = __expf(ww - p);
        float wkv = __fdividef(e1 * aa + e2 * vc, e1 * bb + e2);
        float sr = __fdividef(1.0f, 1.0f + __expf(-rc));
        float ov = sr * wkv;
        size_t oi = base + (size_t)t * Dd;
        __nv_bfloat16 h = __float2bfloat16(ov);
        oh[oi] = h;
        ol[oi] = __float2bfloat16(ov - __bfloat162float(h));
        float ww2 = pp + tdd;
        float p2  = fmaxf(ww2, kc);
        float e1b = __expf(ww2 - p2);
        float e2b = __expf(kc - p2);
        aa = e1b * aa + e2b * vc;
        bb = e1b * bb + e2b;
        pp = p2;
    }
}

// ---------------- tensor-core GEMM (preconverted bf16 hi/lo, fp32 acc) ----
// C[M,N] = A @ W; acc += Ah*Wh + Ah*Wl + Al*Wh
// BM=64, BN=64, BK=32, 128 threads = 4 warps (2m x 2n), warp tile 32x32.
// Double-buffered cp.async pipeline; no conversion in the hot loop.
// Epilogues: 0=store f32, 1=C+=acc, 2=sqrelu->bf16 hi/lo, 3=sigmoid, 4=C+=G*acc
struct GPtrs {
    const __nv_bfloat16* Ah[3];
    const __nv_bfloat16* Al[3];
    const __nv_bfloat16* Wh[3];
    const __nv_bfloat16* Wl[3];
    float*               C[3];
    __nv_bfloat16*       C2h;
    __nv_bfloat16*       C2l;
    const float*         G;
};

#define GBM 64
#define GBN 64
#define GBK 32

struct Stage {
    __nv_bfloat16 Ah[GBM][GBK + 8];   // row stride 80B (16B-aligned)
    __nv_bfloat16 Al[GBM][GBK + 8];
    __nv_bfloat16 Bh[GBK][GBN + 8];   // row stride 144B
    __nv_bfloat16 Bl[GBK][GBN + 8];
};
#define SMEM_BYTES (2 * sizeof(Stage) > sizeof(float) * GBM * (GBN + 4) ? \
                    2 * sizeof(Stage) : sizeof(float) * GBM * (GBN + 4))

template<int EPI>
__global__ __launch_bounds__(128, 4)
void gemm_tc(GPtrs p, int Ng, int Kg) {
    __shared__ __align__(16) unsigned char smbuf[SMEM_BYTES];
    Stage* st = reinterpret_cast<Stage*>(smbuf);
    float (*Csm)[GBN + 4] = reinterpret_cast<float(*)[GBN + 4]>(smbuf);

    const int bz = blockIdx.z;
    const __nv_bfloat16* __restrict__ Ahp = p.Ah[bz];
    const __nv_bfloat16* __restrict__ Alp = p.Al[bz];
    const __nv_bfloat16* __restrict__ Whp = p.Wh[bz];
    const __nv_bfloat16* __restrict__ Wlp = p.Wl[bz];
    float* __restrict__ C = p.C[bz];
    const float* __restrict__ G = p.G;

    const int tid = threadIdx.x;
    const int wid = tid >> 5;
    const int wm = wid >> 1, wn = wid & 1;
    const int m0 = blockIdx.y * GBM;
    const int n0 = blockIdx.x * GBN;

    // copy indices: A: 2 threads/row, 16 elems each; B: 4 threads/row, 16 elems each
    const int ar = tid >> 1;
    const int ac = (tid & 1) * 16;
    const int br = tid >> 2;
    const int bc = (tid & 3) * 16;

    wmma::fragment<wmma::accumulator, 16, 16, 16, float> acc[2][2];
    #pragma unroll
    for (int i = 0; i < 2; i++)
        #pragma unroll
        for (int j = 0; j < 2; j++)
            wmma::fill_fragment(acc[i][j], 0.0f);

    const int nk = Kg / GBK;

    auto issue = [&](int s, int ks) {
        int k0 = ks * GBK;
        const __nv_bfloat16* a0 = Ahp + (size_t)(m0 + ar) * Kg + k0 + ac;
        const __nv_bfloat16* a1 = Alp + (size_t)(m0 + ar) * Kg + k0 + ac;
        cpa16(&st[s].Ah[ar][ac],     a0);
        cpa16(&st[s].Ah[ar][ac + 8], a0 + 8);
        cpa16(&st[s].Al[ar][ac],     a1);
        cpa16(&st[s].Al[ar][ac + 8], a1 + 8);
        const __nv_bfloat16* b0 = Whp + (size_t)(k0 + br) * Ng + n0 + bc;
        const __nv_bfloat16* b1 = Wlp + (size_t)(k0 + br) * Ng + n0 + bc;
        cpa16(&st[s].Bh[br][bc],     b0);
        cpa16(&st[s].Bh[br][bc + 8], b0 + 8);
        cpa16(&st[s].Bl[br][bc],     b1);
        cpa16(&st[s].Bl[br][bc + 8], b1 + 8);
        cp_commit();
    };

    issue(0, 0);

    for (int ks = 0; ks < nk; ks++) {
        if (ks + 1 < nk) {
            issue((ks + 1) & 1, ks + 1);
            cp_wait<1>();
        } else {
            cp_wait<0>();
        }
        __syncthreads();

        Stage& S = st[ks & 1];
        #pragma unroll
        for (int kk = 0; kk < GBK; kk += 16) {
            wmma::fragment<wmma::matrix_a, 16, 16, 16, __nv_bfloat16, wmma::row_major> ah[2], al[2];
            wmma::fragment<wmma::matrix_b, 16, 16, 16, __nv_bfloat16, wmma::row_major> bh[2], bl[2];
            #pragma unroll
            for (int i = 0; i < 2; i++) {
                wmma::load_matrix_sync(ah[i], &S.Ah[wm * 32 + i * 16][kk], GBK + 8);
                wmma::load_matrix_sync(al[i], &S.Al[wm * 32 + i * 16][kk], GBK + 8);
            }
            #pragma unroll
            for (int j = 0; j < 2; j++) {
                wmma::load_matrix_sync(bh[j], &S.Bh[kk][wn * 32 + j * 16], GBN + 8);
                wmma::load_matrix_sync(bl[j], &S.Bl[kk][wn * 32 + j * 16], GBN + 8);
            }
            #pragma unroll
            for (int i = 0; i < 2; i++)
                #pragma unroll
                for (int j = 0; j < 2; j++) {
                    wmma::mma_sync(acc[i][j], ah[i], bh[j], acc[i][j]);
                    wmma::mma_sync(acc[i][j], ah[i], bl[j], acc[i][j]);
                    wmma::mma_sync(acc[i][j], al[i], bh[j], acc[i][j]);
                }
        }
        __syncthreads();
    }

    // ---- epilogue via smem ----
    #pragma unroll
    for (int i = 0; i < 2; i++)
        #pragma unroll
        for (int j = 0; j < 2; j++)
            wmma::store_matrix_sync(&Csm[wm * 32 + i * 16][wn * 32 + j * 16],
                                    acc[i][j], GBN + 4, wmma::mem_row_major);
    __syncthreads();

    const int ecol = tid & 63;
    const int erow = tid >> 6;   // 0..1
    #pragma unroll
    for (int i = 0; i < 32; i++) {
        int rr = i * 2 + erow;
        int m = m0 + rr;
        int n = n0 + ecol;
        size_t idx = (size_t)m * Ng + n;
        float val = Csm[rr][ecol];
        if (EPI == 0) {
            C[idx] = val;
        } else if (EPI == 1) {
            C[idx] += val;
        } else if (EPI == 2) {
            float t0 = fmaxf(val, 0.0f);
            float hv = t0 * t0;
            __nv_bfloat16 h = __float2bfloat16(hv);
            p.C2h[idx] = h;
            p.C2l[idx] = __float2bfloat16(hv - __bfloat162float(h));
        } else if (EPI == 3) {
            C[idx] = __fdividef(1.0f, 1.0f + __expf(-val));
        } else if (EPI == 4) {
            C[idx] += G[idx] * val;
        }
    }
}

// ---------------- host launcher ----------------
extern "C" void kernel_launch(void* const* d_in, const int* in_sizes, int n_in,
                              void* d_out, int out_size) {
    const int*   tokens     = (const int*)  d_in[0];
    const float* emb        = (const float*)d_in[1];
    const float* ln0_w      = (const float*)d_in[2];
    const float* ln0_b      = (const float*)d_in[3];
    const float* ln1_w      = (const float*)d_in[4];
    const float* ln1_b      = (const float*)d_in[5];
    const float* ln2_w      = (const float*)d_in[6];
    const float* ln2_b      = (const float*)d_in[7];
    const float* att_mix_k  = (const float*)d_in[8];
    const float* att_mix_v  = (const float*)d_in[9];
    const float* att_mix_r  = (const float*)d_in[10];
    const float* time_first = (const float*)d_in[11];
    const float* time_decay = (const float*)d_in[12];
    const float* att_Wk     = (const float*)d_in[13];
    const float* att_Wv     = (const float*)d_in[14];
    const float* att_Wr     = (const float*)d_in[15];
    const float* att_Wo     = (const float*)d_in[16];
    const float* ffn_mix_k  = (const float*)d_in[17];
    const float* ffn_mix_r  = (const float*)d_in[18];
    const float* ffn_Wk     = (const float*)d_in[19];
    const float* ffn_Wv     = (const float*)d_in[20];
    const float* ffn_Wr     = (const float*)d_in[21];
    const float* lnout_w    = (const float*)d_in[22];
    const float* lnout_b    = (const float*)d_in[23];
    float* out = (float*)d_out;

    float *x, *xn, *kvr, *r2;
    __nv_bfloat16 *mixh, *mixl, *rwkvh, *rwkvl, *hh, *hl, *wh, *wl;
    cudaGetSymbolAddress((void**)&x,     g_x);
    cudaGetSymbolAddress((void**)&xn,    g_xn);
    cudaGetSymbolAddress((void**)&kvr,   g_kvr);
    cudaGetSymbolAddress((void**)&r2,    g_r2);
    cudaGetSymbolAddress((void**)&mixh,  g_mixh);
    cudaGetSymbolAddress((void**)&mixl,  g_mixl);
    cudaGetSymbolAddress((void**)&rwkvh, g_rwkvh);
    cudaGetSymbolAddress((void**)&rwkvl, g_rwkvl);
    cudaGetSymbolAddress((void**)&hh,    g_hh);
    cudaGetSymbolAddress((void**)&hl,    g_hl);
    cudaGetSymbolAddress((void**)&wh,    g_wh);
    cudaGetSymbolAddress((void**)&wl,    g_wl);

    // ---- preconvert all weights to bf16 hi/lo (once per call) ----
    auto conv = [&](const float* W, size_t off, int n) {
        int n4 = n / 4;
        split_w_kernel<<<(n4 + 255) / 256, 256>>>(
            (const float4*)W, (__nv_bfloat162*)(wh + off), (__nv_bfloat162*)(wl + off), n4);
    };
    conv(att_Wk, OFF_WK, NDD);
    conv(att_Wv, OFF_WV, NDD);
    conv(att_Wr, OFF_WR, NDD);
    conv(att_Wo, OFF_WO, NDD);
    conv(ffn_Wk, OFF_FK, NDF);
    conv(ffn_Wv, OFF_FV, NDF);
    conv(ffn_Wr, OFF_FR, NDD);

    // x = LN0(emb[tokens])
    embed_ln_kernel<<<MM, 256>>>(tokens, emb, ln0_w, ln0_b, x);

    for (int l = 0; l < Ll; l++) {
        // ---- time mixing ----
        ln_kernel<<<MM, 256>>>(x, ln1_w + l * Dd, ln1_b + l * Dd, xn);
        mix3b_kernel<<<MD / 256, 256>>>(xn,
            att_mix_k + l * Dd, att_mix_v + l * Dd, att_mix_r + l * Dd,
            mixh, mixl, mixh + MD, mixl + MD, mixh + 2 * MD, mixl + 2 * MD);

        // k/v/r = mix @ {Wk,Wv,Wr}
        {
            GPtrs p{};
            p.Ah[0] = mixh;          p.Al[0] = mixl;
            p.Ah[1] = mixh + MD;     p.Al[1] = mixl + MD;
            p.Ah[2] = mixh + 2 * MD; p.Al[2] = mixl + 2 * MD;
            p.Wh[0] = wh + OFF_WK + (size_t)l * Dd * Dd; p.Wl[0] = wl + OFF_WK + (size_t)l * Dd * Dd;
            p.Wh[1] = wh + OFF_WV + (size_t)l * Dd * Dd; p.Wl[1] = wl + OFF_WV + (size_t)l * Dd * Dd;
            p.Wh[2] = wh + OFF_WR + (size_t)l * Dd * Dd; p.Wl[2] = wl + OFF_WR + (size_t)l * Dd * Dd;
            p.C[0] = kvr; p.C[1] = kvr + MD; p.C[2] = kvr + 2 * MD;
            dim3 grid(Dd / GBN, MM / GBM, 3);
            gemm_tc<0><<<grid, 128>>>(p, Dd, Dd);
        }

        // sequential WKV over T, gated by sigmoid(r), bf16 hi/lo output
        wkv_kernel<<<(Bb * Dd) / 64, 64>>>(kvr, kvr + MD, kvr + 2 * MD,
                                           time_first + l * Dd, time_decay + l * Dd,
                                           rwkvh, rwkvl);

        // x += rwkv @ Wo
        {
            GPtrs p{};
            p.Ah[0] = rwkvh; p.Al[0] = rwkvl;
            p.Wh[0] = wh + OFF_WO + (size_t)l * Dd * Dd; p.Wl[0] = wl + OFF_WO + (size_t)l * Dd * Dd;
            p.C[0] = x;
            dim3 grid(Dd / GBN, MM / GBM, 1);
            gemm_tc<1><<<grid, 128>>>(p, Dd, Dd);
        }

        // ---- channel mixing ----
        ln_kernel<<<MM, 256>>>(x, ln2_w + l * Dd, ln2_b + l * Dd, xn);
        mix2b_kernel<<<MD / 256, 256>>>(xn,
            ffn_mix_k + l * Dd, ffn_mix_r + l * Dd,
            mixh, mixl, mixh + MD, mixl + MD);

        // h = sqrelu(xk2 @ ffn_Wk) -> bf16 hi/lo
        {
            GPtrs p{};
            p.Ah[0] = mixh; p.Al[0] = mixl;
            p.Wh[0] = wh + OFF_FK + (size_t)l * Dd * Ff; p.Wl[0] = wl + OFF_FK + (size_t)l * Dd * Ff;
            p.C2h = hh; p.C2l = hl;
            dim3 grid(Ff / GBN, MM / GBM, 1);
            gemm_tc<2><<<grid, 128>>>(p, Ff, Dd);
        }
        // r2 = sigmoid(xr2 @ ffn_Wr)
        {
            GPtrs p{};
            p.Ah[0] = mixh + MD; p.Al[0] = mixl + MD;
            p.Wh[0] = wh + OFF_FR + (size_t)l * Dd * Dd; p.Wl[0] = wl + OFF_FR + (size_t)l * Dd * Dd;
            p.C[0] = r2;
            dim3 grid(Dd / GBN, MM / GBM, 1);
            gemm_tc<3><<<grid, 128>>>(p, Dd, Dd);
        }
        // x += r2 * (h @ ffn_Wv)
        {
            GPtrs p{};
            p.Ah[0] = hh; p.Al[0] = hl;
            p.Wh[0] = wh + OFF_FV + (size_t)l * Ff * Dd; p.Wl[0] = wl + OFF_FV + (size_t)l * Ff * Dd;
            p.C[0] = x; p.G = r2;
            dim3 grid(Dd / GBN, MM / GBM, 1);
            gemm_tc<4><<<grid, 128>>>(p, Dd, Ff);
        }
    }

    // out = LN_out(x)
    ln_kernel<<<MM, 256>>>(x, lnout_w, lnout_b, out);
}

// round 5
// speedup vs baseline: 2.3204x; 1.2089x over previous
#include <cuda_runtime.h>
#include <cuda_bf16.h>
#include <mma.h>
#include <math.h>
#include <cstdint>

using namespace nvcuda;

// Constants
#define Ll 12
#define Dd 768
#define Bb 4
#define Tt 256
#define Ff 3072
#define MM (Bb*Tt)   // 1024
#define MD (MM*Dd)

// converted-weight offsets (elements)
#define NDD (Ll*Dd*Dd)
#define NDF (Ll*Dd*Ff)
#define OFF_WK 0
#define OFF_WV (NDD)
#define OFF_WR (2*NDD)
#define OFF_WO (3*NDD)
#define OFF_FK (4*NDD)
#define OFF_FV (4*NDD + NDF)
#define OFF_FR (4*NDD + 2*NDF)
#define NWTOT  (4*NDD + 2*NDF + NDD)

// ---------------- scratch (device globals) ----------
__device__ __align__(256) float g_x[MD];                 // residual stream
__device__ __align__(256) float g_kvr[3*MD];             // k/v/r fp32
__device__ __align__(256) float g_r2[MD];                // ffn gate fp32
__device__ __align__(256) float g_part[4*MD];            // split-K partials
__device__ __align__(256) __nv_bfloat16 g_mixh[3*MD];
__device__ __align__(256) __nv_bfloat16 g_mixl[3*MD];
__device__ __align__(256) __nv_bfloat16 g_rwkvh[MD];
__device__ __align__(256) __nv_bfloat16 g_rwkvl[MD];
__device__ __align__(256) __nv_bfloat16 g_hh[MM*Ff];
__device__ __align__(256) __nv_bfloat16 g_hl[MM*Ff];
__device__ __align__(256) __nv_bfloat16 g_wh[NWTOT];
__device__ __align__(256) __nv_bfloat16 g_wl[NWTOT];

__device__ __forceinline__ void split_bf16(float x, __nv_bfloat16& h, __nv_bfloat16& l) {
    h = __float2bfloat16(x);
    l = __float2bfloat16(x - __bfloat162float(h));
}

// ---------------- cp.async helpers ----------------
__device__ __forceinline__ void cpa16(void* dst, const void* src) {
    unsigned d = (unsigned)__cvta_generic_to_shared(dst);
    asm volatile("cp.async.cg.shared.global [%0], [%1], 16;" :: "r"(d), "l"(src));
}
__device__ __forceinline__ void cp_commit() { asm volatile("cp.async.commit_group;"); }
template<int N> __device__ __forceinline__ void cp_wait() {
    asm volatile("cp.async.wait_group %0;" :: "n"(N));
}

// ---------------- weight split preconversion ----------------
__global__ void split_w_kernel(const float4* __restrict__ W,
                               __nv_bfloat162* __restrict__ hi,
                               __nv_bfloat162* __restrict__ lo, int n4) {
    int i = blockIdx.x * 256 + threadIdx.x;
    if (i >= n4) return;
    float4 w = W[i];
    __nv_bfloat16 h0, h1, h2, h3, l0, l1, l2, l3;
    split_bf16(w.x, h0, l0);
    split_bf16(w.y, h1, l1);
    split_bf16(w.z, h2, l2);
    split_bf16(w.w, h3, l3);
    hi[2*i]   = __halves2bfloat162(h0, h1);
    hi[2*i+1] = __halves2bfloat162(h2, h3);
    lo[2*i]   = __halves2bfloat162(l0, l1);
    lo[2*i+1] = __halves2bfloat162(l2, l3);
}

// ---------------- block reduces ----------------
__device__ __forceinline__ float blockReduceSum(float v, float* sh) {
    int lane = threadIdx.x & 31, w = threadIdx.x >> 5;
    #pragma unroll
    for (int o = 16; o; o >>= 1) v += __shfl_xor_sync(0xffffffffu, v, o);
    if (lane == 0) sh[w] = v;
    __syncthreads();
    float r;
    if (threadIdx.x < 8) {
        r = sh[threadIdx.x];
        #pragma unroll
        for (int o = 4; o; o >>= 1) r += __shfl_xor_sync(0x000000ffu, r, o);
        if (threadIdx.x == 0) sh[0] = r;
    }
    __syncthreads();
    r = sh[0];
    __syncthreads();
    return r;
}

__device__ __forceinline__ float2 blockReduceSum2(float2 v, float2* sh) {
    int lane = threadIdx.x & 31, w = threadIdx.x >> 5;
    #pragma unroll
    for (int o = 16; o; o >>= 1) {
        v.x += __shfl_xor_sync(0xffffffffu, v.x, o);
        v.y += __shfl_xor_sync(0xffffffffu, v.y, o);
    }
    if (lane == 0) sh[w] = v;
    __syncthreads();
    float2 r;
    if (threadIdx.x < 8) {
        r = sh[threadIdx.x];
        #pragma unroll
        for (int o = 4; o; o >>= 1) {
            r.x += __shfl_xor_sync(0x000000ffu, r.x, o);
            r.y += __shfl_xor_sync(0x000000ffu, r.y, o);
        }
        if (threadIdx.x == 0) sh[0] = r;
    }
    __syncthreads();
    r = sh[0];
    __syncthreads();
    return r;
}

// ---------------- embedding gather + LN (ln0) ----------------
__global__ void embed_ln_kernel(const int* __restrict__ tokens,
                                const float* __restrict__ emb,
                                const float* __restrict__ w,
                                const float* __restrict__ b,
                                float* __restrict__ Y) {
    __shared__ float sh[8];
    int m = blockIdx.x;
    int tok = tokens[m];
    const float* xr = emb + (size_t)tok * Dd;
    int i0 = threadIdx.x, i1 = i0 + 256, i2 = i0 + 512;
    float v0 = xr[i0], v1 = xr[i1], v2 = xr[i2];
    float s = blockReduceSum(v0 + v1 + v2, sh);
    float mu = s * (1.0f / 768.0f);
    float c0 = v0 - mu, c1 = v1 - mu, c2 = v2 - mu;
    float ss = blockReduceSum(c0*c0 + c1*c1 + c2*c2, sh);
    float inv = rsqrtf(ss * (1.0f / 768.0f) + 1e-5f);
    float* yr = Y + (size_t)m * Dd;
    yr[i0] = c0 * inv * w[i0] + b[i0];
    yr[i1] = c1 * inv * w[i1] + b[i1];
    yr[i2] = c2 * inv * w[i2] + b[i2];
}

// ---------------- final LN ----------------
__global__ void ln_kernel(const float* __restrict__ X,
                          const float* __restrict__ w,
                          const float* __restrict__ b,
                          float* __restrict__ Y) {
    __shared__ float sh[8];
    int m = blockIdx.x;
    const float* xr = X + (size_t)m * Dd;
    int i0 = threadIdx.x, i1 = i0 + 256, i2 = i0 + 512;
    float v0 = xr[i0], v1 = xr[i1], v2 = xr[i2];
    float s = blockReduceSum(v0 + v1 + v2, sh);
    float mu = s * (1.0f / 768.0f);
    float c0 = v0 - mu, c1 = v1 - mu, c2 = v2 - mu;
    float ss = blockReduceSum(c0*c0 + c1*c1 + c2*c2, sh);
    float inv = rsqrtf(ss * (1.0f / 768.0f) + 1e-5f);
    float* yr = Y + (size_t)m * Dd;
    yr[i0] = c0 * inv * w[i0] + b[i0];
    yr[i1] = c1 * inv * w[i1] + b[i1];
    yr[i2] = c2 * inv * w[i2] + b[i2];
}

// ---------------- fused LN + token-shift mix -> bf16 hi/lo ----------------
// Block m computes LN(x[m]) and LN(x[m-1]) (recompute), then mixes.
// NMIX = 3 (att: k,v,r) or 2 (ffn: k,r)
template<int NMIX>
__global__ void lnmix_kernel(const float* __restrict__ X,
                             const float* __restrict__ w,
                             const float* __restrict__ b,
                             const float* __restrict__ mk,
                             const float* __restrict__ mv,
                             const float* __restrict__ mr,
                             __nv_bfloat16* __restrict__ oh,
                             __nv_bfloat16* __restrict__ ol) {
    __shared__ float2 sh[8];
    int m = blockIdx.x;
    bool hasPrev = (m & (Tt - 1)) != 0;
    const float* xc = X + (size_t)m * Dd;
    const float* xp = X + (size_t)(m - 1) * Dd;   // only read if hasPrev
    int i0 = threadIdx.x, i1 = i0 + 256, i2 = i0 + 512;
    float c0 = xc[i0], c1 = xc[i1], c2 = xc[i2];
    float p0 = 0.f, p1 = 0.f, p2 = 0.f;
    if (hasPrev) { p0 = xp[i0]; p1 = xp[i1]; p2 = xp[i2]; }
    float2 s = blockReduceSum2(make_float2(c0 + c1 + c2, p0 + p1 + p2), sh);
    float muc = s.x * (1.0f / 768.0f), mup = s.y * (1.0f / 768.0f);
    float cc0 = c0 - muc, cc1 = c1 - muc, cc2 = c2 - muc;
    float pc0 = p0 - mup, pc1 = p1 - mup, pc2 = p2 - mup;
    float2 ss = blockReduceSum2(make_float2(cc0*cc0 + cc1*cc1 + cc2*cc2,
                                            pc0*pc0 + pc1*pc1 + pc2*pc2), sh);
    float invc = rsqrtf(ss.x * (1.0f / 768.0f) + 1e-5f);
    float invp = rsqrtf(ss.y * (1.0f / 768.0f) + 1e-5f);

    size_t base = (size_t)m * Dd;
    #pragma unroll
    for (int q = 0; q < 3; q++) {
        int i = threadIdx.x + q * 256;
        float cv = (q == 0 ? cc0 : q == 1 ? cc1 : cc2) * invc * w[i] + b[i];
        float pv = 0.0f;
        if (hasPrev)
            pv = (q == 0 ? pc0 : q == 1 ? pc1 : pc2) * invp * w[i] + b[i];
        float a = mk[i];
        float xk = cv * a + pv * (1.0f - a);
        split_bf16(xk, oh[base + i], ol[base + i]);
        if (NMIX == 3) {
            float c = mv[i];
            float xv = cv * c + pv * (1.0f - c);
            split_bf16(xv, oh[MD + base + i], ol[MD + base + i]);
        }
        float e = mr[i];
        float xr = cv * e + pv * (1.0f - e);
        int slot = (NMIX == 3) ? 2 : 1;
        split_bf16(xr, oh[slot * MD + base + i], ol[slot * MD + base + i]);
    }
}

// ---------------- WKV sequential recurrence (per-channel) ----------------
__global__ void wkv_kernel(const float* __restrict__ k,
                           const float* __restrict__ v,
                           const float* __restrict__ r,
                           const float* __restrict__ tf,
                           const float* __restrict__ td,
                           __nv_bfloat16* __restrict__ oh,
                           __nv_bfloat16* __restrict__ ol) {
    int ch = blockIdx.x * 32 + threadIdx.x;   // < Bb*Dd
    int b = ch / Dd, d = ch % Dd;
    float tfd = tf[d], tdd = td[d];
    float aa = 0.0f, bb = 0.0f, pp = -1e30f;
    size_t base = (size_t)b * Tt * Dd + d;
    float kb[2], vb[2], rb[2];
    kb[0] = k[base];        vb[0] = v[base];        rb[0] = r[base];
    kb[1] = k[base + Dd];   vb[1] = v[base + Dd];   rb[1] = r[base + Dd];
    for (int t = 0; t < Tt; t++) {
        float kc = kb[t & 1], vc = vb[t & 1], rc = rb[t & 1];
        if (t + 2 < Tt) {
            size_t nb = base + (size_t)(t + 2) * Dd;
            kb[t & 1] = k[nb]; vb[t & 1] = v[nb]; rb[t & 1] = r[nb];
        }
        float ww = tfd + kc;
        float p  = fmaxf(pp, ww);
        float e1 = __expf(pp - p);
        float e2 = __expf(ww - p);
        float wkv = __fdividef(e1 * aa + e2 * vc, e1 * bb + e2);
        float sr = __fdividef(1.0f, 1.0f + __expf(-rc));
        float ov = sr * wkv;
        size_t oi = base + (size_t)t * Dd;
        __nv_bfloat16 h = __float2bfloat16(ov);
        oh[oi] = h;
        ol[oi] = __float2bfloat16(ov - __bfloat162float(h));
        float ww2 = pp + tdd;
        float p2  = fmaxf(ww2, kc);
        float e1b = __expf(ww2 - p2);
        float e2b = __expf(kc - p2);
        aa = e1b * aa + e2b * vc;
        bb = e1b * bb + e2b;
        pp = p2;
    }
}

// ---------------- split-K reductions ----------------
__global__ void red_wo_kernel(float4* __restrict__ x,
                              const float4* __restrict__ p0,
                              const float4* __restrict__ p1) {
    int i = blockIdx.x * 256 + threadIdx.x;     // MD/4 elems
    float4 a = x[i], u = p0[i], v = p1[i];
    a.x += u.x + v.x; a.y += u.y + v.y; a.z += u.z + v.z; a.w += u.w + v.w;
    x[i] = a;
}

__global__ void red_fv_kernel(float4* __restrict__ x,
                              const float4* __restrict__ g,
                              const float4* __restrict__ p0,
                              const float4* __restrict__ p1,
                              const float4* __restrict__ p2,
                              const float4* __restrict__ p3) {
    int i = blockIdx.x * 256 + threadIdx.x;
    float4 a = x[i], gg = g[i];
    float4 u0 = p0[i], u1 = p1[i], u2 = p2[i], u3 = p3[i];
    a.x += gg.x * (u0.x + u1.x + u2.x + u3.x);
    a.y += gg.y * (u0.y + u1.y + u2.y + u3.y);
    a.z += gg.z * (u0.z + u1.z + u2.z + u3.z);
    a.w += gg.w * (u0.w + u1.w + u2.w + u3.w);
    x[i] = a;
}

// ---------------- tensor-core GEMM (bf16 hi/lo, fp32 acc) ----
// acc += Ah*Wh + Ah*Wl + Al*Wh over K range [kOff, kOff+Kg)
// BM=64, BN=64, BK=32, 128 threads = 4 warps (2m x 2n), warp tile 32x32.
// epi: 0 = store f32 to C; 2 = sqrelu -> bf16 hi/lo; 3 = sigmoid -> C f32
struct GArg {
    const __nv_bfloat16* Ah;
    const __nv_bfloat16* Al;
    const __nv_bfloat16* Wh;
    const __nv_bfloat16* Wl;
    float*               C;
    __nv_bfloat16*       C2h;
    __nv_bfloat16*       C2l;
    int Ng, Kg, kOff, lda, epi;
};
struct GPack { GArg g[4]; };

#define GBM 64
#define GBN 64
#define GBK 32

struct Stage {
    __nv_bfloat16 Ah[GBM][GBK + 8];
    __nv_bfloat16 Al[GBM][GBK + 8];
    __nv_bfloat16 Bh[GBK][GBN + 8];
    __nv_bfloat16 Bl[GBK][GBN + 8];
};
#define SMEM_BYTES (2 * sizeof(Stage) > sizeof(float) * GBM * (GBN + 4) ? \
                    2 * sizeof(Stage) : sizeof(float) * GBM * (GBN + 4))

__global__ __launch_bounds__(128)
void gemm_tc(GPack pk) {
    GArg ga = pk.g[blockIdx.z];
    const int n0 = blockIdx.x * GBN;
    if (n0 >= ga.Ng) return;

    __shared__ __align__(16) unsigned char smbuf[SMEM_BYTES];
    Stage* st = reinterpret_cast<Stage*>(smbuf);
    float (*Csm)[GBN + 4] = reinterpret_cast<float(*)[GBN + 4]>(smbuf);

    const __nv_bfloat16* __restrict__ Ahp = ga.Ah;
    const __nv_bfloat16* __restrict__ Alp = ga.Al;
    const __nv_bfloat16* __restrict__ Whp = ga.Wh;
    const __nv_bfloat16* __restrict__ Wlp = ga.Wl;
    const int Ng = ga.Ng, lda = ga.lda, kOff = ga.kOff;

    const int tid = threadIdx.x;
    const int wid = tid >> 5;
    const int wm = wid >> 1, wn = wid & 1;
    const int m0 = blockIdx.y * GBM;

    const int ar = tid >> 1;
    const int ac = (tid & 1) * 16;
    const int br = tid >> 2;
    const int bc = (tid & 3) * 16;

    wmma::fragment<wmma::accumulator, 16, 16, 16, float> acc[2][2];
    #pragma unroll
    for (int i = 0; i < 2; i++)
        #pragma unroll
        for (int j = 0; j < 2; j++)
            wmma::fill_fragment(acc[i][j], 0.0f);

    const int nk = ga.Kg / GBK;

    auto issue = [&](int s, int ks) {
        int k0 = kOff + ks * GBK;
        const __nv_bfloat16* a0 = Ahp + (size_t)(m0 + ar) * lda + k0 + ac;
        const __nv_bfloat16* a1 = Alp + (size_t)(m0 + ar) * lda + k0 + ac;
        cpa16(&st[s].Ah[ar][ac],     a0);
        cpa16(&st[s].Ah[ar][ac + 8], a0 + 8);
        cpa16(&st[s].Al[ar][ac],     a1);
        cpa16(&st[s].Al[ar][ac + 8], a1 + 8);
        const __nv_bfloat16* b0 = Whp + (size_t)(k0 + br) * Ng + n0 + bc;
        const __nv_bfloat16* b1 = Wlp + (size_t)(k0 + br) * Ng + n0 + bc;
        cpa16(&st[s].Bh[br][bc],     b0);
        cpa16(&st[s].Bh[br][bc + 8], b0 + 8);
        cpa16(&st[s].Bl[br][bc],     b1);
        cpa16(&st[s].Bl[br][bc + 8], b1 + 8);
        cp_commit();
    };

    issue(0, 0);

    for (int ks = 0; ks < nk; ks++) {
        if (ks + 1 < nk) {
            issue((ks + 1) & 1, ks + 1);
            cp_wait<1>();
        } else {
            cp_wait<0>();
        }
        __syncthreads();

        Stage& S = st[ks & 1];
        #pragma unroll
        for (int kk = 0; kk < GBK; kk += 16) {
            wmma::fragment<wmma::matrix_a, 16, 16, 16, __nv_bfloat16, wmma::row_major> ah[2], al[2];
            wmma::fragment<wmma::matrix_b, 16, 16, 16, __nv_bfloat16, wmma::row_major> bh[2], bl[2];
            #pragma unroll
            for (int i = 0; i < 2; i++) {
                wmma::load_matrix_sync(ah[i], &S.Ah[wm * 32 + i * 16][kk], GBK + 8);
                wmma::load_matrix_sync(al[i], &S.Al[wm * 32 + i * 16][kk], GBK + 8);
            }
            #pragma unroll
            for (int j = 0; j < 2; j++) {
                wmma::load_matrix_sync(bh[j], &S.Bh[kk][wn * 32 + j * 16], GBN + 8);
                wmma::load_matrix_sync(bl[j], &S.Bl[kk][wn * 32 + j * 16], GBN + 8);
            }
            #pragma unroll
            for (int i = 0; i < 2; i++)
                #pragma unroll
                for (int j = 0; j < 2; j++) {
                    wmma::mma_sync(acc[i][j], ah[i], bh[j], acc[i][j]);
                    wmma::mma_sync(acc[i][j], ah[i], bl[j], acc[i][j]);
                    wmma::mma_sync(acc[i][j], al[i], bh[j], acc[i][j]);
                }
        }
        __syncthreads();
    }

    // ---- epilogue via smem ----
    #pragma unroll
    for (int i = 0; i < 2; i++)
        #pragma unroll
        for (int j = 0; j < 2; j++)
            wmma::store_matrix_sync(&Csm[wm * 32 + i * 16][wn * 32 + j * 16],
                                    acc[i][j], GBN + 4, wmma::mem_row_major);
    __syncthreads();

    const int ecol = tid & 63;
    const int erow = tid >> 6;
    const int epi = ga.epi;
    #pragma unroll
    for (int i = 0; i < 32; i++) {
        int rr = i * 2 + erow;
        size_t idx = (size_t)(m0 + rr) * Ng + n0 + ecol;
        float val = Csm[rr][ecol];
        if (epi == 0) {
            ga.C[idx] = val;
        } else if (epi == 2) {
            float t0 = fmaxf(val, 0.0f);
            float hv = t0 * t0;
            __nv_bfloat16 h = __float2bfloat16(hv);
            ga.C2h[idx] = h;
            ga.C2l[idx] = __float2bfloat16(hv - __bfloat162float(h));
        } else {
            ga.C[idx] = __fdividef(1.0f, 1.0f + __expf(-val));
        }
    }
}

// ---------------- host launcher ----------------
extern "C" void kernel_launch(void* const* d_in, const int* in_sizes, int n_in,
                              void* d_out, int out_size) {
    const int*   tokens     = (const int*)  d_in[0];
    const float* emb        = (const float*)d_in[1];
    const float* ln0_w      = (const float*)d_in[2];
    const float* ln0_b      = (const float*)d_in[3];
    const float* ln1_w      = (const float*)d_in[4];
    const float* ln1_b      = (const float*)d_in[5];
    const float* ln2_w      = (const float*)d_in[6];
    const float* ln2_b      = (const float*)d_in[7];
    const float* att_mix_k  = (const float*)d_in[8];
    const float* att_mix_v  = (const float*)d_in[9];
    const float* att_mix_r  = (const float*)d_in[10];
    const float* time_first = (const float*)d_in[11];
    const float* time_decay = (const float*)d_in[12];
    const float* att_Wk     = (const float*)d_in[13];
    const float* att_Wv     = (const float*)d_in[14];
    const float* att_Wr     = (const float*)d_in[15];
    const float* att_Wo     = (const float*)d_in[16];
    const float* ffn_mix_k  = (const float*)d_in[17];
    const float* ffn_mix_r  = (const float*)d_in[18];
    const float* ffn_Wk     = (const float*)d_in[19];
    const float* ffn_Wv     = (const float*)d_in[20];
    const float* ffn_Wr     = (const float*)d_in[21];
    const float* lnout_w    = (const float*)d_in[22];
    const float* lnout_b    = (const float*)d_in[23];
    float* out = (float*)d_out;

    float *x, *kvr, *r2, *part;
    __nv_bfloat16 *mixh, *mixl, *rwkvh, *rwkvl, *hh, *hl, *wh, *wl;
    cudaGetSymbolAddress((void**)&x,     g_x);
    cudaGetSymbolAddress((void**)&kvr,   g_kvr);
    cudaGetSymbolAddress((void**)&r2,    g_r2);
    cudaGetSymbolAddress((void**)&part,  g_part);
    cudaGetSymbolAddress((void**)&mixh,  g_mixh);
    cudaGetSymbolAddress((void**)&mixl,  g_mixl);
    cudaGetSymbolAddress((void**)&rwkvh, g_rwkvh);
    cudaGetSymbolAddress((void**)&rwkvl, g_rwkvl);
    cudaGetSymbolAddress((void**)&hh,    g_hh);
    cudaGetSymbolAddress((void**)&hl,    g_hl);
    cudaGetSymbolAddress((void**)&wh,    g_wh);
    cudaGetSymbolAddress((void**)&wl,    g_wl);

    // ---- preconvert all weights to bf16 hi/lo ----
    auto conv = [&](const float* W, size_t off, int n) {
        int n4 = n / 4;
        split_w_kernel<<<(n4 + 255) / 256, 256>>>(
            (const float4*)W, (__nv_bfloat162*)(wh + off), (__nv_bfloat162*)(wl + off), n4);
    };
    conv(att_Wk, OFF_WK, NDD);
    conv(att_Wv, OFF_WV, NDD);
    conv(att_Wr, OFF_WR, NDD);
    conv(att_Wo, OFF_WO, NDD);
    conv(ffn_Wk, OFF_FK, NDF);
    conv(ffn_Wv, OFF_FV, NDF);
    conv(ffn_Wr, OFF_FR, NDD);

    // x = LN0(emb[tokens])
    embed_ln_kernel<<<MM, 256>>>(tokens, emb, ln0_w, ln0_b, x);

    for (int l = 0; l < Ll; l++) {
        // ---- time mixing: fused LN1 + mix3 ----
        lnmix_kernel<3><<<MM, 256>>>(x, ln1_w + l * Dd, ln1_b + l * Dd,
                                     att_mix_k + l * Dd, att_mix_v + l * Dd, att_mix_r + l * Dd,
                                     mixh, mixl);

        // k/v/r = mix @ {Wk,Wv,Wr}
        {
            GPack pk{};
            for (int z = 0; z < 3; z++) {
                pk.g[z].Ah = mixh + z * MD; pk.g[z].Al = mixl + z * MD;
                size_t wo = (z == 0 ? OFF_WK : z == 1 ? OFF_WV : OFF_WR) + (size_t)l * Dd * Dd;
                pk.g[z].Wh = wh + wo; pk.g[z].Wl = wl + wo;
                pk.g[z].C = kvr + z * MD;
                pk.g[z].Ng = Dd; pk.g[z].Kg = Dd; pk.g[z].kOff = 0; pk.g[z].lda = Dd; pk.g[z].epi = 0;
            }
            gemm_tc<<<dim3(Dd / GBN, MM / GBM, 3), 128>>>(pk);
        }

        // sequential WKV, gated by sigmoid(r), bf16 hi/lo output
        wkv_kernel<<<(Bb * Dd) / 32, 32>>>(kvr, kvr + MD, kvr + 2 * MD,
                                           time_first + l * Dd, time_decay + l * Dd,
                                           rwkvh, rwkvl);

        // Wo GEMM, split-K=2 -> partials
        {
            GPack pk{};
            for (int z = 0; z < 2; z++) {
                pk.g[z].Ah = rwkvh; pk.g[z].Al = rwkvl;
                size_t wo = OFF_WO + (size_t)l * Dd * Dd;
                pk.g[z].Wh = wh + wo; pk.g[z].Wl = wl + wo;
                pk.g[z].C = part + z * MD;
                pk.g[z].Ng = Dd; pk.g[z].Kg = Dd / 2; pk.g[z].kOff = z * (Dd / 2);
                pk.g[z].lda = Dd; pk.g[z].epi = 0;
            }
            gemm_tc<<<dim3(Dd / GBN, MM / GBM, 2), 128>>>(pk);
        }
        // x += p0 + p1
        red_wo_kernel<<<MD / 1024, 256>>>((float4*)x, (const float4*)part, (const float4*)(part + MD));

        // ---- channel mixing: fused LN2 + mix2 ----
        lnmix_kernel<2><<<MM, 256>>>(x, ln2_w + l * Dd, ln2_b + l * Dd,
                                     ffn_mix_k + l * Dd, nullptr, ffn_mix_r + l * Dd,
                                     mixh, mixl);

        // Batched FK (sqrelu -> hh/hl) + FR (sigmoid -> r2)
        {
            GPack pk{};
            pk.g[0].Ah = mixh; pk.g[0].Al = mixl;
            pk.g[0].Wh = wh + OFF_FK + (size_t)l * Dd * Ff;
            pk.g[0].Wl = wl + OFF_FK + (size_t)l * Dd * Ff;
            pk.g[0].C2h = hh; pk.g[0].C2l = hl;
            pk.g[0].Ng = Ff; pk.g[0].Kg = Dd; pk.g[0].kOff = 0; pk.g[0].lda = Dd; pk.g[0].epi = 2;
            pk.g[1].Ah = mixh + MD; pk.g[1].Al = mixl + MD;
            pk.g[1].Wh = wh + OFF_FR + (size_t)l * Dd * Dd;
            pk.g[1].Wl = wl + OFF_FR + (size_t)l * Dd * Dd;
            pk.g[1].C = r2;
            pk.g[1].Ng = Dd; pk.g[1].Kg = Dd; pk.g[1].kOff = 0; pk.g[1].lda = Dd; pk.g[1].epi = 3;
            gemm_tc<<<dim3(Ff / GBN, MM / GBM, 2), 128>>>(pk);
        }

        // FV GEMM, split-K=4 -> partials
        {
            GPack pk{};
            for (int z = 0; z < 4; z++) {
                pk.g[z].Ah = hh; pk.g[z].Al = hl;
                size_t wo = OFF_FV + (size_t)l * Ff * Dd;
                pk.g[z].Wh = wh + wo; pk.g[z].Wl = wl + wo;
                pk.g[z].C = part + z * MD;
                pk.g[z].Ng = Dd; pk.g[z].Kg = Ff / 4; pk.g[z].kOff = z * (Ff / 4);
                pk.g[z].lda = Ff; pk.g[z].epi = 0;
            }
            gemm_tc<<<dim3(Dd / GBN, MM / GBM, 4), 128>>>(pk);
        }
        // x += r2 * (p0+p1+p2+p3)
        red_fv_kernel<<<MD / 1024, 256>>>((float4*)x, (const float4*)r2,
                                          (const float4*)part, (const float4*)(part + MD),
                                          (const float4*)(part + 2 * MD), (const float4*)(part + 3 * MD));
    }

    // out = LN_out(x)
    ln_kernel<<<MM, 256>>>(x, lnout_w, lnout_b, out);
}

// round 7
// speedup vs baseline: 2.9800x; 1.2843x over previous
#include <cuda_runtime.h>
#include <cuda_fp16.h>
#include <mma.h>
#include <math.h>
#include <cstdint>

using namespace nvcuda;

// Constants
#define Ll 12
#define Dd 768
#define Bb 4
#define Tt 256
#define Ff 3072
#define MM (Bb*Tt)   // 1024
#define MD (MM*Dd)

// transposed fp16 weight offsets (elements), layout [N,K] per layer slice
#define NDD (Ll*Dd*Dd)
#define NDF (Ll*Dd*Ff)
#define OFF_WK 0
#define OFF_WV (NDD)
#define OFF_WR (2*NDD)
#define OFF_WO (3*NDD)
#define OFF_FK (4*NDD)
#define OFF_FV (4*NDD + NDF)
#define OFF_FR (4*NDD + 2*NDF)
#define NWTOT  (4*NDD + 2*NDF + NDD)

// ---------------- scratch (device globals) ----------
__device__ __align__(256) float g_x[MD];
__device__ __align__(256) float g_kvr[3*MD];
__device__ __align__(256) float g_r2[MD];
__device__ __align__(256) float g_part[3*MD];
__device__ __align__(256) __half g_mixh[3*MD];
__device__ __align__(256) __half g_mixl[3*MD];
__device__ __align__(256) __half g_rwkvh[MD];
__device__ __align__(256) __half g_rwkvl[MD];
__device__ __align__(256) __half g_hh[MM*Ff];
__device__ __align__(256) __half g_hl[MM*Ff];
__device__ __align__(256) __half g_w[NWTOT];     // W^T fp16  [N,K]

__device__ __forceinline__ void split_h(float x, __half& h, __half& l) {
    h = __float2half(x);
    l = __float2half(x - __half2float(h));
}

// ---------------- cp.async helpers ----------------
__device__ __forceinline__ void cpa16(void* dst, const void* src) {
    unsigned d = (unsigned)__cvta_generic_to_shared(dst);
    asm volatile("cp.async.cg.shared.global [%0], [%1], 16;" :: "r"(d), "l"(src));
}
__device__ __forceinline__ void cp_commit() { asm volatile("cp.async.commit_group;"); }
template<int N> __device__ __forceinline__ void cp_wait() {
    asm volatile("cp.async.wait_group %0;" :: "n"(N));
}

// ---------------- transpose + convert:  W[K,N] fp32 -> W^T fp16 [N,K] ------
__global__ void transposeW_kernel(const float* __restrict__ W,
                                  __half* __restrict__ out,
                                  int K, int N) {
    __shared__ float t[32][33];
    const float* Wl = W + (size_t)blockIdx.z * K * N;
    size_t ob = (size_t)blockIdx.z * K * N;
    int k0 = blockIdx.x * 32, n0 = blockIdx.y * 32;
    #pragma unroll
    for (int i = threadIdx.y; i < 32; i += 8)
        t[i][threadIdx.x] = Wl[(size_t)(k0 + i) * N + n0 + threadIdx.x];
    __syncthreads();
    #pragma unroll
    for (int i = threadIdx.y; i < 32; i += 8)
        out[ob + (size_t)(n0 + i) * K + k0 + threadIdx.x] = __float2half(t[threadIdx.x][i]);
}

// ---------------- block reduces ----------------
__device__ __forceinline__ float blockReduceSum(float v, float* sh) {
    int lane = threadIdx.x & 31, w = threadIdx.x >> 5;
    #pragma unroll
    for (int o = 16; o; o >>= 1) v += __shfl_xor_sync(0xffffffffu, v, o);
    if (lane == 0) sh[w] = v;
    __syncthreads();
    float r;
    if (threadIdx.x < 8) {
        r = sh[threadIdx.x];
        #pragma unroll
        for (int o = 4; o; o >>= 1) r += __shfl_xor_sync(0x000000ffu, r, o);
        if (threadIdx.x == 0) sh[0] = r;
    }
    __syncthreads();
    r = sh[0];
    __syncthreads();
    return r;
}
__device__ __forceinline__ float2 blockReduceSum2(float2 v, float2* sh) {
    int lane = threadIdx.x & 31, w = threadIdx.x >> 5;
    #pragma unroll
    for (int o = 16; o; o >>= 1) {
        v.x += __shfl_xor_sync(0xffffffffu, v.x, o);
        v.y += __shfl_xor_sync(0xffffffffu, v.y, o);
    }
    if (lane == 0) sh[w] = v;
    __syncthreads();
    float2 r;
    if (threadIdx.x < 8) {
        r = sh[threadIdx.x];
        #pragma unroll
        for (int o = 4; o; o >>= 1) {
            r.x += __shfl_xor_sync(0x000000ffu, r.x, o);
            r.y += __shfl_xor_sync(0x000000ffu, r.y, o);
        }
        if (threadIdx.x == 0) sh[0] = r;
    }
    __syncthreads();
    r = sh[0];
    __syncthreads();
    return r;
}

// ---------------- embedding gather + LN (ln0) ----------------
__global__ void embed_ln_kernel(const int* __restrict__ tokens,
                                const float* __restrict__ emb,
                                const float* __restrict__ w,
                                const float* __restrict__ b,
                                float* __restrict__ Y) {
    __shared__ float sh[8];
    int m = blockIdx.x;
    int tok = tokens[m];
    const float* xr = emb + (size_t)tok * Dd;
    int i0 = threadIdx.x, i1 = i0 + 256, i2 = i0 + 512;
    float v0 = xr[i0], v1 = xr[i1], v2 = xr[i2];
    float s = blockReduceSum(v0 + v1 + v2, sh);
    float mu = s * (1.0f / 768.0f);
    float c0 = v0 - mu, c1 = v1 - mu, c2 = v2 - mu;
    float ss = blockReduceSum(c0*c0 + c1*c1 + c2*c2, sh);
    float inv = rsqrtf(ss * (1.0f / 768.0f) + 1e-5f);
    float* yr = Y + (size_t)m * Dd;
    yr[i0] = c0 * inv * w[i0] + b[i0];
    yr[i1] = c1 * inv * w[i1] + b[i1];
    yr[i2] = c2 * inv * w[i2] + b[i2];
}

// ---------------- final LN ----------------
__global__ void ln_kernel(const float* __restrict__ X,
                          const float* __restrict__ w,
                          const float* __restrict__ b,
                          float* __restrict__ Y) {
    __shared__ float sh[8];
    int m = blockIdx.x;
    const float* xr = X + (size_t)m * Dd;
    int i0 = threadIdx.x, i1 = i0 + 256, i2 = i0 + 512;
    float v0 = xr[i0], v1 = xr[i1], v2 = xr[i2];
    float s = blockReduceSum(v0 + v1 + v2, sh);
    float mu = s * (1.0f / 768.0f);
    float c0 = v0 - mu, c1 = v1 - mu, c2 = v2 - mu;
    float ss = blockReduceSum(c0*c0 + c1*c1 + c2*c2, sh);
    float inv = rsqrtf(ss * (1.0f / 768.0f) + 1e-5f);
    float* yr = Y + (size_t)m * Dd;
    yr[i0] = c0 * inv * w[i0] + b[i0];
    yr[i1] = c1 * inv * w[i1] + b[i1];
    yr[i2] = c2 * inv * w[i2] + b[i2];
}

// ---------------- fused LN + token-shift mix -> fp16 hi/lo ----------------
template<int NMIX>
__global__ void lnmix_kernel(const float* __restrict__ X,
                             const float* __restrict__ w,
                             const float* __restrict__ b,
                             const float* __restrict__ mk,
                             const float* __restrict__ mv,
                             const float* __restrict__ mr,
                             __half* __restrict__ oh,
                             __half* __restrict__ ol) {
    __shared__ float2 sh[8];
    int m = blockIdx.x;
    bool hasPrev = (m & (Tt - 1)) != 0;
    const float* xc = X + (size_t)m * Dd;
    const float* xp = X + (size_t)(m - 1) * Dd;
    int i0 = threadIdx.x, i1 = i0 + 256, i2 = i0 + 512;
    float c0 = xc[i0], c1 = xc[i1], c2 = xc[i2];
    float p0 = 0.f, p1 = 0.f, p2 = 0.f;
    if (hasPrev) { p0 = xp[i0]; p1 = xp[i1]; p2 = xp[i2]; }
    float2 s = blockReduceSum2(make_float2(c0 + c1 + c2, p0 + p1 + p2), sh);
    float muc = s.x * (1.0f / 768.0f), mup = s.y * (1.0f / 768.0f);
    float cc0 = c0 - muc, cc1 = c1 - muc, cc2 = c2 - muc;
    float pc0 = p0 - mup, pc1 = p1 - mup, pc2 = p2 - mup;
    float2 ss = blockReduceSum2(make_float2(cc0*cc0 + cc1*cc1 + cc2*cc2,
                                            pc0*pc0 + pc1*pc1 + pc2*pc2), sh);
    float invc = rsqrtf(ss.x * (1.0f / 768.0f) + 1e-5f);
    float invp = rsqrtf(ss.y * (1.0f / 768.0f) + 1e-5f);

    size_t base = (size_t)m * Dd;
    #pragma unroll
    for (int q = 0; q < 3; q++) {
        int i = threadIdx.x + q * 256;
        float cv = (q == 0 ? cc0 : q == 1 ? cc1 : cc2) * invc * w[i] + b[i];
        float pv = 0.0f;
        if (hasPrev)
            pv = (q == 0 ? pc0 : q == 1 ? pc1 : pc2) * invp * w[i] + b[i];
        float a = mk[i];
        float xk = cv * a + pv * (1.0f - a);
        split_h(xk, oh[base + i], ol[base + i]);
        if (NMIX == 3) {
            float c = mv[i];
            float xv = cv * c + pv * (1.0f - c);
            split_h(xv, oh[MD + base + i], ol[MD + base + i]);
        }
        float e = mr[i];
        float xr = cv * e + pv * (1.0f - e);
        int slot = (NMIX == 3) ? 2 : 1;
        split_h(xr, oh[slot * MD + base + i], ol[slot * MD + base + i]);
    }
}

// ---------------- WKV sequential recurrence (per-channel) ----------------
__global__ void wkv_kernel(const float* __restrict__ k,
                           const float* __restrict__ v,
                           const float* __restrict__ r,
                           const float* __restrict__ tf,
                           const float* __restrict__ td,
                           __half* __restrict__ oh,
                           __half* __restrict__ ol) {
    int ch = blockIdx.x * 32 + threadIdx.x;
    int b = ch / Dd, d = ch % Dd;
    float tfd = tf[d], tdd = td[d];
    float aa = 0.0f, bb = 0.0f, pp = -1e30f;
    size_t base = (size_t)b * Tt * Dd + d;
    float kb[2], vb[2], rb[2];
    kb[0] = k[base];        vb[0] = v[base];        rb[0] = r[base];
    kb[1] = k[base + Dd];   vb[1] = v[base + Dd];   rb[1] = r[base + Dd];
    for (int t = 0; t < Tt; t++) {
        float kc = kb[t & 1], vc = vb[t & 1], rc = rb[t & 1];
        if (t + 2 < Tt) {
            size_t nb = base + (size_t)(t + 2) * Dd;
            kb[t & 1] = k[nb]; vb[t & 1] = v[nb]; rb[t & 1] = r[nb];
        }
        float ww = tfd + kc;
        float p  = fmaxf(pp, ww);
        float e1 = __expf(pp - p);
        float e2 = __expf(ww - p);
        float wkv = __fdividef(e1 * aa + e2 * vc, e1 * bb + e2);
        float sr = __fdividef(1.0f, 1.0f + __expf(-rc));
        float ov = sr * wkv;
        size_t oi = base + (size_t)t * Dd;
        __half h = __float2half(ov);
        oh[oi] = h;
        ol[oi] = __float2half(ov - __half2float(h));
        float ww2 = pp + tdd;
        float p2  = fmaxf(ww2, kc);
        float e1b = __expf(ww2 - p2);
        float e2b = __expf(kc - p2);
        aa = e1b * aa + e2b * vc;
        bb = e1b * bb + e2b;
        pp = p2;
    }
}

// ---------------- split-K reductions (3 partials) ----------------
__global__ void red_wo_kernel(float4* __restrict__ x,
                              const float4* __restrict__ p0,
                              const float4* __restrict__ p1,
                              const float4* __restrict__ p2) {
    int i = blockIdx.x * 256 + threadIdx.x;
    float4 a = x[i], u = p0[i], v = p1[i], w = p2[i];
    a.x += u.x + v.x + w.x; a.y += u.y + v.y + w.y;
    a.z += u.z + v.z + w.z; a.w += u.w + v.w + w.w;
    x[i] = a;
}
__global__ void red_fv_kernel(float4* __restrict__ x,
                              const float4* __restrict__ g,
                              const float4* __restrict__ p0,
                              const float4* __restrict__ p1,
                              const float4* __restrict__ p2) {
    int i = blockIdx.x * 256 + threadIdx.x;
    float4 a = x[i], gg = g[i];
    float4 u0 = p0[i], u1 = p1[i], u2 = p2[i];
    a.x += gg.x * (u0.x + u1.x + u2.x);
    a.y += gg.y * (u0.y + u1.y + u2.y);
    a.z += gg.z * (u0.z + u1.z + u2.z);
    a.w += gg.w * (u0.w + u1.w + u2.w);
    x[i] = a;
}

// ---------------- tensor-core GEMM: fp16 2-term (Ah+Al) x W, fp32 acc -----
// A: [M,lda] fp16 hi/lo row-major. W: W^T [N,ldb] fp16 (K contiguous).
// BM=128, BN=128, BK=32; 256 threads = 8 warps (2m x 4n), warp tile 64x32.
// epi: 0 = store fp32; 2 = sqrelu -> fp16 hi/lo; 3 = sigmoid -> fp32
struct GArg {
    const __half *Ah, *Al, *W;
    float* C;
    __half *C2h, *C2l;
    int Ng, Kg, kOff, lda, ldb, epi;
};
struct GPack { GArg g[4]; };

#define BM 128
#define BN 128
#define BK 32
#define AST 40   // padded row stride (halves)

struct Stage {
    __half Ah[BM][AST];
    __half Al[BM][AST];
    __half Bw[BN][AST];
};
// 2 stages = 61440 B; C staging = 128*132*4 = 67584 B -> dynamic smem 67584
#define GSMEM 67584

__global__ __launch_bounds__(256)
void gemm_h(GPack pk) {
    GArg ga = pk.g[blockIdx.z];
    const int n0 = blockIdx.x * BN;
    if (n0 >= ga.Ng) return;

    extern __shared__ __align__(16) char smraw[];
    Stage* st = reinterpret_cast<Stage*>(smraw);
    float (*Csm)[BN + 4] = reinterpret_cast<float(*)[BN + 4]>(smraw);

    const int tid = threadIdx.x;
    const int wid = tid >> 5;
    const int wm = wid & 1;        // 0..1 -> 64 rows each
    const int wn = wid >> 1;       // 0..3 -> 32 cols each
    const int m0 = blockIdx.y * BM;

    const int ar = tid >> 1;           // 0..127
    const int ac = (tid & 1) * 16;     // 0 or 16

    const __half* pAh = ga.Ah + (size_t)(m0 + ar) * ga.lda + ga.kOff + ac;
    const __half* pAl = ga.Al + (size_t)(m0 + ar) * ga.lda + ga.kOff + ac;
    const __half* pW  = ga.W  + (size_t)(n0 + ar) * ga.ldb + ga.kOff + ac;

    wmma::fragment<wmma::accumulator, 16, 16, 16, float> acc[4][2];
    #pragma unroll
    for (int i = 0; i < 4; i++)
        #pragma unroll
        for (int j = 0; j < 2; j++)
            wmma::fill_fragment(acc[i][j], 0.0f);

    const int nk = ga.Kg / BK;

    auto issue = [&](int s, int c) {
        int k0 = c * BK;
        cpa16(&st[s].Ah[ar][ac],     pAh + k0);
        cpa16(&st[s].Ah[ar][ac + 8], pAh + k0 + 8);
        cpa16(&st[s].Al[ar][ac],     pAl + k0);
        cpa16(&st[s].Al[ar][ac + 8], pAl + k0 + 8);
        cpa16(&st[s].Bw[ar][ac],     pW + k0);
        cpa16(&st[s].Bw[ar][ac + 8], pW + k0 + 8);
        cp_commit();
    };

    issue(0, 0);

    for (int c = 0; c < nk; c++) {
        if (c + 1 < nk) {
            issue((c + 1) & 1, c + 1);
            cp_wait<1>();
        } else {
            cp_wait<0>();
        }
        __syncthreads();

        Stage& S = st[c & 1];
        #pragma unroll
        for (int kk = 0; kk < BK; kk += 16) {
            wmma::fragment<wmma::matrix_b, 16, 16, 16, __half, wmma::col_major> bf[2];
            #pragma unroll
            for (int j = 0; j < 2; j++)
                wmma::load_matrix_sync(bf[j], &S.Bw[wn * 32 + j * 16][kk], AST);

            wmma::fragment<wmma::matrix_a, 16, 16, 16, __half, wmma::row_major> af[4];
            #pragma unroll
            for (int i = 0; i < 4; i++)
                wmma::load_matrix_sync(af[i], &S.Ah[wm * 64 + i * 16][kk], AST);
            #pragma unroll
            for (int i = 0; i < 4; i++)
                #pragma unroll
                for (int j = 0; j < 2; j++)
                    wmma::mma_sync(acc[i][j], af[i], bf[j], acc[i][j]);

            #pragma unroll
            for (int i = 0; i < 4; i++)
                wmma::load_matrix_sync(af[i], &S.Al[wm * 64 + i * 16][kk], AST);
            #pragma unroll
            for (int i = 0; i < 4; i++)
                #pragma unroll
                for (int j = 0; j < 2; j++)
                    wmma::mma_sync(acc[i][j], af[i], bf[j], acc[i][j]);
        }
        __syncthreads();
    }

    // ---- epilogue: stage C through smem (reuses stage memory) ----
    #pragma unroll
    for (int i = 0; i < 4; i++)
        #pragma unroll
        for (int j = 0; j < 2; j++)
            wmma::store_matrix_sync(&Csm[wm * 64 + i * 16][wn * 32 + j * 16],
                                    acc[i][j], BN + 4, wmma::mem_row_major);
    __syncthreads();

    const int ecol = tid & 127;
    const int erow = tid >> 7;   // 0..1
    const int Ng = ga.Ng, epi = ga.epi;
    #pragma unroll
    for (int i = 0; i < 64; i++) {
        int rr = i * 2 + erow;
        size_t idx = (size_t)(m0 + rr) * Ng + n0 + ecol;
        float val = Csm[rr][ecol];
        if (epi == 0) {
            ga.C[idx] = val;
        } else if (epi == 2) {
            float t0 = fmaxf(val, 0.0f);
            float hv = t0 * t0;
            __half h = __float2half(hv);
            ga.C2h[idx] = h;
            ga.C2l[idx] = __float2half(hv - __half2float(h));
        } else {
            ga.C[idx] = __fdividef(1.0f, 1.0f + __expf(-val));
        }
    }
}

// ---------------- host launcher ----------------
extern "C" void kernel_launch(void* const* d_in, const int* in_sizes, int n_in,
                              void* d_out, int out_size) {
    const int*   tokens     = (const int*)  d_in[0];
    const float* emb        = (const float*)d_in[1];
    const float* ln0_w      = (const float*)d_in[2];
    const float* ln0_b      = (const float*)d_in[3];
    const float* ln1_w      = (const float*)d_in[4];
    const float* ln1_b      = (const float*)d_in[5];
    const float* ln2_w      = (const float*)d_in[6];
    const float* ln2_b      = (const float*)d_in[7];
    const float* att_mix_k  = (const float*)d_in[8];
    const float* att_mix_v  = (const float*)d_in[9];
    const float* att_mix_r  = (const float*)d_in[10];
    const float* time_first = (const float*)d_in[11];
    const float* time_decay = (const float*)d_in[12];
    const float* att_Wk     = (const float*)d_in[13];
    const float* att_Wv     = (const float*)d_in[14];
    const float* att_Wr     = (const float*)d_in[15];
    const float* att_Wo     = (const float*)d_in[16];
    const float* ffn_mix_k  = (const float*)d_in[17];
    const float* ffn_mix_r  = (const float*)d_in[18];
    const float* ffn_Wk     = (const float*)d_in[19];
    const float* ffn_Wv     = (const float*)d_in[20];
    const float* ffn_Wr     = (const float*)d_in[21];
    const float* lnout_w    = (const float*)d_in[22];
    const float* lnout_b    = (const float*)d_in[23];
    float* out = (float*)d_out;

    float *x, *kvr, *r2, *part;
    __half *mixh, *mixl, *rwkvh, *rwkvl, *hh, *hl, *w16;
    cudaGetSymbolAddress((void**)&x,     g_x);
    cudaGetSymbolAddress((void**)&kvr,   g_kvr);
    cudaGetSymbolAddress((void**)&r2,    g_r2);
    cudaGetSymbolAddress((void**)&part,  g_part);
    cudaGetSymbolAddress((void**)&mixh,  g_mixh);
    cudaGetSymbolAddress((void**)&mixl,  g_mixl);
    cudaGetSymbolAddress((void**)&rwkvh, g_rwkvh);
    cudaGetSymbolAddress((void**)&rwkvl, g_rwkvl);
    cudaGetSymbolAddress((void**)&hh,    g_hh);
    cudaGetSymbolAddress((void**)&hl,    g_hl);
    cudaGetSymbolAddress((void**)&w16,   g_w);

    cudaFuncSetAttribute(gemm_h, cudaFuncAttributeMaxDynamicSharedMemorySize, GSMEM);

    // ---- transpose + convert all weights: W[K,N] fp32 -> W^T fp16 [N,K] ----
    dim3 tb(32, 8);
    transposeW_kernel<<<dim3(Dd/32, Dd/32, Ll), tb>>>(att_Wk, w16 + OFF_WK, Dd, Dd);
    transposeW_kernel<<<dim3(Dd/32, Dd/32, Ll), tb>>>(att_Wv, w16 + OFF_WV, Dd, Dd);
    transposeW_kernel<<<dim3(Dd/32, Dd/32, Ll), tb>>>(att_Wr, w16 + OFF_WR, Dd, Dd);
    transposeW_kernel<<<dim3(Dd/32, Dd/32, Ll), tb>>>(att_Wo, w16 + OFF_WO, Dd, Dd);
    transposeW_kernel<<<dim3(Dd/32, Ff/32, Ll), tb>>>(ffn_Wk, w16 + OFF_FK, Dd, Ff);
    transposeW_kernel<<<dim3(Ff/32, Dd/32, Ll), tb>>>(ffn_Wv, w16 + OFF_FV, Ff, Dd);
    transposeW_kernel<<<dim3(Dd/32, Dd/32, Ll), tb>>>(ffn_Wr, w16 + OFF_FR, Dd, Dd);

    // x = LN0(emb[tokens])
    embed_ln_kernel<<<MM, 256>>>(tokens, emb, ln0_w, ln0_b, x);

    for (int l = 0; l < Ll; l++) {
        // ---- time mixing ----
        lnmix_kernel<3><<<MM, 256>>>(x, ln1_w + l * Dd, ln1_b + l * Dd,
                                     att_mix_k + l * Dd, att_mix_v + l * Dd, att_mix_r + l * Dd,
                                     mixh, mixl);
        // k/v/r = mix @ {Wk,Wv,Wr}   (z-batched)
        {
            GPack pk{};
            for (int z = 0; z < 3; z++) {
                pk.g[z].Ah = mixh + z * MD; pk.g[z].Al = mixl + z * MD;
                size_t wo = (z == 0 ? OFF_WK : z == 1 ? OFF_WV : OFF_WR) + (size_t)l * Dd * Dd;
                pk.g[z].W = w16 + wo;
                pk.g[z].C = kvr + z * MD;
                pk.g[z].Ng = Dd; pk.g[z].Kg = Dd; pk.g[z].kOff = 0;
                pk.g[z].lda = Dd; pk.g[z].ldb = Dd; pk.g[z].epi = 0;
            }
            gemm_h<<<dim3(Dd / BN, MM / BM, 3), 256, GSMEM>>>(pk);
        }
        // sequential WKV
        wkv_kernel<<<(Bb * Dd) / 32, 32>>>(kvr, kvr + MD, kvr + 2 * MD,
                                           time_first + l * Dd, time_decay + l * Dd,
                                           rwkvh, rwkvl);
        // Wo GEMM, split-K=3 -> partials
        {
            GPack pk{};
            for (int z = 0; z < 3; z++) {
                pk.g[z].Ah = rwkvh; pk.g[z].Al = rwkvl;
                pk.g[z].W = w16 + OFF_WO + (size_t)l * Dd * Dd;
                pk.g[z].C = part + z * MD;
                pk.g[z].Ng = Dd; pk.g[z].Kg = Dd / 3; pk.g[z].kOff = z * (Dd / 3);
                pk.g[z].lda = Dd; pk.g[z].ldb = Dd; pk.g[z].epi = 0;
            }
            gemm_h<<<dim3(Dd / BN, MM / BM, 3), 256, GSMEM>>>(pk);
        }
        red_wo_kernel<<<MD / 1024, 256>>>((float4*)x, (const float4*)part,
                                          (const float4*)(part + MD), (const float4*)(part + 2 * MD));

        // ---- channel mixing ----
        lnmix_kernel<2><<<MM, 256>>>(x, ln2_w + l * Dd, ln2_b + l * Dd,
                                     ffn_mix_k + l * Dd, nullptr, ffn_mix_r + l * Dd,
                                     mixh, mixl);
        // FK: h = sqrelu(xk2 @ ffn_Wk) -> fp16 hi/lo
        {
            GPack pk{};
            pk.g[0].Ah = mixh; pk.g[0].Al = mixl;
            pk.g[0].W = w16 + OFF_FK + (size_t)l * Dd * Ff;
            pk.g[0].C2h = hh; pk.g[0].C2l = hl;
            pk.g[0].Ng = Ff; pk.g[0].Kg = Dd; pk.g[0].kOff = 0;
            pk.g[0].lda = Dd; pk.g[0].ldb = Dd; pk.g[0].epi = 2;
            gemm_h<<<dim3(Ff / BN, MM / BM, 1), 256, GSMEM>>>(pk);
        }
        // FV split-K=3 (z=0..2) batched with FR sigmoid (z=3)
        {
            GPack pk{};
            for (int z = 0; z < 3; z++) {
                pk.g[z].Ah = hh; pk.g[z].Al = hl;
                pk.g[z].W = w16 + OFF_FV + (size_t)l * Ff * Dd;
                pk.g[z].C = part + z * MD;
                pk.g[z].Ng = Dd; pk.g[z].Kg = Ff / 3; pk.g[z].kOff = z * (Ff / 3);
                pk.g[z].lda = Ff; pk.g[z].ldb = Ff; pk.g[z].epi = 0;
            }
            pk.g[3].Ah = mixh + MD; pk.g[3].Al = mixl + MD;
            pk.g[3].W = w16 + OFF_FR + (size_t)l * Dd * Dd;
            pk.g[3].C = r2;
            pk.g[3].Ng = Dd; pk.g[3].Kg = Dd; pk.g[3].kOff = 0;
            pk.g[3].lda = Dd; pk.g[3].ldb = Dd; pk.g[3].epi = 3;
            gemm_h<<<dim3(Dd / BN, MM / BM, 4), 256, GSMEM>>>(pk);
        }
        red_fv_kernel<<<MD / 1024, 256>>>((float4*)x, (const float4*)r2,
                                          (const float4*)part, (const float4*)(part + MD),
                                          (const float4*)(part + 2 * MD));
    }

    // out = LN_out(x)
    ln_kernel<<<MM, 256>>>(x, lnout_w, lnout_b, out);
}

// round 8
// speedup vs baseline: 4.4864x; 1.5055x over previous
#include <cuda_runtime.h>
#include <cuda_fp16.h>
#include <mma.h>
#include <math.h>
#include <cstdint>

using namespace nvcuda;

// Constants
#define Ll 12
#define Dd 768
#define Bb 4
#define Tt 256
#define Ff 3072
#define MM (Bb*Tt)   // 1024
#define MD (MM*Dd)

// transposed fp16 weight offsets (elements), layout [N,K] per layer slice
#define NDD (Ll*Dd*Dd)
#define NDF (Ll*Dd*Ff)
#define OFF_WK 0
#define OFF_WV (NDD)
#define OFF_WR (2*NDD)
#define OFF_WO (3*NDD)
#define OFF_FK (4*NDD)
#define OFF_FV (4*NDD + NDF)
#define OFF_FR (4*NDD + 2*NDF)
#define NWTOT  (4*NDD + 2*NDF + NDD)

// ---------------- scratch (device globals) ----------
__device__ __align__(256) float g_x[MD];        // residual ping
__device__ __align__(256) float g_x2[MD];       // residual pong
__device__ __align__(256) float g_kvr[3*MD];
__device__ __align__(256) float g_r2[MD];
__device__ __align__(256) float g_part[3*MD];
__device__ __align__(256) __half g_mixh[3*MD];  // mixed activations (fp16)
__device__ __align__(256) __half g_rwkvh[MD];
__device__ __align__(256) __half g_hh[MM*Ff];
__device__ __align__(256) __half g_w[NWTOT];    // W^T fp16 [N,K]

// ---------------- cp.async helpers ----------------
__device__ __forceinline__ void cpa16(void* dst, const void* src) {
    unsigned d = (unsigned)__cvta_generic_to_shared(dst);
    asm volatile("cp.async.cg.shared.global [%0], [%1], 16;" :: "r"(d), "l"(src));
}
__device__ __forceinline__ void cp_commit() { asm volatile("cp.async.commit_group;"); }
template<int N> __device__ __forceinline__ void cp_wait() {
    asm volatile("cp.async.wait_group %0;" :: "n"(N));
}

// ---------------- transpose + convert:  W[K,N] fp32 -> W^T fp16 [N,K] ------
__global__ void transposeW_kernel(const float* __restrict__ W,
                                  __half* __restrict__ out,
                                  int K, int N) {
    __shared__ float t[32][33];
    const float* Wl = W + (size_t)blockIdx.z * K * N;
    size_t ob = (size_t)blockIdx.z * K * N;
    int k0 = blockIdx.x * 32, n0 = blockIdx.y * 32;
    #pragma unroll
    for (int i = threadIdx.y; i < 32; i += 8)
        t[i][threadIdx.x] = Wl[(size_t)(k0 + i) * N + n0 + threadIdx.x];
    __syncthreads();
    #pragma unroll
    for (int i = threadIdx.y; i < 32; i += 8)
        out[ob + (size_t)(n0 + i) * K + k0 + threadIdx.x] = __float2half(t[threadIdx.x][i]);
}

// ---------------- block reduces ----------------
__device__ __forceinline__ float blockReduceSum(float v, float* sh) {
    int lane = threadIdx.x & 31, w = threadIdx.x >> 5;
    #pragma unroll
    for (int o = 16; o; o >>= 1) v += __shfl_xor_sync(0xffffffffu, v, o);
    if (lane == 0) sh[w] = v;
    __syncthreads();
    float r;
    if (threadIdx.x < 8) {
        r = sh[threadIdx.x];
        #pragma unroll
        for (int o = 4; o; o >>= 1) r += __shfl_xor_sync(0x000000ffu, r, o);
        if (threadIdx.x == 0) sh[0] = r;
    }
    __syncthreads();
    r = sh[0];
    __syncthreads();
    return r;
}
__device__ __forceinline__ float2 blockReduceSum2(float2 v, float2* sh) {
    int lane = threadIdx.x & 31, w = threadIdx.x >> 5;
    #pragma unroll
    for (int o = 16; o; o >>= 1) {
        v.x += __shfl_xor_sync(0xffffffffu, v.x, o);
        v.y += __shfl_xor_sync(0xffffffffu, v.y, o);
    }
    if (lane == 0) sh[w] = v;
    __syncthreads();
    float2 r;
    if (threadIdx.x < 8) {
        r = sh[threadIdx.x];
        #pragma unroll
        for (int o = 4; o; o >>= 1) {
            r.x += __shfl_xor_sync(0x000000ffu, r.x, o);
            r.y += __shfl_xor_sync(0x000000ffu, r.y, o);
        }
        if (threadIdx.x == 0) sh[0] = r;
    }
    __syncthreads();
    r = sh[0];
    __syncthreads();
    return r;
}

// ---------------- embedding gather + LN (ln0) ----------------
__global__ void embed_ln_kernel(const int* __restrict__ tokens,
                                const float* __restrict__ emb,
                                const float* __restrict__ w,
                                const float* __restrict__ b,
                                float* __restrict__ Y) {
    __shared__ float sh[8];
    int m = blockIdx.x;
    int tok = tokens[m];
    const float* xr = emb + (size_t)tok * Dd;
    int i0 = threadIdx.x, i1 = i0 + 256, i2 = i0 + 512;
    float v0 = xr[i0], v1 = xr[i1], v2 = xr[i2];
    float s = blockReduceSum(v0 + v1 + v2, sh);
    float mu = s * (1.0f / 768.0f);
    float c0 = v0 - mu, c1 = v1 - mu, c2 = v2 - mu;
    float ss = blockReduceSum(c0*c0 + c1*c1 + c2*c2, sh);
    float inv = rsqrtf(ss * (1.0f / 768.0f) + 1e-5f);
    float* yr = Y + (size_t)m * Dd;
    yr[i0] = c0 * inv * w[i0] + b[i0];
    yr[i1] = c1 * inv * w[i1] + b[i1];
    yr[i2] = c2 * inv * w[i2] + b[i2];
}

// ---------------- final LN with fused gated split-K reduction --------------
__global__ void ln_red_kernel(const float* __restrict__ X,
                              const float* __restrict__ g,
                              const float* __restrict__ q0,
                              const float* __restrict__ q1,
                              const float* __restrict__ q2,
                              const float* __restrict__ w,
                              const float* __restrict__ b,
                              float* __restrict__ Y) {
    __shared__ float sh[8];
    int m = blockIdx.x;
    size_t base = (size_t)m * Dd;
    int i0 = threadIdx.x, i1 = i0 + 256, i2 = i0 + 512;
    float v0 = X[base+i0] + g[base+i0] * (q0[base+i0] + q1[base+i0] + q2[base+i0]);
    float v1 = X[base+i1] + g[base+i1] * (q0[base+i1] + q1[base+i1] + q2[base+i1]);
    float v2 = X[base+i2] + g[base+i2] * (q0[base+i2] + q1[base+i2] + q2[base+i2]);
    float s = blockReduceSum(v0 + v1 + v2, sh);
    float mu = s * (1.0f / 768.0f);
    float c0 = v0 - mu, c1 = v1 - mu, c2 = v2 - mu;
    float ss = blockReduceSum(c0*c0 + c1*c1 + c2*c2, sh);
    float inv = rsqrtf(ss * (1.0f / 768.0f) + 1e-5f);
    float* yr = Y + base;
    yr[i0] = c0 * inv * w[i0] + b[i0];
    yr[i1] = c1 * inv * w[i1] + b[i1];
    yr[i2] = c2 * inv * w[i2] + b[i2];
}

// ------- fused [split-K reduce +] LN + token-shift mix -> fp16 -------------
// RED: 0 = none; 1 = x += q0+q1+q2; 2 = x += gate*(q0+q1+q2)
// When RED>0, writes the updated residual row m to Xout (ping-pong buffer).
template<int NMIX, int RED>
__global__ void lnmix_kernel(const float* __restrict__ X,
                             const float* __restrict__ gate,
                             const float* __restrict__ q0,
                             const float* __restrict__ q1,
                             const float* __restrict__ q2,
                             float* __restrict__ Xout,
                             const float* __restrict__ w,
                             const float* __restrict__ b,
                             const float* __restrict__ mk,
                             const float* __restrict__ mv,
                             const float* __restrict__ mr,
                             __half* __restrict__ oh) {
    __shared__ float2 sh[8];
    int m = blockIdx.x;
    bool hasPrev = (m & (Tt - 1)) != 0;
    size_t bc = (size_t)m * Dd;
    size_t bp = bc - Dd;

    float cur[3], prv[3];
    #pragma unroll
    for (int q = 0; q < 3; q++) {
        int i = threadIdx.x + q * 256;
        float v = X[bc + i];
        if (RED == 1) v += q0[bc+i] + q1[bc+i] + q2[bc+i];
        else if (RED == 2) v += gate[bc+i] * (q0[bc+i] + q1[bc+i] + q2[bc+i]);
        if (RED) Xout[bc + i] = v;
        cur[q] = v;
        float p = 0.0f;
        if (hasPrev) {
            p = X[bp + i];
            if (RED == 1) p += q0[bp+i] + q1[bp+i] + q2[bp+i];
            else if (RED == 2) p += gate[bp+i] * (q0[bp+i] + q1[bp+i] + q2[bp+i]);
        }
        prv[q] = p;
    }

    float2 s = blockReduceSum2(make_float2(cur[0]+cur[1]+cur[2], prv[0]+prv[1]+prv[2]), sh);
    float muc = s.x * (1.0f / 768.0f), mup = s.y * (1.0f / 768.0f);
    float cc[3], pc[3];
    #pragma unroll
    for (int q = 0; q < 3; q++) { cc[q] = cur[q] - muc; pc[q] = prv[q] - mup; }
    float2 ss = blockReduceSum2(make_float2(cc[0]*cc[0]+cc[1]*cc[1]+cc[2]*cc[2],
                                            pc[0]*pc[0]+pc[1]*pc[1]+pc[2]*pc[2]), sh);
    float invc = rsqrtf(ss.x * (1.0f / 768.0f) + 1e-5f);
    float invp = rsqrtf(ss.y * (1.0f / 768.0f) + 1e-5f);

    #pragma unroll
    for (int q = 0; q < 3; q++) {
        int i = threadIdx.x + q * 256;
        float cv = cc[q] * invc * w[i] + b[i];
        float pv = hasPrev ? (pc[q] * invp * w[i] + b[i]) : 0.0f;
        float a = mk[i];
        oh[bc + i] = __float2half(cv * a + pv * (1.0f - a));
        if (NMIX == 3) {
            float c = mv[i];
            oh[MD + bc + i] = __float2half(cv * c + pv * (1.0f - c));
        }
        float e = mr[i];
        int slot = (NMIX == 3) ? 2 : 1;
        oh[slot * MD + bc + i] = __float2half(cv * e + pv * (1.0f - e));
    }
}

// ---------------- WKV sequential recurrence (per-channel) ----------------
__global__ void wkv_kernel(const float* __restrict__ k,
                           const float* __restrict__ v,
                           const float* __restrict__ r,
                           const float* __restrict__ tf,
                           const float* __restrict__ td,
                           __half* __restrict__ oh) {
    int ch = blockIdx.x * 32 + threadIdx.x;
    int b = ch / Dd, d = ch % Dd;
    float tfd = tf[d], tdd = td[d];
    float aa = 0.0f, bb = 0.0f, pp = -1e30f;
    size_t base = (size_t)b * Tt * Dd + d;
    float kb[2], vb[2], rb[2];
    kb[0] = k[base];        vb[0] = v[base];        rb[0] = r[base];
    kb[1] = k[base + Dd];   vb[1] = v[base + Dd];   rb[1] = r[base + Dd];
    for (int t = 0; t < Tt; t++) {
        float kc = kb[t & 1], vc = vb[t & 1], rc = rb[t & 1];
        if (t + 2 < Tt) {
            size_t nb = base + (size_t)(t + 2) * Dd;
            kb[t & 1] = k[nb]; vb[t & 1] = v[nb]; rb[t & 1] = r[nb];
        }
        float ww = tfd + kc;
        float p  = fmaxf(pp, ww);
        float e1 = __expf(pp - p);
        float e2 = __expf(ww - p);
        float wkv = __fdividef(e1 * aa + e2 * vc, e1 * bb + e2);
        float sr = __fdividef(1.0f, 1.0f + __expf(-rc));
        oh[base + (size_t)t * Dd] = __float2half(sr * wkv);
        float ww2 = pp + tdd;
        float p2  = fmaxf(ww2, kc);
        float e1b = __expf(ww2 - p2);
        float e2b = __expf(kc - p2);
        aa = e1b * aa + e2b * vc;
        bb = e1b * bb + e2b;
        pp = p2;
    }
}

// ---------------- tensor-core GEMM: fp16 x fp16, fp32 acc ------------------
// A: [M,lda] fp16 row-major. W: W^T [N,ldb] fp16 (K contiguous).
// BM=128, BN=128, BK=32; 256 threads = 8 warps (2m x 4n), warp tile 64x32.
// epi: 0 = store fp32; 2 = sqrelu -> fp16; 3 = sigmoid -> fp32
struct GArg {
    const __half *A, *W;
    float* C;
    __half* C2;
    int Ng, Kg, kOff, lda, ldb, epi;
};
struct GPack { GArg g[4]; };

#define BM 128
#define BN 128
#define BK 32
#define AST 40   // padded row stride (halves)

struct Stage {
    __half Ah[BM][AST];
    __half Bw[BN][AST];
};
// 2 stages = 40960 B; C staging = 128*132*4 = 67584 B -> dynamic smem 67584
#define GSMEM 67584

__global__ __launch_bounds__(256)
void gemm_h(GPack pk) {
    GArg ga = pk.g[blockIdx.z];
    const int n0 = blockIdx.x * BN;
    if (n0 >= ga.Ng) return;

    extern __shared__ __align__(16) char smraw[];
    Stage* st = reinterpret_cast<Stage*>(smraw);
    float (*Csm)[BN + 4] = reinterpret_cast<float(*)[BN + 4]>(smraw);

    const int tid = threadIdx.x;
    const int wid = tid >> 5;
    const int wm = wid & 1;        // 0..1 -> 64 rows each
    const int wn = wid >> 1;       // 0..3 -> 32 cols each
    const int m0 = blockIdx.y * BM;

    const int ar = tid >> 1;           // 0..127
    const int ac = (tid & 1) * 16;     // 0 or 16

    const __half* pA = ga.A + (size_t)(m0 + ar) * ga.lda + ga.kOff + ac;
    const __half* pW = ga.W + (size_t)(n0 + ar) * ga.ldb + ga.kOff + ac;

    wmma::fragment<wmma::accumulator, 16, 16, 16, float> acc[4][2];
    #pragma unroll
    for (int i = 0; i < 4; i++)
        #pragma unroll
        for (int j = 0; j < 2; j++)
            wmma::fill_fragment(acc[i][j], 0.0f);

    const int nk = ga.Kg / BK;

    auto issue = [&](int s, int c) {
        int k0 = c * BK;
        cpa16(&st[s].Ah[ar][ac],     pA + k0);
        cpa16(&st[s].Ah[ar][ac + 8], pA + k0 + 8);
        cpa16(&st[s].Bw[ar][ac],     pW + k0);
        cpa16(&st[s].Bw[ar][ac + 8], pW + k0 + 8);
        cp_commit();
    };

    issue(0, 0);

    for (int c = 0; c < nk; c++) {
        if (c + 1 < nk) {
            issue((c + 1) & 1, c + 1);
            cp_wait<1>();
        } else {
            cp_wait<0>();
        }
        __syncthreads();

        Stage& S = st[c & 1];
        #pragma unroll
        for (int kk = 0; kk < BK; kk += 16) {
            wmma::fragment<wmma::matrix_b, 16, 16, 16, __half, wmma::col_major> bf[2];
            #pragma unroll
            for (int j = 0; j < 2; j++)
                wmma::load_matrix_sync(bf[j], &S.Bw[wn * 32 + j * 16][kk], AST);

            wmma::fragment<wmma::matrix_a, 16, 16, 16, __half, wmma::row_major> af[4];
            #pragma unroll
            for (int i = 0; i < 4; i++)
                wmma::load_matrix_sync(af[i], &S.Ah[wm * 64 + i * 16][kk], AST);
            #pragma unroll
            for (int i = 0; i < 4; i++)
                #pragma unroll
                for (int j = 0; j < 2; j++)
                    wmma::mma_sync(acc[i][j], af[i], bf[j], acc[i][j]);
        }
        __syncthreads();
    }

    // ---- epilogue: stage C through smem ----
    #pragma unroll
    for (int i = 0; i < 4; i++)
        #pragma unroll
        for (int j = 0; j < 2; j++)
            wmma::store_matrix_sync(&Csm[wm * 64 + i * 16][wn * 32 + j * 16],
                                    acc[i][j], BN + 4, wmma::mem_row_major);
    __syncthreads();

    const int ecol = tid & 127;
    const int erow = tid >> 7;   // 0..1
    const int Ng = ga.Ng, epi = ga.epi;
    #pragma unroll
    for (int i = 0; i < 64; i++) {
        int rr = i * 2 + erow;
        size_t idx = (size_t)(m0 + rr) * Ng + n0 + ecol;
        float val = Csm[rr][ecol];
        if (epi == 0) {
            ga.C[idx] = val;
        } else if (epi == 2) {
            float t0 = fmaxf(val, 0.0f);
            ga.C2[idx] = __float2half(t0 * t0);
        } else {
            ga.C[idx] = __fdividef(1.0f, 1.0f + __expf(-val));
        }
    }
}

// ---------------- host launcher ----------------
extern "C" void kernel_launch(void* const* d_in, const int* in_sizes, int n_in,
                              void* d_out, int out_size) {
    const int*   tokens     = (const int*)  d_in[0];
    const float* emb        = (const float*)d_in[1];
    const float* ln0_w      = (const float*)d_in[2];
    const float* ln0_b      = (const float*)d_in[3];
    const float* ln1_w      = (const float*)d_in[4];
    const float* ln1_b      = (const float*)d_in[5];
    const float* ln2_w      = (const float*)d_in[6];
    const float* ln2_b      = (const float*)d_in[7];
    const float* att_mix_k  = (const float*)d_in[8];
    const float* att_mix_v  = (const float*)d_in[9];
    const float* att_mix_r  = (const float*)d_in[10];
    const float* time_first = (const float*)d_in[11];
    const float* time_decay = (const float*)d_in[12];
    const float* att_Wk     = (const float*)d_in[13];
    const float* att_Wv     = (const float*)d_in[14];
    const float* att_Wr     = (const float*)d_in[15];
    const float* att_Wo     = (const float*)d_in[16];
    const float* ffn_mix_k  = (const float*)d_in[17];
    const float* ffn_mix_r  = (const float*)d_in[18];
    const float* ffn_Wk     = (const float*)d_in[19];
    const float* ffn_Wv     = (const float*)d_in[20];
    const float* ffn_Wr     = (const float*)d_in[21];
    const float* lnout_w    = (const float*)d_in[22];
    const float* lnout_b    = (const float*)d_in[23];
    float* out = (float*)d_out;

    float *xa, *xb, *kvr, *r2, *part;
    __half *mixh, *rwkvh, *hh, *w16;
    cudaGetSymbolAddress((void**)&xa,    g_x);
    cudaGetSymbolAddress((void**)&xb,    g_x2);
    cudaGetSymbolAddress((void**)&kvr,   g_kvr);
    cudaGetSymbolAddress((void**)&r2,    g_r2);
    cudaGetSymbolAddress((void**)&part,  g_part);
    cudaGetSymbolAddress((void**)&mixh,  g_mixh);
    cudaGetSymbolAddress((void**)&rwkvh, g_rwkvh);
    cudaGetSymbolAddress((void**)&hh,    g_hh);
    cudaGetSymbolAddress((void**)&w16,   g_w);

    cudaFuncSetAttribute(gemm_h, cudaFuncAttributeMaxDynamicSharedMemorySize, GSMEM);

    // ---- transpose + convert all weights: W[K,N] fp32 -> W^T fp16 [N,K] ----
    dim3 tb(32, 8);
    transposeW_kernel<<<dim3(Dd/32, Dd/32, Ll), tb>>>(att_Wk, w16 + OFF_WK, Dd, Dd);
    transposeW_kernel<<<dim3(Dd/32, Dd/32, Ll), tb>>>(att_Wv, w16 + OFF_WV, Dd, Dd);
    transposeW_kernel<<<dim3(Dd/32, Dd/32, Ll), tb>>>(att_Wr, w16 + OFF_WR, Dd, Dd);
    transposeW_kernel<<<dim3(Dd/32, Dd/32, Ll), tb>>>(att_Wo, w16 + OFF_WO, Dd, Dd);
    transposeW_kernel<<<dim3(Dd/32, Ff/32, Ll), tb>>>(ffn_Wk, w16 + OFF_FK, Dd, Ff);
    transposeW_kernel<<<dim3(Ff/32, Dd/32, Ll), tb>>>(ffn_Wv, w16 + OFF_FV, Ff, Dd);
    transposeW_kernel<<<dim3(Dd/32, Dd/32, Ll), tb>>>(ffn_Wr, w16 + OFF_FR, Dd, Dd);

    // x(a) = LN0(emb[tokens])
    embed_ln_kernel<<<MM, 256>>>(tokens, emb, ln0_w, ln0_b, xa);

    for (int l = 0; l < Ll; l++) {
        // ---- time mixing: [gated FV reduce +] LN1 + mix3 ----
        if (l == 0) {
            lnmix_kernel<3, 0><<<MM, 256>>>(xa, nullptr, nullptr, nullptr, nullptr, nullptr,
                                            ln1_w, ln1_b,
                                            att_mix_k, att_mix_v, att_mix_r, mixh);
        } else {
            lnmix_kernel<3, 2><<<MM, 256>>>(xb, r2, part, part + MD, part + 2 * MD, xa,
                                            ln1_w + l * Dd, ln1_b + l * Dd,
                                            att_mix_k + l * Dd, att_mix_v + l * Dd,
                                            att_mix_r + l * Dd, mixh);
        }
        // k/v/r = mix @ {Wk,Wv,Wr}
        {
            GPack pk{};
            for (int z = 0; z < 3; z++) {
                pk.g[z].A = mixh + z * MD;
                size_t wo = (z == 0 ? OFF_WK : z == 1 ? OFF_WV : OFF_WR) + (size_t)l * Dd * Dd;
                pk.g[z].W = w16 + wo;
                pk.g[z].C = kvr + z * MD;
                pk.g[z].Ng = Dd; pk.g[z].Kg = Dd; pk.g[z].kOff = 0;
                pk.g[z].lda = Dd; pk.g[z].ldb = Dd; pk.g[z].epi = 0;
            }
            gemm_h<<<dim3(Dd / BN, MM / BM, 3), 256, GSMEM>>>(pk);
        }
        // sequential WKV
        wkv_kernel<<<(Bb * Dd) / 32, 32>>>(kvr, kvr + MD, kvr + 2 * MD,
                                           time_first + l * Dd, time_decay + l * Dd, rwkvh);
        // Wo GEMM, split-K=3 -> partials
        {
            GPack pk{};
            for (int z = 0; z < 3; z++) {
                pk.g[z].A = rwkvh;
                pk.g[z].W = w16 + OFF_WO + (size_t)l * Dd * Dd;
                pk.g[z].C = part + z * MD;
                pk.g[z].Ng = Dd; pk.g[z].Kg = Dd / 3; pk.g[z].kOff = z * (Dd / 3);
                pk.g[z].lda = Dd; pk.g[z].ldb = Dd; pk.g[z].epi = 0;
            }
            gemm_h<<<dim3(Dd / BN, MM / BM, 3), 256, GSMEM>>>(pk);
        }
        // ---- channel mixing: Wo reduce + LN2 + mix2 (xa + parts -> xb) ----
        lnmix_kernel<2, 1><<<MM, 256>>>(xa, nullptr, part, part + MD, part + 2 * MD, xb,
                                        ln2_w + l * Dd, ln2_b + l * Dd,
                                        ffn_mix_k + l * Dd, nullptr, ffn_mix_r + l * Dd, mixh);
        // FK: h = sqrelu(xk2 @ ffn_Wk) -> fp16
        {
            GPack pk{};
            pk.g[0].A = mixh;
            pk.g[0].W = w16 + OFF_FK + (size_t)l * Dd * Ff;
            pk.g[0].C2 = hh;
            pk.g[0].Ng = Ff; pk.g[0].Kg = Dd; pk.g[0].kOff = 0;
            pk.g[0].lda = Dd; pk.g[0].ldb = Dd; pk.g[0].epi = 2;
            gemm_h<<<dim3(Ff / BN, MM / BM, 1), 256, GSMEM>>>(pk);
        }
        // FV split-K=3 (z=0..2) batched with FR sigmoid (z=3)
        {
            GPack pk{};
            for (int z = 0; z < 3; z++) {
                pk.g[z].A = hh;
                pk.g[z].W = w16 + OFF_FV + (size_t)l * Ff * Dd;
                pk.g[z].C = part + z * MD;
                pk.g[z].Ng = Dd; pk.g[z].Kg = Ff / 3; pk.g[z].kOff = z * (Ff / 3);
                pk.g[z].lda = Ff; pk.g[z].ldb = Ff; pk.g[z].epi = 0;
            }
            pk.g[3].A = mixh + MD;
            pk.g[3].W = w16 + OFF_FR + (size_t)l * Dd * Dd;
            pk.g[3].C = r2;
            pk.g[3].Ng = Dd; pk.g[3].Kg = Dd; pk.g[3].kOff = 0;
            pk.g[3].lda = Dd; pk.g[3].ldb = Dd; pk.g[3].epi = 3;
            gemm_h<<<dim3(Dd / BN, MM / BM, 4), 256, GSMEM>>>(pk);
        }
    }

    // out = LN_out(xb + r2*(parts))
    ln_red_kernel<<<MM, 256>>>(xb, r2, part, part + MD, part + 2 * MD,
                               lnout_w, lnout_b, out);
}

// round 9
// speedup vs baseline: 5.1758x; 1.1537x over previous
#include <cuda_runtime.h>
#include <cuda_fp16.h>
#include <mma.h>
#include <math.h>
#include <cstdint>

using namespace nvcuda;

// Constants
#define Ll 12
#define Dd 768
#define Bb 4
#define Tt 256
#define Ff 3072
#define MM (Bb*Tt)   // 1024
#define MD (MM*Dd)

// fp16 weight offsets (elements), NATIVE [K,N] layout per layer slice
#define NDD (Ll*Dd*Dd)
#define NDF (Ll*Dd*Ff)
#define OFF_WK 0
#define OFF_WV (NDD)
#define OFF_WR (2*NDD)
#define OFF_WO (3*NDD)
#define OFF_FK (4*NDD)
#define OFF_FV (4*NDD + NDF)
#define OFF_FR (4*NDD + 2*NDF)
#define NWTOT  (4*NDD + 2*NDF + NDD)

// ---------------- scratch (device globals) ----------
__device__ __align__(256) float g_x[MD];        // residual ping
__device__ __align__(256) float g_x2[MD];       // residual pong
__device__ __align__(256) float g_kvr[3*MD];
__device__ __align__(256) float g_r2[MD];
__device__ __align__(256) float g_part[3*MD];
__device__ __align__(256) __half g_mixh[3*MD];  // mixed activations (fp16)
__device__ __align__(256) __half g_rwkvh[MD];
__device__ __align__(256) __half g_hh[MM*Ff];
__device__ __align__(256) __half g_w[NWTOT];    // W fp16 [K,N] native

// ---------------- cp.async helpers ----------------
__device__ __forceinline__ void cpa16(void* dst, const void* src) {
    unsigned d = (unsigned)__cvta_generic_to_shared(dst);
    asm volatile("cp.async.cg.shared.global [%0], [%1], 16;" :: "r"(d), "l"(src));
}
__device__ __forceinline__ void cp_commit() { asm volatile("cp.async.commit_group;"); }
template<int N> __device__ __forceinline__ void cp_wait() {
    asm volatile("cp.async.wait_group %0;" :: "n"(N));
}

// ---------------- streaming convert: fp32 -> fp16 (no transpose) -----------
__global__ void convW_kernel(const float4* __restrict__ W,
                             uint4* __restrict__ out, int n8) {
    int i = blockIdx.x * 256 + threadIdx.x;
    if (i >= n8) return;
    float4 a = W[2*i], b = W[2*i+1];
    __half2 h0 = __floats2half2_rn(a.x, a.y);
    __half2 h1 = __floats2half2_rn(a.z, a.w);
    __half2 h2 = __floats2half2_rn(b.x, b.y);
    __half2 h3 = __floats2half2_rn(b.z, b.w);
    uint4 o;
    o.x = *(unsigned*)&h0; o.y = *(unsigned*)&h1;
    o.z = *(unsigned*)&h2; o.w = *(unsigned*)&h3;
    out[i] = o;
}

// ---------------- block reduces ----------------
__device__ __forceinline__ float blockReduceSum(float v, float* sh) {
    int lane = threadIdx.x & 31, w = threadIdx.x >> 5;
    #pragma unroll
    for (int o = 16; o; o >>= 1) v += __shfl_xor_sync(0xffffffffu, v, o);
    if (lane == 0) sh[w] = v;
    __syncthreads();
    float r;
    if (threadIdx.x < 8) {
        r = sh[threadIdx.x];
        #pragma unroll
        for (int o = 4; o; o >>= 1) r += __shfl_xor_sync(0x000000ffu, r, o);
        if (threadIdx.x == 0) sh[0] = r;
    }
    __syncthreads();
    r = sh[0];
    __syncthreads();
    return r;
}
__device__ __forceinline__ float2 blockReduceSum2(float2 v, float2* sh) {
    int lane = threadIdx.x & 31, w = threadIdx.x >> 5;
    #pragma unroll
    for (int o = 16; o; o >>= 1) {
        v.x += __shfl_xor_sync(0xffffffffu, v.x, o);
        v.y += __shfl_xor_sync(0xffffffffu, v.y, o);
    }
    if (lane == 0) sh[w] = v;
    __syncthreads();
    float2 r;
    if (threadIdx.x < 8) {
        r = sh[threadIdx.x];
        #pragma unroll
        for (int o = 4; o; o >>= 1) {
            r.x += __shfl_xor_sync(0x000000ffu, r.x, o);
            r.y += __shfl_xor_sync(0x000000ffu, r.y, o);
        }
        if (threadIdx.x == 0) sh[0] = r;
    }
    __syncthreads();
    r = sh[0];
    __syncthreads();
    return r;
}

// ---------------- embedding gather + LN (ln0) ----------------
__global__ void embed_ln_kernel(const int* __restrict__ tokens,
                                const float* __restrict__ emb,
                                const float* __restrict__ w,
                                const float* __restrict__ b,
                                float* __restrict__ Y) {
    __shared__ float sh[8];
    int m = blockIdx.x;
    int tok = tokens[m];
    const float* xr = emb + (size_t)tok * Dd;
    int i0 = threadIdx.x, i1 = i0 + 256, i2 = i0 + 512;
    float v0 = xr[i0], v1 = xr[i1], v2 = xr[i2];
    float s = blockReduceSum(v0 + v1 + v2, sh);
    float mu = s * (1.0f / 768.0f);
    float c0 = v0 - mu, c1 = v1 - mu, c2 = v2 - mu;
    float ss = blockReduceSum(c0*c0 + c1*c1 + c2*c2, sh);
    float inv = rsqrtf(ss * (1.0f / 768.0f) + 1e-5f);
    float* yr = Y + (size_t)m * Dd;
    yr[i0] = c0 * inv * w[i0] + b[i0];
    yr[i1] = c1 * inv * w[i1] + b[i1];
    yr[i2] = c2 * inv * w[i2] + b[i2];
}

// ---------------- final LN with fused gated split-K reduction --------------
__global__ void ln_red_kernel(const float* __restrict__ X,
                              const float* __restrict__ g,
                              const float* __restrict__ q0,
                              const float* __restrict__ q1,
                              const float* __restrict__ q2,
                              const float* __restrict__ w,
                              const float* __restrict__ b,
                              float* __restrict__ Y) {
    __shared__ float sh[8];
    int m = blockIdx.x;
    size_t base = (size_t)m * Dd;
    int i0 = threadIdx.x, i1 = i0 + 256, i2 = i0 + 512;
    float v0 = X[base+i0] + g[base+i0] * (q0[base+i0] + q1[base+i0] + q2[base+i0]);
    float v1 = X[base+i1] + g[base+i1] * (q0[base+i1] + q1[base+i1] + q2[base+i1]);
    float v2 = X[base+i2] + g[base+i2] * (q0[base+i2] + q1[base+i2] + q2[base+i2]);
    float s = blockReduceSum(v0 + v1 + v2, sh);
    float mu = s * (1.0f / 768.0f);
    float c0 = v0 - mu, c1 = v1 - mu, c2 = v2 - mu;
    float ss = blockReduceSum(c0*c0 + c1*c1 + c2*c2, sh);
    float inv = rsqrtf(ss * (1.0f / 768.0f) + 1e-5f);
    float* yr = Y + base;
    yr[i0] = c0 * inv * w[i0] + b[i0];
    yr[i1] = c1 * inv * w[i1] + b[i1];
    yr[i2] = c2 * inv * w[i2] + b[i2];
}

// ------- fused [split-K reduce +] LN + token-shift mix -> fp16 -------------
// RED: 0 = none; 1 = x += q0+q1+q2; 2 = x += gate*(q0+q1+q2)
template<int NMIX, int RED>
__global__ void lnmix_kernel(const float* __restrict__ X,
                             const float* __restrict__ gate,
                             const float* __restrict__ q0,
                             const float* __restrict__ q1,
                             const float* __restrict__ q2,
                             float* __restrict__ Xout,
                             const float* __restrict__ w,
                             const float* __restrict__ b,
                             const float* __restrict__ mk,
                             const float* __restrict__ mv,
                             const float* __restrict__ mr,
                             __half* __restrict__ oh) {
    __shared__ float2 sh[8];
    int m = blockIdx.x;
    bool hasPrev = (m & (Tt - 1)) != 0;
    size_t bc = (size_t)m * Dd;
    size_t bp = bc - Dd;

    float cur[3], prv[3];
    #pragma unroll
    for (int q = 0; q < 3; q++) {
        int i = threadIdx.x + q * 256;
        float v = X[bc + i];
        if (RED == 1) v += q0[bc+i] + q1[bc+i] + q2[bc+i];
        else if (RED == 2) v += gate[bc+i] * (q0[bc+i] + q1[bc+i] + q2[bc+i]);
        if (RED) Xout[bc + i] = v;
        cur[q] = v;
        float p = 0.0f;
        if (hasPrev) {
            p = X[bp + i];
            if (RED == 1) p += q0[bp+i] + q1[bp+i] + q2[bp+i];
            else if (RED == 2) p += gate[bp+i] * (q0[bp+i] + q1[bp+i] + q2[bp+i]);
        }
        prv[q] = p;
    }

    float2 s = blockReduceSum2(make_float2(cur[0]+cur[1]+cur[2], prv[0]+prv[1]+prv[2]), sh);
    float muc = s.x * (1.0f / 768.0f), mup = s.y * (1.0f / 768.0f);
    float cc[3], pc[3];
    #pragma unroll
    for (int q = 0; q < 3; q++) { cc[q] = cur[q] - muc; pc[q] = prv[q] - mup; }
    float2 ss = blockReduceSum2(make_float2(cc[0]*cc[0]+cc[1]*cc[1]+cc[2]*cc[2],
                                            pc[0]*pc[0]+pc[1]*pc[1]+pc[2]*pc[2]), sh);
    float invc = rsqrtf(ss.x * (1.0f / 768.0f) + 1e-5f);
    float invp = rsqrtf(ss.y * (1.0f / 768.0f) + 1e-5f);

    #pragma unroll
    for (int q = 0; q < 3; q++) {
        int i = threadIdx.x + q * 256;
        float cv = cc[q] * invc * w[i] + b[i];
        float pv = hasPrev ? (pc[q] * invp * w[i] + b[i]) : 0.0f;
        float a = mk[i];
        oh[bc + i] = __float2half(cv * a + pv * (1.0f - a));
        if (NMIX == 3) {
            float c = mv[i];
            oh[MD + bc + i] = __float2half(cv * c + pv * (1.0f - c));
        }
        float e = mr[i];
        int slot = (NMIX == 3) ? 2 : 1;
        oh[slot * MD + bc + i] = __float2half(cv * e + pv * (1.0f - e));
    }
}

// ---------------- WKV sequential recurrence (per-channel) ----------------
__global__ void wkv_kernel(const float* __restrict__ k,
                           const float* __restrict__ v,
                           const float* __restrict__ r,
                           const float* __restrict__ tf,
                           const float* __restrict__ td,
                           __half* __restrict__ oh) {
    int ch = blockIdx.x * 32 + threadIdx.x;
    int b = ch / Dd, d = ch % Dd;
    float tfd = tf[d], tdd = td[d];
    float aa = 0.0f, bb = 0.0f, pp = -1e30f;
    size_t base = (size_t)b * Tt * Dd + d;
    float kb[2], vb[2], rb[2];
    kb[0] = k[base];        vb[0] = v[base];        rb[0] = r[base];
    kb[1] = k[base + Dd];   vb[1] = v[base + Dd];   rb[1] = r[base + Dd];
    for (int t = 0; t < Tt; t++) {
        float kc = kb[t & 1], vc = vb[t & 1], rc = rb[t & 1];
        if (t + 2 < Tt) {
            size_t nb = base + (size_t)(t + 2) * Dd;
            kb[t & 1] = k[nb]; vb[t & 1] = v[nb]; rb[t & 1] = r[nb];
        }
        float ww = tfd + kc;
        float p  = fmaxf(pp, ww);
        float e1 = __expf(pp - p);
        float e2 = __expf(ww - p);
        float wkv = __fdividef(e1 * aa + e2 * vc, e1 * bb + e2);
        float sr = __fdividef(1.0f, 1.0f + __expf(-rc));
        oh[base + (size_t)t * Dd] = __float2half(sr * wkv);
        float ww2 = pp + tdd;
        float p2  = fmaxf(ww2, kc);
        float e1b = __expf(ww2 - p2);
        float e2b = __expf(kc - p2);
        aa = e1b * aa + e2b * vc;
        bb = e1b * bb + e2b;
        pp = p2;
    }
}

// ---------------- tensor-core GEMM: fp16 x fp16[K,N], fp32 acc -------------
// A: [M,lda] fp16 row-major. W: [K,ldb] fp16 row-major (N contiguous).
// BM=128, BN=128, BK=32; 256 threads = 8 warps (2m x 4n), warp tile 64x32.
// 3-stage cp.async pipeline; epilogue straight from fragments (epi 0/3);
// epi 2 (sqrelu->fp16) stages through smem.
// epi: 0 = store fp32; 2 = sqrelu -> fp16; 3 = sigmoid -> fp32
struct GArg {
    const __half *A, *W;
    float* C;
    __half* C2;
    int Ng, Kg, kOff, lda, ldb, epi;
};
struct GPack { GArg g[4]; };

#define BM 128
#define BN 128
#define BK 32
#define AST 40    // A row stride (halves)
#define BST 136   // B row stride (halves)

struct Stage {
    __half Ah[BM][AST];   // 10240 B
    __half Bw[BK][BST];   // 8704 B
};
// 3 stages = 56832 B; C staging (epi2) = 128*132*4 = 67584 B
#define GSMEM 67584

__global__ __launch_bounds__(256)
void gemm_h(GPack pk) {
    GArg ga = pk.g[blockIdx.z];
    const int n0 = blockIdx.x * BN;
    if (n0 >= ga.Ng) return;

    extern __shared__ __align__(16) char smraw[];
    Stage* st = reinterpret_cast<Stage*>(smraw);
    float (*Csm)[BN + 4] = reinterpret_cast<float(*)[BN + 4]>(smraw);

    const int tid = threadIdx.x;
    const int wid = tid >> 5;
    const int wm = wid & 1;        // 0..1 -> 64 rows each
    const int wn = wid >> 1;       // 0..3 -> 32 cols each
    const int m0 = blockIdx.y * BM;

    const int ar = tid >> 1;           // 0..127
    const int ac = (tid & 1) * 16;     // 0 or 16
    const int br = tid >> 3;           // 0..31
    const int bc = (tid & 7) * 16;     // 0..112

    const __half* pA = ga.A + (size_t)(m0 + ar) * ga.lda + ga.kOff + ac;
    const __half* pW = ga.W + (size_t)(ga.kOff + br) * ga.ldb + n0 + bc;
    const size_t wstep = (size_t)ga.ldb;

    wmma::fragment<wmma::accumulator, 16, 16, 16, float> acc[4][2];
    #pragma unroll
    for (int i = 0; i < 4; i++)
        #pragma unroll
        for (int j = 0; j < 2; j++)
            wmma::fill_fragment(acc[i][j], 0.0f);

    const int nk = ga.Kg / BK;

    auto issue = [&](int s, int c) {
        int k0 = c * BK;
        cpa16(&st[s].Ah[ar][ac],     pA + k0);
        cpa16(&st[s].Ah[ar][ac + 8], pA + k0 + 8);
        cpa16(&st[s].Bw[br][bc],     pW + (size_t)k0 * wstep);
        cpa16(&st[s].Bw[br][bc + 8], pW + (size_t)k0 * wstep + 8);
        cp_commit();
    };

    issue(0, 0);
    if (nk > 1) issue(1, 1);

    for (int c = 0; c < nk; c++) {
        if (c + 1 < nk) cp_wait<1>(); else cp_wait<0>();
        __syncthreads();
        if (c + 2 < nk) issue((c + 2) % 3, c + 2);

        Stage& S = st[c % 3];
        #pragma unroll
        for (int kk = 0; kk < BK; kk += 16) {
            wmma::fragment<wmma::matrix_b, 16, 16, 16, __half, wmma::row_major> bf[2];
            #pragma unroll
            for (int j = 0; j < 2; j++)
                wmma::load_matrix_sync(bf[j], &S.Bw[kk][wn * 32 + j * 16], BST);

            wmma::fragment<wmma::matrix_a, 16, 16, 16, __half, wmma::row_major> af[4];
            #pragma unroll
            for (int i = 0; i < 4; i++)
                wmma::load_matrix_sync(af[i], &S.Ah[wm * 64 + i * 16][kk], AST);
            #pragma unroll
            for (int i = 0; i < 4; i++)
                #pragma unroll
                for (int j = 0; j < 2; j++)
                    wmma::mma_sync(acc[i][j], af[i], bf[j], acc[i][j]);
        }
    }

    const int Ng = ga.Ng, epi = ga.epi;

    if (epi == 2) {
        // staged epilogue (fp16 sqrelu out)
        __syncthreads();
        #pragma unroll
        for (int i = 0; i < 4; i++)
            #pragma unroll
            for (int j = 0; j < 2; j++)
                wmma::store_matrix_sync(&Csm[wm * 64 + i * 16][wn * 32 + j * 16],
                                        acc[i][j], BN + 4, wmma::mem_row_major);
        __syncthreads();
        const int ecol = tid & 127;
        const int erow = tid >> 7;
        #pragma unroll
        for (int i = 0; i < 64; i++) {
            int rr = i * 2 + erow;
            size_t idx = (size_t)(m0 + rr) * Ng + n0 + ecol;
            float t0 = fmaxf(Csm[rr][ecol], 0.0f);
            ga.C2[idx] = __float2half(t0 * t0);
        }
    } else {
        // direct fragment store (fp32 / sigmoid)
        if (epi == 3) {
            #pragma unroll
            for (int i = 0; i < 4; i++)
                #pragma unroll
                for (int j = 0; j < 2; j++)
                    #pragma unroll
                    for (int e = 0; e < acc[i][j].num_elements; e++)
                        acc[i][j].x[e] = __fdividef(1.0f, 1.0f + __expf(-acc[i][j].x[e]));
        }
        #pragma unroll
        for (int i = 0; i < 4; i++)
            #pragma unroll
            for (int j = 0; j < 2; j++)
                wmma::store_matrix_sync(
                    ga.C + (size_t)(m0 + wm * 64 + i * 16) * Ng + n0 + wn * 32 + j * 16,
                    acc[i][j], Ng, wmma::mem_row_major);
    }
}

// ---------------- host launcher ----------------
extern "C" void kernel_launch(void* const* d_in, const int* in_sizes, int n_in,
                              void* d_out, int out_size) {
    const int*   tokens     = (const int*)  d_in[0];
    const float* emb        = (const float*)d_in[1];
    const float* ln0_w      = (const float*)d_in[2];
    const float* ln0_b      = (const float*)d_in[3];
    const float* ln1_w      = (const float*)d_in[4];
    const float* ln1_b      = (const float*)d_in[5];
    const float* ln2_w      = (const float*)d_in[6];
    const float* ln2_b      = (const float*)d_in[7];
    const float* att_mix_k  = (const float*)d_in[8];
    const float* att_mix_v  = (const float*)d_in[9];
    const float* att_mix_r  = (const float*)d_in[10];
    const float* time_first = (const float*)d_in[11];
    const float* time_decay = (const float*)d_in[12];
    const float* att_Wk     = (const float*)d_in[13];
    const float* att_Wv     = (const float*)d_in[14];
    const float* att_Wr     = (const float*)d_in[15];
    const float* att_Wo     = (const float*)d_in[16];
    const float* ffn_mix_k  = (const float*)d_in[17];
    const float* ffn_mix_r  = (const float*)d_in[18];
    const float* ffn_Wk     = (const float*)d_in[19];
    const float* ffn_Wv     = (const float*)d_in[20];
    const float* ffn_Wr     = (const float*)d_in[21];
    const float* lnout_w    = (const float*)d_in[22];
    const float* lnout_b    = (const float*)d_in[23];
    float* out = (float*)d_out;

    float *xa, *xb, *kvr, *r2, *part;
    __half *mixh, *rwkvh, *hh, *w16;
    cudaGetSymbolAddress((void**)&xa,    g_x);
    cudaGetSymbolAddress((void**)&xb,    g_x2);
    cudaGetSymbolAddress((void**)&kvr,   g_kvr);
    cudaGetSymbolAddress((void**)&r2,    g_r2);
    cudaGetSymbolAddress((void**)&part,  g_part);
    cudaGetSymbolAddress((void**)&mixh,  g_mixh);
    cudaGetSymbolAddress((void**)&rwkvh, g_rwkvh);
    cudaGetSymbolAddress((void**)&hh,    g_hh);
    cudaGetSymbolAddress((void**)&w16,   g_w);

    cudaFuncSetAttribute(gemm_h, cudaFuncAttributeMaxDynamicSharedMemorySize, GSMEM);

    // ---- streaming convert: W fp32 [K,N] -> fp16 [K,N] (no transpose) ----
    auto conv = [&](const float* W, size_t off, int n) {
        int n8 = n / 8;
        convW_kernel<<<(n8 + 255) / 256, 256>>>((const float4*)W, (uint4*)(w16 + off), n8);
    };
    conv(att_Wk, OFF_WK, NDD);
    conv(att_Wv, OFF_WV, NDD);
    conv(att_Wr, OFF_WR, NDD);
    conv(att_Wo, OFF_WO, NDD);
    conv(ffn_Wk, OFF_FK, NDF);
    conv(ffn_Wv, OFF_FV, NDF);
    conv(ffn_Wr, OFF_FR, NDD);

    // x(a) = LN0(emb[tokens])
    embed_ln_kernel<<<MM, 256>>>(tokens, emb, ln0_w, ln0_b, xa);

    for (int l = 0; l < Ll; l++) {
        // ---- time mixing: [gated FV reduce +] LN1 + mix3 ----
        if (l == 0) {
            lnmix_kernel<3, 0><<<MM, 256>>>(xa, nullptr, nullptr, nullptr, nullptr, nullptr,
                                            ln1_w, ln1_b,
                                            att_mix_k, att_mix_v, att_mix_r, mixh);
        } else {
            lnmix_kernel<3, 2><<<MM, 256>>>(xb, r2, part, part + MD, part + 2 * MD, xa,
                                            ln1_w + l * Dd, ln1_b + l * Dd,
                                            att_mix_k + l * Dd, att_mix_v + l * Dd,
                                            att_mix_r + l * Dd, mixh);
        }
        // k/v/r = mix @ {Wk,Wv,Wr}
        {
            GPack pk{};
            for (int z = 0; z < 3; z++) {
                pk.g[z].A = mixh + z * MD;
                size_t wo = (z == 0 ? OFF_WK : z == 1 ? OFF_WV : OFF_WR) + (size_t)l * Dd * Dd;
                pk.g[z].W = w16 + wo;
                pk.g[z].C = kvr + z * MD;
                pk.g[z].Ng = Dd; pk.g[z].Kg = Dd; pk.g[z].kOff = 0;
                pk.g[z].lda = Dd; pk.g[z].ldb = Dd; pk.g[z].epi = 0;
            }
            gemm_h<<<dim3(Dd / BN, MM / BM, 3), 256, GSMEM>>>(pk);
        }
        // sequential WKV
        wkv_kernel<<<(Bb * Dd) / 32, 32>>>(kvr, kvr + MD, kvr + 2 * MD,
                                           time_first + l * Dd, time_decay + l * Dd, rwkvh);
        // Wo GEMM, split-K=3 -> partials
        {
            GPack pk{};
            for (int z = 0; z < 3; z++) {
                pk.g[z].A = rwkvh;
                pk.g[z].W = w16 + OFF_WO + (size_t)l * Dd * Dd;
                pk.g[z].C = part + z * MD;
                pk.g[z].Ng = Dd; pk.g[z].Kg = Dd / 3; pk.g[z].kOff = z * (Dd / 3);
                pk.g[z].lda = Dd; pk.g[z].ldb = Dd; pk.g[z].epi = 0;
            }
            gemm_h<<<dim3(Dd / BN, MM / BM, 3), 256, GSMEM>>>(pk);
        }
        // ---- channel mixing: Wo reduce + LN2 + mix2 (xa + parts -> xb) ----
        lnmix_kernel<2, 1><<<MM, 256>>>(xa, nullptr, part, part + MD, part + 2 * MD, xb,
                                        ln2_w + l * Dd, ln2_b + l * Dd,
                                        ffn_mix_k + l * Dd, nullptr, ffn_mix_r + l * Dd, mixh);
        // FK: h = sqrelu(xk2 @ ffn_Wk) -> fp16
        {
            GPack pk{};
            pk.g[0].A = mixh;
            pk.g[0].W = w16 + OFF_FK + (size_t)l * Dd * Ff;
            pk.g[0].C2 = hh;
            pk.g[0].Ng = Ff; pk.g[0].Kg = Dd; pk.g[0].kOff = 0;
            pk.g[0].lda = Dd; pk.g[0].ldb = Ff; pk.g[0].epi = 2;
            gemm_h<<<dim3(Ff / BN, MM / BM, 1), 256, GSMEM>>>(pk);
        }
        // FV split-K=3 (z=0..2) batched with FR sigmoid (z=3)
        {
            GPack pk{};
            for (int z = 0; z < 3; z++) {
                pk.g[z].A = hh;
                pk.g[z].W = w16 + OFF_FV + (size_t)l * Ff * Dd;
                pk.g[z].C = part + z * MD;
                pk.g[z].Ng = Dd; pk.g[z].Kg = Ff / 3; pk.g[z].kOff = z * (Ff / 3);
                pk.g[z].lda = Ff; pk.g[z].ldb = Dd; pk.g[z].epi = 0;
            }
            pk.g[3].A = mixh + MD;
            pk.g[3].W = w16 + OFF_FR + (size_t)l * Dd * Dd;
            pk.g[3].C = r2;
            pk.g[3].Ng = Dd; pk.g[3].Kg = Dd; pk.g[3].kOff = 0;
            pk.g[3].lda = Dd; pk.g[3].ldb = Dd; pk.g[3].epi = 3;
            gemm_h<<<dim3(Dd / BN, MM / BM, 4), 256, GSMEM>>>(pk);
        }
    }

    // out = LN_out(xb + r2*(parts))
    ln_red_kernel<<<MM, 256>>>(xb, r2, part, part + MD, part + 2 * MD,
                               lnout_w, lnout_b, out);
}

// round 10
// speedup vs baseline: 5.2863x; 1.0214x over previous
#include <cuda_runtime.h>
#include <cuda_fp16.h>
#include <mma.h>
#include <math.h>
#include <cstdint>

using namespace nvcuda;

// Constants
#define Ll 12
#define Dd 768
#define Bb 4
#define Tt 256
#define Ff 3072
#define MM (Bb*Tt)   // 1024
#define MD (MM*Dd)

// fp16 weight offsets (elements), NATIVE [K,N] layout per layer slice
#define NDD (Ll*Dd*Dd)
#define NDF (Ll*Dd*Ff)
#define OFF_WK 0
#define OFF_WV (NDD)
#define OFF_WR (2*NDD)
#define OFF_WO (3*NDD)
#define OFF_FK (4*NDD)
#define OFF_FV (4*NDD + NDF)
#define OFF_FR (4*NDD + 2*NDF)
#define NWTOT  (4*NDD + 2*NDF + NDD)

// ---------------- scratch (device globals) ----------
__device__ __align__(256) float g_x[MD];        // residual ping
__device__ __align__(256) float g_x2[MD];       // residual pong
__device__ __align__(256) float g_kvr[3*MD];
__device__ __align__(256) float g_r2[MD];
__device__ __align__(256) float g_part[3*MD];
__device__ __align__(256) __half g_mixh[3*MD];  // mixed activations (fp16)
__device__ __align__(256) __half g_rwkvh[MD];
__device__ __align__(256) __half g_hh[MM*Ff];
__device__ __align__(256) __half g_w[NWTOT];    // W fp16 [K,N] native

// ---------------- cp.async helpers ----------------
__device__ __forceinline__ void cpa16(void* dst, const void* src) {
    unsigned d = (unsigned)__cvta_generic_to_shared(dst);
    asm volatile("cp.async.cg.shared.global [%0], [%1], 16;" :: "r"(d), "l"(src));
}
__device__ __forceinline__ void cp_commit() { asm volatile("cp.async.commit_group;"); }
template<int N> __device__ __forceinline__ void cp_wait() {
    asm volatile("cp.async.wait_group %0;" :: "n"(N));
}

// ---------------- streaming convert: fp32 -> fp16 (no transpose) -----------
__global__ void convW_kernel(const float4* __restrict__ W,
                             uint4* __restrict__ out, int n8) {
    int i = blockIdx.x * 256 + threadIdx.x;
    if (i >= n8) return;
    float4 a = W[2*i], b = W[2*i+1];
    __half2 h0 = __floats2half2_rn(a.x, a.y);
    __half2 h1 = __floats2half2_rn(a.z, a.w);
    __half2 h2 = __floats2half2_rn(b.x, b.y);
    __half2 h3 = __floats2half2_rn(b.z, b.w);
    uint4 o;
    o.x = *(unsigned*)&h0; o.y = *(unsigned*)&h1;
    o.z = *(unsigned*)&h2; o.w = *(unsigned*)&h3;
    out[i] = o;
}

// ---------------- block reduces ----------------
__device__ __forceinline__ float blockReduceSum(float v, float* sh) {
    int lane = threadIdx.x & 31, w = threadIdx.x >> 5;
    #pragma unroll
    for (int o = 16; o; o >>= 1) v += __shfl_xor_sync(0xffffffffu, v, o);
    if (lane == 0) sh[w] = v;
    __syncthreads();
    float r;
    if (threadIdx.x < 8) {
        r = sh[threadIdx.x];
        #pragma unroll
        for (int o = 4; o; o >>= 1) r += __shfl_xor_sync(0x000000ffu, r, o);
        if (threadIdx.x == 0) sh[0] = r;
    }
    __syncthreads();
    r = sh[0];
    __syncthreads();
    return r;
}
__device__ __forceinline__ float2 blockReduceSum2(float2 v, float2* sh) {
    int lane = threadIdx.x & 31, w = threadIdx.x >> 5;
    #pragma unroll
    for (int o = 16; o; o >>= 1) {
        v.x += __shfl_xor_sync(0xffffffffu, v.x, o);
        v.y += __shfl_xor_sync(0xffffffffu, v.y, o);
    }
    if (lane == 0) sh[w] = v;
    __syncthreads();
    float2 r;
    if (threadIdx.x < 8) {
        r = sh[threadIdx.x];
        #pragma unroll
        for (int o = 4; o; o >>= 1) {
            r.x += __shfl_xor_sync(0x000000ffu, r.x, o);
            r.y += __shfl_xor_sync(0x000000ffu, r.y, o);
        }
        if (threadIdx.x == 0) sh[0] = r;
    }
    __syncthreads();
    r = sh[0];
    __syncthreads();
    return r;
}

// ---------------- embedding gather + LN (ln0) ----------------
__global__ void embed_ln_kernel(const int* __restrict__ tokens,
                                const float* __restrict__ emb,
                                const float* __restrict__ w,
                                const float* __restrict__ b,
                                float* __restrict__ Y) {
    __shared__ float sh[8];
    int m = blockIdx.x;
    int tok = tokens[m];
    const float* xr = emb + (size_t)tok * Dd;
    int i0 = threadIdx.x, i1 = i0 + 256, i2 = i0 + 512;
    float v0 = xr[i0], v1 = xr[i1], v2 = xr[i2];
    float s = blockReduceSum(v0 + v1 + v2, sh);
    float mu = s * (1.0f / 768.0f);
    float c0 = v0 - mu, c1 = v1 - mu, c2 = v2 - mu;
    float ss = blockReduceSum(c0*c0 + c1*c1 + c2*c2, sh);
    float inv = rsqrtf(ss * (1.0f / 768.0f) + 1e-5f);
    float* yr = Y + (size_t)m * Dd;
    yr[i0] = c0 * inv * w[i0] + b[i0];
    yr[i1] = c1 * inv * w[i1] + b[i1];
    yr[i2] = c2 * inv * w[i2] + b[i2];
}

// ---------------- final LN with fused gated split-K reduction --------------
__global__ void ln_red_kernel(const float* __restrict__ X,
                              const float* __restrict__ g,
                              const float* __restrict__ q0,
                              const float* __restrict__ q1,
                              const float* __restrict__ q2,
                              const float* __restrict__ w,
                              const float* __restrict__ b,
                              float* __restrict__ Y) {
    __shared__ float sh[8];
    int m = blockIdx.x;
    size_t base = (size_t)m * Dd;
    int i0 = threadIdx.x, i1 = i0 + 256, i2 = i0 + 512;
    float v0 = X[base+i0] + g[base+i0] * (q0[base+i0] + q1[base+i0] + q2[base+i0]);
    float v1 = X[base+i1] + g[base+i1] * (q0[base+i1] + q1[base+i1] + q2[base+i1]);
    float v2 = X[base+i2] + g[base+i2] * (q0[base+i2] + q1[base+i2] + q2[base+i2]);
    float s = blockReduceSum(v0 + v1 + v2, sh);
    float mu = s * (1.0f / 768.0f);
    float c0 = v0 - mu, c1 = v1 - mu, c2 = v2 - mu;
    float ss = blockReduceSum(c0*c0 + c1*c1 + c2*c2, sh);
    float inv = rsqrtf(ss * (1.0f / 768.0f) + 1e-5f);
    float* yr = Y + base;
    yr[i0] = c0 * inv * w[i0] + b[i0];
    yr[i1] = c1 * inv * w[i1] + b[i1];
    yr[i2] = c2 * inv * w[i2] + b[i2];
}

// ------- fused [split-K reduce +] LN + token-shift mix -> fp16 -------------
// RED: 0 = none; 1 = x += q0+q1+q2; 2 = x += gate*(q0+q1+q2)
template<int NMIX, int RED>
__global__ void lnmix_kernel(const float* __restrict__ X,
                             const float* __restrict__ gate,
                             const float* __restrict__ q0,
                             const float* __restrict__ q1,
                             const float* __restrict__ q2,
                             float* __restrict__ Xout,
                             const float* __restrict__ w,
                             const float* __restrict__ b,
                             const float* __restrict__ mk,
                             const float* __restrict__ mv,
                             const float* __restrict__ mr,
                             __half* __restrict__ oh) {
    __shared__ float2 sh[8];
    int m = blockIdx.x;
    bool hasPrev = (m & (Tt - 1)) != 0;
    size_t bc = (size_t)m * Dd;
    size_t bp = bc - Dd;

    float cur[3], prv[3];
    #pragma unroll
    for (int q = 0; q < 3; q++) {
        int i = threadIdx.x + q * 256;
        float v = X[bc + i];
        if (RED == 1) v += q0[bc+i] + q1[bc+i] + q2[bc+i];
        else if (RED == 2) v += gate[bc+i] * (q0[bc+i] + q1[bc+i] + q2[bc+i]);
        if (RED) Xout[bc + i] = v;
        cur[q] = v;
        float p = 0.0f;
        if (hasPrev) {
            p = X[bp + i];
            if (RED == 1) p += q0[bp+i] + q1[bp+i] + q2[bp+i];
            else if (RED == 2) p += gate[bp+i] * (q0[bp+i] + q1[bp+i] + q2[bp+i]);
        }
        prv[q] = p;
    }

    float2 s = blockReduceSum2(make_float2(cur[0]+cur[1]+cur[2], prv[0]+prv[1]+prv[2]), sh);
    float muc = s.x * (1.0f / 768.0f), mup = s.y * (1.0f / 768.0f);
    float cc[3], pc[3];
    #pragma unroll
    for (int q = 0; q < 3; q++) { cc[q] = cur[q] - muc; pc[q] = prv[q] - mup; }
    float2 ss = blockReduceSum2(make_float2(cc[0]*cc[0]+cc[1]*cc[1]+cc[2]*cc[2],
                                            pc[0]*pc[0]+pc[1]*pc[1]+pc[2]*pc[2]), sh);
    float invc = rsqrtf(ss.x * (1.0f / 768.0f) + 1e-5f);
    float invp = rsqrtf(ss.y * (1.0f / 768.0f) + 1e-5f);

    #pragma unroll
    for (int q = 0; q < 3; q++) {
        int i = threadIdx.x + q * 256;
        float cv = cc[q] * invc * w[i] + b[i];
        float pv = hasPrev ? (pc[q] * invp * w[i] + b[i]) : 0.0f;
        float a = mk[i];
        oh[bc + i] = __float2half(cv * a + pv * (1.0f - a));
        if (NMIX == 3) {
            float c = mv[i];
            oh[MD + bc + i] = __float2half(cv * c + pv * (1.0f - c));
        }
        float e = mr[i];
        int slot = (NMIX == 3) ? 2 : 1;
        oh[slot * MD + bc + i] = __float2half(cv * e + pv * (1.0f - e));
    }
}

// ---------------- WKV sequential recurrence (per-channel) ----------------
__global__ void wkv_kernel(const float* __restrict__ k,
                           const float* __restrict__ v,
                           const float* __restrict__ r,
                           const float* __restrict__ tf,
                           const float* __restrict__ td,
                           __half* __restrict__ oh) {
    int ch = blockIdx.x * 32 + threadIdx.x;
    int b = ch / Dd, d = ch % Dd;
    float tfd = tf[d], tdd = td[d];
    float aa = 0.0f, bb = 0.0f, pp = -1e30f;
    size_t base = (size_t)b * Tt * Dd + d;
    float kb[2], vb[2], rb[2];
    kb[0] = k[base];        vb[0] = v[base];        rb[0] = r[base];
    kb[1] = k[base + Dd];   vb[1] = v[base + Dd];   rb[1] = r[base + Dd];
    for (int t = 0; t < Tt; t++) {
        float kc = kb[t & 1], vc = vb[t & 1], rc = rb[t & 1];
        if (t + 2 < Tt) {
            size_t nb = base + (size_t)(t + 2) * Dd;
            kb[t & 1] = k[nb]; vb[t & 1] = v[nb]; rb[t & 1] = r[nb];
        }
        float ww = tfd + kc;
        float p  = fmaxf(pp, ww);
        float e1 = __expf(pp - p);
        float e2 = __expf(ww - p);
        float wkv = __fdividef(e1 * aa + e2 * vc, e1 * bb + e2);
        float sr = __fdividef(1.0f, 1.0f + __expf(-rc));
        oh[base + (size_t)t * Dd] = __float2half(sr * wkv);
        float ww2 = pp + tdd;
        float p2  = fmaxf(ww2, kc);
        float e1b = __expf(ww2 - p2);
        float e2b = __expf(kc - p2);
        aa = e1b * aa + e2b * vc;
        bb = e1b * bb + e2b;
        pp = p2;
    }
}

// ---------------- tensor-core GEMM: fp16 x fp16[K,N], fp32 acc -------------
// A: [M,lda] fp16 row-major. W: [K,ldb] fp16 row-major (N contiguous).
// BM=128, BN=128, BK=32; 256 threads = 8 warps (2m x 4n), warp tile 64x32.
// 3-stage cp.async pipeline; 2 CTAs/SM (launch_bounds) to hide sync/ldsm gaps.
// epi: 0 = store fp32; 2 = sqrelu -> fp16 (staged); 3 = sigmoid -> fp32
struct GArg {
    const __half *A, *W;
    float* C;
    __half* C2;
    int Ng, Kg, kOff, lda, ldb, epi;
};
struct GPack { GArg g[4]; };

#define BM 128
#define BN 128
#define BK 32
#define AST 40    // A row stride (halves)
#define BST 136   // B row stride (halves)

struct Stage {
    __half Ah[BM][AST];   // 10240 B
    __half Bw[BK][BST];   // 8704 B
};
// 3 stages = 56832 B; C staging (epi2) = 128*132*4 = 67584 B
#define GSMEM 67584

__global__ __launch_bounds__(256, 2)
void gemm_h(GPack pk) {
    GArg ga = pk.g[blockIdx.z];
    const int n0 = blockIdx.x * BN;
    if (n0 >= ga.Ng) return;

    extern __shared__ __align__(16) char smraw[];
    Stage* st = reinterpret_cast<Stage*>(smraw);
    float (*Csm)[BN + 4] = reinterpret_cast<float(*)[BN + 4]>(smraw);

    const int tid = threadIdx.x;
    const int wid = tid >> 5;
    const int wm = wid & 1;        // 0..1 -> 64 rows each
    const int wn = wid >> 1;       // 0..3 -> 32 cols each
    const int m0 = blockIdx.y * BM;

    const int ar = tid >> 1;           // 0..127
    const int ac = (tid & 1) * 16;     // 0 or 16
    const int br = tid >> 3;           // 0..31
    const int bc = (tid & 7) * 16;     // 0..112

    const __half* pA = ga.A + (size_t)(m0 + ar) * ga.lda + ga.kOff + ac;
    const __half* pW = ga.W + (size_t)(ga.kOff + br) * ga.ldb + n0 + bc;
    const size_t wstep = (size_t)ga.ldb;

    wmma::fragment<wmma::accumulator, 16, 16, 16, float> acc[4][2];
    #pragma unroll
    for (int i = 0; i < 4; i++)
        #pragma unroll
        for (int j = 0; j < 2; j++)
            wmma::fill_fragment(acc[i][j], 0.0f);

    const int nk = ga.Kg / BK;

    auto issue = [&](int s, int c) {
        int k0 = c * BK;
        cpa16(&st[s].Ah[ar][ac],     pA + k0);
        cpa16(&st[s].Ah[ar][ac + 8], pA + k0 + 8);
        cpa16(&st[s].Bw[br][bc],     pW + (size_t)k0 * wstep);
        cpa16(&st[s].Bw[br][bc + 8], pW + (size_t)k0 * wstep + 8);
        cp_commit();
    };

    issue(0, 0);
    if (nk > 1) issue(1, 1);

    for (int c = 0; c < nk; c++) {
        if (c + 1 < nk) cp_wait<1>(); else cp_wait<0>();
        __syncthreads();
        if (c + 2 < nk) issue((c + 2) % 3, c + 2);

        Stage& S = st[c % 3];
        #pragma unroll
        for (int kk = 0; kk < BK; kk += 16) {
            wmma::fragment<wmma::matrix_b, 16, 16, 16, __half, wmma::row_major> bf[2];
            #pragma unroll
            for (int j = 0; j < 2; j++)
                wmma::load_matrix_sync(bf[j], &S.Bw[kk][wn * 32 + j * 16], BST);

            wmma::fragment<wmma::matrix_a, 16, 16, 16, __half, wmma::row_major> af[4];
            #pragma unroll
            for (int i = 0; i < 4; i++)
                wmma::load_matrix_sync(af[i], &S.Ah[wm * 64 + i * 16][kk], AST);
            #pragma unroll
            for (int i = 0; i < 4; i++)
                #pragma unroll
                for (int j = 0; j < 2; j++)
                    wmma::mma_sync(acc[i][j], af[i], bf[j], acc[i][j]);
        }
    }

    const int Ng = ga.Ng, epi = ga.epi;

    if (epi == 2) {
        // staged epilogue (fp16 sqrelu out)
        __syncthreads();
        #pragma unroll
        for (int i = 0; i < 4; i++)
            #pragma unroll
            for (int j = 0; j < 2; j++)
                wmma::store_matrix_sync(&Csm[wm * 64 + i * 16][wn * 32 + j * 16],
                                        acc[i][j], BN + 4, wmma::mem_row_major);
        __syncthreads();
        const int ecol = tid & 127;
        const int erow = tid >> 7;
        #pragma unroll
        for (int i = 0; i < 64; i++) {
            int rr = i * 2 + erow;
            size_t idx = (size_t)(m0 + rr) * Ng + n0 + ecol;
            float t0 = fmaxf(Csm[rr][ecol], 0.0f);
            ga.C2[idx] = __float2half(t0 * t0);
        }
    } else {
        // direct fragment store (fp32 / sigmoid)
        if (epi == 3) {
            #pragma unroll
            for (int i = 0; i < 4; i++)
                #pragma unroll
                for (int j = 0; j < 2; j++)
                    #pragma unroll
                    for (int e = 0; e < acc[i][j].num_elements; e++)
                        acc[i][j].x[e] = __fdividef(1.0f, 1.0f + __expf(-acc[i][j].x[e]));
        }
        #pragma unroll
        for (int i = 0; i < 4; i++)
            #pragma unroll
            for (int j = 0; j < 2; j++)
                wmma::store_matrix_sync(
                    ga.C + (size_t)(m0 + wm * 64 + i * 16) * Ng + n0 + wn * 32 + j * 16,
                    acc[i][j], Ng, wmma::mem_row_major);
    }
}

// ---------------- host launcher ----------------
extern "C" void kernel_launch(void* const* d_in, const int* in_sizes, int n_in,
                              void* d_out, int out_size) {
    const int*   tokens     = (const int*)  d_in[0];
    const float* emb        = (const float*)d_in[1];
    const float* ln0_w      = (const float*)d_in[2];
    const float* ln0_b      = (const float*)d_in[3];
    const float* ln1_w      = (const float*)d_in[4];
    const float* ln1_b      = (const float*)d_in[5];
    const float* ln2_w      = (const float*)d_in[6];
    const float* ln2_b      = (const float*)d_in[7];
    const float* att_mix_k  = (const float*)d_in[8];
    const float* att_mix_v  = (const float*)d_in[9];
    const float* att_mix_r  = (const float*)d_in[10];
    const float* time_first = (const float*)d_in[11];
    const float* time_decay = (const float*)d_in[12];
    const float* att_Wk     = (const float*)d_in[13];
    const float* att_Wv     = (const float*)d_in[14];
    const float* att_Wr     = (const float*)d_in[15];
    const float* att_Wo     = (const float*)d_in[16];
    const float* ffn_mix_k  = (const float*)d_in[17];
    const float* ffn_mix_r  = (const float*)d_in[18];
    const float* ffn_Wk     = (const float*)d_in[19];
    const float* ffn_Wv     = (const float*)d_in[20];
    const float* ffn_Wr     = (const float*)d_in[21];
    const float* lnout_w    = (const float*)d_in[22];
    const float* lnout_b    = (const float*)d_in[23];
    float* out = (float*)d_out;

    float *xa, *xb, *kvr, *r2, *part;
    __half *mixh, *rwkvh, *hh, *w16;
    cudaGetSymbolAddress((void**)&xa,    g_x);
    cudaGetSymbolAddress((void**)&xb,    g_x2);
    cudaGetSymbolAddress((void**)&kvr,   g_kvr);
    cudaGetSymbolAddress((void**)&r2,    g_r2);
    cudaGetSymbolAddress((void**)&part,  g_part);
    cudaGetSymbolAddress((void**)&mixh,  g_mixh);
    cudaGetSymbolAddress((void**)&rwkvh, g_rwkvh);
    cudaGetSymbolAddress((void**)&hh,    g_hh);
    cudaGetSymbolAddress((void**)&w16,   g_w);

    cudaFuncSetAttribute(gemm_h, cudaFuncAttributeMaxDynamicSharedMemorySize, GSMEM);

    // ---- streaming convert: W fp32 [K,N] -> fp16 [K,N] (no transpose) ----
    auto conv = [&](const float* W, size_t off, int n) {
        int n8 = n / 8;
        convW_kernel<<<(n8 + 255) / 256, 256>>>((const float4*)W, (uint4*)(w16 + off), n8);
    };
    conv(att_Wk, OFF_WK, NDD);
    conv(att_Wv, OFF_WV, NDD);
    conv(att_Wr, OFF_WR, NDD);
    conv(att_Wo, OFF_WO, NDD);
    conv(ffn_Wk, OFF_FK, NDF);
    conv(ffn_Wv, OFF_FV, NDF);
    conv(ffn_Wr, OFF_FR, NDD);

    // x(a) = LN0(emb[tokens])
    embed_ln_kernel<<<MM, 256>>>(tokens, emb, ln0_w, ln0_b, xa);

    for (int l = 0; l < Ll; l++) {
        // ---- time mixing: [gated FV reduce +] LN1 + mix3 ----
        if (l == 0) {
            lnmix_kernel<3, 0><<<MM, 256>>>(xa, nullptr, nullptr, nullptr, nullptr, nullptr,
                                            ln1_w, ln1_b,
                                            att_mix_k, att_mix_v, att_mix_r, mixh);
        } else {
            lnmix_kernel<3, 2><<<MM, 256>>>(xb, r2, part, part + MD, part + 2 * MD, xa,
                                            ln1_w + l * Dd, ln1_b + l * Dd,
                                            att_mix_k + l * Dd, att_mix_v + l * Dd,
                                            att_mix_r + l * Dd, mixh);
        }
        // k/v/r = mix @ {Wk,Wv,Wr}
        {
            GPack pk{};
            for (int z = 0; z < 3; z++) {
                pk.g[z].A = mixh + z * MD;
                size_t wo = (z == 0 ? OFF_WK : z == 1 ? OFF_WV : OFF_WR) + (size_t)l * Dd * Dd;
                pk.g[z].W = w16 + wo;
                pk.g[z].C = kvr + z * MD;
                pk.g[z].Ng = Dd; pk.g[z].Kg = Dd; pk.g[z].kOff = 0;
                pk.g[z].lda = Dd; pk.g[z].ldb = Dd; pk.g[z].epi = 0;
            }
            gemm_h<<<dim3(Dd / BN, MM / BM, 3), 256, GSMEM>>>(pk);
        }
        // sequential WKV
        wkv_kernel<<<(Bb * Dd) / 32, 32>>>(kvr, kvr + MD, kvr + 2 * MD,
                                           time_first + l * Dd, time_decay + l * Dd, rwkvh);
        // Wo GEMM, split-K=3 -> partials
        {
            GPack pk{};
            for (int z = 0; z < 3; z++) {
                pk.g[z].A = rwkvh;
                pk.g[z].W = w16 + OFF_WO + (size_t)l * Dd * Dd;
                pk.g[z].C = part + z * MD;
                pk.g[z].Ng = Dd; pk.g[z].Kg = Dd / 3; pk.g[z].kOff = z * (Dd / 3);
                pk.g[z].lda = Dd; pk.g[z].ldb = Dd; pk.g[z].epi = 0;
            }
            gemm_h<<<dim3(Dd / BN, MM / BM, 3), 256, GSMEM>>>(pk);
        }
        // ---- channel mixing: Wo reduce + LN2 + mix2 (xa + parts -> xb) ----
        lnmix_kernel<2, 1><<<MM, 256>>>(xa, nullptr, part, part + MD, part + 2 * MD, xb,
                                        ln2_w + l * Dd, ln2_b + l * Dd,
                                        ffn_mix_k + l * Dd, nullptr, ffn_mix_r + l * Dd, mixh);
        // FK: h = sqrelu(xk2 @ ffn_Wk) -> fp16
        {
            GPack pk{};
            pk.g[0].A = mixh;
            pk.g[0].W = w16 + OFF_FK + (size_t)l * Dd * Ff;
            pk.g[0].C2 = hh;
            pk.g[0].Ng = Ff; pk.g[0].Kg = Dd; pk.g[0].kOff = 0;
            pk.g[0].lda = Dd; pk.g[0].ldb = Ff; pk.g[0].epi = 2;
            gemm_h<<<dim3(Ff / BN, MM / BM, 1), 256, GSMEM>>>(pk);
        }
        // FV split-K=3 (z=0..2) batched with FR sigmoid (z=3)
        {
            GPack pk{};
            for (int z = 0; z < 3; z++) {
                pk.g[z].A = hh;
                pk.g[z].W = w16 + OFF_FV + (size_t)l * Ff * Dd;
                pk.g[z].C = part + z * MD;
                pk.g[z].Ng = Dd; pk.g[z].Kg = Ff / 3; pk.g[z].kOff = z * (Ff / 3);
                pk.g[z].lda = Ff; pk.g[z].ldb = Dd; pk.g[z].epi = 0;
            }
            pk.g[3].A = mixh + MD;
            pk.g[3].W = w16 + OFF_FR + (size_t)l * Dd * Dd;
            pk.g[3].C = r2;
            pk.g[3].Ng = Dd; pk.g[3].Kg = Dd; pk.g[3].kOff = 0;
            pk.g[3].lda = Dd; pk.g[3].ldb = Dd; pk.g[3].epi = 3;
            gemm_h<<<dim3(Dd / BN, MM / BM, 4), 256, GSMEM>>>(pk);
        }
    }

    // out = LN_out(xb + r2*(parts))
    ln_red_kernel<<<MM, 256>>>(xb, r2, part, part + MD, part + 2 * MD,
                               lnout_w, lnout_b, out);
}

// round 11
// speedup vs baseline: 5.4249x; 1.0262x over previous
#include <cuda_runtime.h>
#include <cuda_fp16.h>
#include <mma.h>
#include <math.h>
#include <cstdint>

using namespace nvcuda;

// Constants
#define Ll 12
#define Dd 768
#define Bb 4
#define Tt 256
#define Ff 3072
#define MM (Bb*Tt)   // 1024
#define MD (MM*Dd)

// fp16 weight offsets (elements), NATIVE [K,N] layout per layer slice
#define NDD (Ll*Dd*Dd)
#define NDF (Ll*Dd*Ff)
#define OFF_WK 0
#define OFF_WV (NDD)
#define OFF_WR (2*NDD)
#define OFF_WO (3*NDD)
#define OFF_FK (4*NDD)
#define OFF_FV (4*NDD + NDF)
#define OFF_FR (4*NDD + 2*NDF)
#define NWTOT  (4*NDD + 2*NDF + NDD)

// ---------------- scratch (device globals) ----------
__device__ __align__(256) float g_x[MD];        // residual ping
__device__ __align__(256) float g_x2[MD];       // residual pong
__device__ __align__(256) float g_kvr[3*MD];
__device__ __align__(256) float g_r2[MD];
__device__ __align__(256) float g_part[3*MD];
__device__ __align__(256) __half g_mixh[3*MD];  // mixed activations (fp16)
__device__ __align__(256) __half g_rwkvh[MD];
__device__ __align__(256) __half g_hh[MM*Ff];
__device__ __align__(256) __half g_w[NWTOT];    // W fp16 [K,N] native

// ---------------- cp.async helpers ----------------
__device__ __forceinline__ void cpa16(void* dst, const void* src) {
    unsigned d = (unsigned)__cvta_generic_to_shared(dst);
    asm volatile("cp.async.cg.shared.global [%0], [%1], 16;" :: "r"(d), "l"(src));
}
__device__ __forceinline__ void cp_commit() { asm volatile("cp.async.commit_group;"); }
template<int N> __device__ __forceinline__ void cp_wait() {
    asm volatile("cp.async.wait_group %0;" :: "n"(N));
}

// ---------------- streaming convert: fp32 -> fp16 (4x ILP) -----------------
__global__ void convW_kernel(const float4* __restrict__ W,
                             uint4* __restrict__ out, int n8) {
    int i = blockIdx.x * 1024 + threadIdx.x;
    #pragma unroll
    for (int u = 0; u < 4; u++, i += 256) {
        if (i < n8) {
            float4 a = W[2*i], b = W[2*i+1];
            __half2 h0 = __floats2half2_rn(a.x, a.y);
            __half2 h1 = __floats2half2_rn(a.z, a.w);
            __half2 h2 = __floats2half2_rn(b.x, b.y);
            __half2 h3 = __floats2half2_rn(b.z, b.w);
            uint4 o;
            o.x = *(unsigned*)&h0; o.y = *(unsigned*)&h1;
            o.z = *(unsigned*)&h2; o.w = *(unsigned*)&h3;
            out[i] = o;
        }
    }
}

// ---------------- block reduces ----------------
__device__ __forceinline__ float blockReduceSum(float v, float* sh) {
    int lane = threadIdx.x & 31, w = threadIdx.x >> 5;
    #pragma unroll
    for (int o = 16; o; o >>= 1) v += __shfl_xor_sync(0xffffffffu, v, o);
    if (lane == 0) sh[w] = v;
    __syncthreads();
    float r;
    if (threadIdx.x < 8) {
        r = sh[threadIdx.x];
        #pragma unroll
        for (int o = 4; o; o >>= 1) r += __shfl_xor_sync(0x000000ffu, r, o);
        if (threadIdx.x == 0) sh[0] = r;
    }
    __syncthreads();
    r = sh[0];
    __syncthreads();
    return r;
}
__device__ __forceinline__ float2 blockReduceSum2(float2 v, float2* sh) {
    int lane = threadIdx.x & 31, w = threadIdx.x >> 5;
    #pragma unroll
    for (int o = 16; o; o >>= 1) {
        v.x += __shfl_xor_sync(0xffffffffu, v.x, o);
        v.y += __shfl_xor_sync(0xffffffffu, v.y, o);
    }
    if (lane == 0) sh[w] = v;
    __syncthreads();
    float2 r;
    if (threadIdx.x < 8) {
        r = sh[threadIdx.x];
        #pragma unroll
        for (int o = 4; o; o >>= 1) {
            r.x += __shfl_xor_sync(0x000000ffu, r.x, o);
            r.y += __shfl_xor_sync(0x000000ffu, r.y, o);
        }
        if (threadIdx.x == 0) sh[0] = r;
    }
    __syncthreads();
    r = sh[0];
    __syncthreads();
    return r;
}

// ---------------- embedding gather + LN (ln0) ----------------
__global__ void embed_ln_kernel(const int* __restrict__ tokens,
                                const float* __restrict__ emb,
                                const float* __restrict__ w,
                                const float* __restrict__ b,
                                float* __restrict__ Y) {
    __shared__ float sh[8];
    int m = blockIdx.x;
    int tok = tokens[m];
    const float* xr = emb + (size_t)tok * Dd;
    int i0 = threadIdx.x, i1 = i0 + 256, i2 = i0 + 512;
    float v0 = xr[i0], v1 = xr[i1], v2 = xr[i2];
    float s = blockReduceSum(v0 + v1 + v2, sh);
    float mu = s * (1.0f / 768.0f);
    float c0 = v0 - mu, c1 = v1 - mu, c2 = v2 - mu;
    float ss = blockReduceSum(c0*c0 + c1*c1 + c2*c2, sh);
    float inv = rsqrtf(ss * (1.0f / 768.0f) + 1e-5f);
    float* yr = Y + (size_t)m * Dd;
    yr[i0] = c0 * inv * w[i0] + b[i0];
    yr[i1] = c1 * inv * w[i1] + b[i1];
    yr[i2] = c2 * inv * w[i2] + b[i2];
}

// ---------------- final LN with fused gated split-K reduction --------------
__global__ void ln_red_kernel(const float* __restrict__ X,
                              const float* __restrict__ g,
                              const float* __restrict__ q0,
                              const float* __restrict__ q1,
                              const float* __restrict__ q2,
                              const float* __restrict__ w,
                              const float* __restrict__ b,
                              float* __restrict__ Y) {
    __shared__ float sh[8];
    int m = blockIdx.x;
    size_t base = (size_t)m * Dd;
    int i0 = threadIdx.x, i1 = i0 + 256, i2 = i0 + 512;
    float v0 = X[base+i0] + g[base+i0] * (q0[base+i0] + q1[base+i0] + q2[base+i0]);
    float v1 = X[base+i1] + g[base+i1] * (q0[base+i1] + q1[base+i1] + q2[base+i1]);
    float v2 = X[base+i2] + g[base+i2] * (q0[base+i2] + q1[base+i2] + q2[base+i2]);
    float s = blockReduceSum(v0 + v1 + v2, sh);
    float mu = s * (1.0f / 768.0f);
    float c0 = v0 - mu, c1 = v1 - mu, c2 = v2 - mu;
    float ss = blockReduceSum(c0*c0 + c1*c1 + c2*c2, sh);
    float inv = rsqrtf(ss * (1.0f / 768.0f) + 1e-5f);
    float* yr = Y + base;
    yr[i0] = c0 * inv * w[i0] + b[i0];
    yr[i1] = c1 * inv * w[i1] + b[i1];
    yr[i2] = c2 * inv * w[i2] + b[i2];
}

// ------- fused [split-K reduce +] LN + token-shift mix -> fp16 -------------
// RED: 0 = none; 1 = x += q0+q1+q2; 2 = x += gate*(q0+q1+q2)
template<int NMIX, int RED>
__global__ void lnmix_kernel(const float* __restrict__ X,
                             const float* __restrict__ gate,
                             const float* __restrict__ q0,
                             const float* __restrict__ q1,
                             const float* __restrict__ q2,
                             float* __restrict__ Xout,
                             const float* __restrict__ w,
                             const float* __restrict__ b,
                             const float* __restrict__ mk,
                             const float* __restrict__ mv,
                             const float* __restrict__ mr,
                             __half* __restrict__ oh) {
    __shared__ float2 sh[8];
    int m = blockIdx.x;
    bool hasPrev = (m & (Tt - 1)) != 0;
    size_t bc = (size_t)m * Dd;
    size_t bp = bc - Dd;

    float cur[3], prv[3];
    #pragma unroll
    for (int q = 0; q < 3; q++) {
        int i = threadIdx.x + q * 256;
        float v = X[bc + i];
        if (RED == 1) v += q0[bc+i] + q1[bc+i] + q2[bc+i];
        else if (RED == 2) v += gate[bc+i] * (q0[bc+i] + q1[bc+i] + q2[bc+i]);
        if (RED) Xout[bc + i] = v;
        cur[q] = v;
        float p = 0.0f;
        if (hasPrev) {
            p = X[bp + i];
            if (RED == 1) p += q0[bp+i] + q1[bp+i] + q2[bp+i];
            else if (RED == 2) p += gate[bp+i] * (q0[bp+i] + q1[bp+i] + q2[bp+i]);
        }
        prv[q] = p;
    }

    float2 s = blockReduceSum2(make_float2(cur[0]+cur[1]+cur[2], prv[0]+prv[1]+prv[2]), sh);
    float muc = s.x * (1.0f / 768.0f), mup = s.y * (1.0f / 768.0f);
    float cc[3], pc[3];
    #pragma unroll
    for (int q = 0; q < 3; q++) { cc[q] = cur[q] - muc; pc[q] = prv[q] - mup; }
    float2 ss = blockReduceSum2(make_float2(cc[0]*cc[0]+cc[1]*cc[1]+cc[2]*cc[2],
                                            pc[0]*pc[0]+pc[1]*pc[1]+pc[2]*pc[2]), sh);
    float invc = rsqrtf(ss.x * (1.0f / 768.0f) + 1e-5f);
    float invp = rsqrtf(ss.y * (1.0f / 768.0f) + 1e-5f);

    #pragma unroll
    for (int q = 0; q < 3; q++) {
        int i = threadIdx.x + q * 256;
        float cv = cc[q] * invc * w[i] + b[i];
        float pv = hasPrev ? (pc[q] * invp * w[i] + b[i]) : 0.0f;
        float a = mk[i];
        oh[bc + i] = __float2half(cv * a + pv * (1.0f - a));
        if (NMIX == 3) {
            float c = mv[i];
            oh[MD + bc + i] = __float2half(cv * c + pv * (1.0f - c));
        }
        float e = mr[i];
        int slot = (NMIX == 3) ? 2 : 1;
        oh[slot * MD + bc + i] = __float2half(cv * e + pv * (1.0f - e));
    }
}

// ---------------- WKV sequential recurrence (per-channel) ----------------
__global__ void wkv_kernel(const float* __restrict__ k,
                           const float* __restrict__ v,
                           const float* __restrict__ r,
                           const float* __restrict__ tf,
                           const float* __restrict__ td,
                           __half* __restrict__ oh) {
    int ch = blockIdx.x * 32 + threadIdx.x;
    int b = ch / Dd, d = ch % Dd;
    float tfd = tf[d], tdd = td[d];
    float aa = 0.0f, bb = 0.0f, pp = -1e30f;
    size_t base = (size_t)b * Tt * Dd + d;
    float kb[2], vb[2], rb[2];
    kb[0] = k[base];        vb[0] = v[base];        rb[0] = r[base];
    kb[1] = k[base + Dd];   vb[1] = v[base + Dd];   rb[1] = r[base + Dd];
    for (int t = 0; t < Tt; t++) {
        float kc = kb[t & 1], vc = vb[t & 1], rc = rb[t & 1];
        if (t + 2 < Tt) {
            size_t nb = base + (size_t)(t + 2) * Dd;
            kb[t & 1] = k[nb]; vb[t & 1] = v[nb]; rb[t & 1] = r[nb];
        }
        float ww = tfd + kc;
        float p  = fmaxf(pp, ww);
        float e1 = __expf(pp - p);
        float e2 = __expf(ww - p);
        float wkv = __fdividef(e1 * aa + e2 * vc, e1 * bb + e2);
        float sr = __fdividef(1.0f, 1.0f + __expf(-rc));
        oh[base + (size_t)t * Dd] = __float2half(sr * wkv);
        float ww2 = pp + tdd;
        float p2  = fmaxf(ww2, kc);
        float e1b = __expf(ww2 - p2);
        float e2b = __expf(kc - p2);
        aa = e1b * aa + e2b * vc;
        bb = e1b * bb + e2b;
        pp = p2;
    }
}

// ---------------- tensor-core GEMM: fp16 x fp16[K,N], fp32 acc -------------
// A: [M,lda] fp16 row-major. W: [K,ldb] fp16 row-major (N contiguous).
// BM=64, BN=128, BK=32; 256 threads = 8 warps (2m x 4n), warp tile 32x32.
// Small tile -> 288-384 CTA grids -> ~2 CTAs/SM co-residency on 148 SMs.
// epi: 0 = store fp32; 2 = sqrelu -> fp16 (staged); 3 = sigmoid -> fp32
struct GArg {
    const __half *A, *W;
    float* C;
    __half* C2;
    int Ng, Kg, kOff, lda, ldb, epi;
};
struct GPack { GArg g[4]; };

#define BM 64
#define BN 128
#define BK 32
#define AST 40    // A row stride (halves)
#define BST 136   // B row stride (halves)

struct Stage {
    __half Ah[BM][AST];   // 5120 B
    __half Bw[BK][BST];   // 8704 B
};
// 3 stages = 41472 B; C staging (epi2) = 64*132*4 = 33792 B
#define GSMEM 41472

__global__ __launch_bounds__(256, 3)
void gemm_h(GPack pk) {
    GArg ga = pk.g[blockIdx.z];
    const int n0 = blockIdx.x * BN;
    if (n0 >= ga.Ng) return;

    extern __shared__ __align__(16) char smraw[];
    Stage* st = reinterpret_cast<Stage*>(smraw);
    float (*Csm)[BN + 4] = reinterpret_cast<float(*)[BN + 4]>(smraw);

    const int tid = threadIdx.x;
    const int wid = tid >> 5;
    const int wm = wid & 1;        // 0..1 -> 32 rows each
    const int wn = wid >> 1;       // 0..3 -> 32 cols each
    const int m0 = blockIdx.y * BM;

    const int ar = tid >> 2;           // 0..63
    const int ac = (tid & 3) * 8;      // 0,8,16,24
    const int br = tid >> 3;           // 0..31
    const int bc = (tid & 7) * 16;     // 0..112

    const __half* pA = ga.A + (size_t)(m0 + ar) * ga.lda + ga.kOff + ac;
    const __half* pW = ga.W + (size_t)(ga.kOff + br) * ga.ldb + n0 + bc;
    const size_t wstep = (size_t)ga.ldb;

    wmma::fragment<wmma::accumulator, 16, 16, 16, float> acc[2][2];
    #pragma unroll
    for (int i = 0; i < 2; i++)
        #pragma unroll
        for (int j = 0; j < 2; j++)
            wmma::fill_fragment(acc[i][j], 0.0f);

    const int nk = ga.Kg / BK;

    auto issue = [&](int s, int c) {
        int k0 = c * BK;
        cpa16(&st[s].Ah[ar][ac], pA + k0);
        cpa16(&st[s].Bw[br][bc],     pW + (size_t)k0 * wstep);
        cpa16(&st[s].Bw[br][bc + 8], pW + (size_t)k0 * wstep + 8);
        cp_commit();
    };

    issue(0, 0);
    if (nk > 1) issue(1, 1);

    for (int c = 0; c < nk; c++) {
        if (c + 1 < nk) cp_wait<1>(); else cp_wait<0>();
        __syncthreads();
        if (c + 2 < nk) issue((c + 2) % 3, c + 2);

        Stage& S = st[c % 3];
        #pragma unroll
        for (int kk = 0; kk < BK; kk += 16) {
            wmma::fragment<wmma::matrix_b, 16, 16, 16, __half, wmma::row_major> bf[2];
            #pragma unroll
            for (int j = 0; j < 2; j++)
                wmma::load_matrix_sync(bf[j], &S.Bw[kk][wn * 32 + j * 16], BST);

            wmma::fragment<wmma::matrix_a, 16, 16, 16, __half, wmma::row_major> af[2];
            #pragma unroll
            for (int i = 0; i < 2; i++)
                wmma::load_matrix_sync(af[i], &S.Ah[wm * 32 + i * 16][kk], AST);
            #pragma unroll
            for (int i = 0; i < 2; i++)
                #pragma unroll
                for (int j = 0; j < 2; j++)
                    wmma::mma_sync(acc[i][j], af[i], bf[j], acc[i][j]);
        }
    }

    const int Ng = ga.Ng, epi = ga.epi;

    if (epi == 2) {
        // staged epilogue (fp16 sqrelu out)
        __syncthreads();
        #pragma unroll
        for (int i = 0; i < 2; i++)
            #pragma unroll
            for (int j = 0; j < 2; j++)
                wmma::store_matrix_sync(&Csm[wm * 32 + i * 16][wn * 32 + j * 16],
                                        acc[i][j], BN + 4, wmma::mem_row_major);
        __syncthreads();
        const int ecol = tid & 127;
        const int erow = tid >> 7;
        #pragma unroll
        for (int i = 0; i < 32; i++) {
            int rr = i * 2 + erow;
            size_t idx = (size_t)(m0 + rr) * Ng + n0 + ecol;
            float t0 = fmaxf(Csm[rr][ecol], 0.0f);
            ga.C2[idx] = __float2half(t0 * t0);
        }
    } else {
        // direct fragment store (fp32 / sigmoid)
        if (epi == 3) {
            #pragma unroll
            for (int i = 0; i < 2; i++)
                #pragma unroll
                for (int j = 0; j < 2; j++)
                    #pragma unroll
                    for (int e = 0; e < acc[i][j].num_elements; e++)
                        acc[i][j].x[e] = __fdividef(1.0f, 1.0f + __expf(-acc[i][j].x[e]));
        }
        #pragma unroll
        for (int i = 0; i < 2; i++)
            #pragma unroll
            for (int j = 0; j < 2; j++)
                wmma::store_matrix_sync(
                    ga.C + (size_t)(m0 + wm * 32 + i * 16) * Ng + n0 + wn * 32 + j * 16,
                    acc[i][j], Ng, wmma::mem_row_major);
    }
}

// ---------------- host launcher ----------------
extern "C" void kernel_launch(void* const* d_in, const int* in_sizes, int n_in,
                              void* d_out, int out_size) {
    const int*   tokens     = (const int*)  d_in[0];
    const float* emb        = (const float*)d_in[1];
    const float* ln0_w      = (const float*)d_in[2];
    const float* ln0_b      = (const float*)d_in[3];
    const float* ln1_w      = (const float*)d_in[4];
    const float* ln1_b      = (const float*)d_in[5];
    const float* ln2_w      = (const float*)d_in[6];
    const float* ln2_b      = (const float*)d_in[7];
    const float* att_mix_k  = (const float*)d_in[8];
    const float* att_mix_v  = (const float*)d_in[9];
    const float* att_mix_r  = (const float*)d_in[10];
    const float* time_first = (const float*)d_in[11];
    const float* time_decay = (const float*)d_in[12];
    const float* att_Wk     = (const float*)d_in[13];
    const float* att_Wv     = (const float*)d_in[14];
    const float* att_Wr     = (const float*)d_in[15];
    const float* att_Wo     = (const float*)d_in[16];
    const float* ffn_mix_k  = (const float*)d_in[17];
    const float* ffn_mix_r  = (const float*)d_in[18];
    const float* ffn_Wk     = (const float*)d_in[19];
    const float* ffn_Wv     = (const float*)d_in[20];
    const float* ffn_Wr     = (const float*)d_in[21];
    const float* lnout_w    = (const float*)d_in[22];
    const float* lnout_b    = (const float*)d_in[23];
    float* out = (float*)d_out;

    float *xa, *xb, *kvr, *r2, *part;
    __half *mixh, *rwkvh, *hh, *w16;
    cudaGetSymbolAddress((void**)&xa,    g_x);
    cudaGetSymbolAddress((void**)&xb,    g_x2);
    cudaGetSymbolAddress((void**)&kvr,   g_kvr);
    cudaGetSymbolAddress((void**)&r2,    g_r2);
    cudaGetSymbolAddress((void**)&part,  g_part);
    cudaGetSymbolAddress((void**)&mixh,  g_mixh);
    cudaGetSymbolAddress((void**)&rwkvh, g_rwkvh);
    cudaGetSymbolAddress((void**)&hh,    g_hh);
    cudaGetSymbolAddress((void**)&w16,   g_w);

    cudaFuncSetAttribute(gemm_h, cudaFuncAttributeMaxDynamicSharedMemorySize, GSMEM);

    // ---- streaming convert: W fp32 [K,N] -> fp16 [K,N] ----
    auto conv = [&](const float* W, size_t off, int n) {
        int n8 = n / 8;
        convW_kernel<<<(n8 + 1023) / 1024, 256>>>((const float4*)W, (uint4*)(w16 + off), n8);
    };
    conv(att_Wk, OFF_WK, NDD);
    conv(att_Wv, OFF_WV, NDD);
    conv(att_Wr, OFF_WR, NDD);
    conv(att_Wo, OFF_WO, NDD);
    conv(ffn_Wk, OFF_FK, NDF);
    conv(ffn_Wv, OFF_FV, NDF);
    conv(ffn_Wr, OFF_FR, NDD);

    // x(a) = LN0(emb[tokens])
    embed_ln_kernel<<<MM, 256>>>(tokens, emb, ln0_w, ln0_b, xa);

    for (int l = 0; l < Ll; l++) {
        // ---- time mixing: [gated FV reduce +] LN1 + mix3 ----
        if (l == 0) {
            lnmix_kernel<3, 0><<<MM, 256>>>(xa, nullptr, nullptr, nullptr, nullptr, nullptr,
                                            ln1_w, ln1_b,
                                            att_mix_k, att_mix_v, att_mix_r, mixh);
        } else {
            lnmix_kernel<3, 2><<<MM, 256>>>(xb, r2, part, part + MD, part + 2 * MD, xa,
                                            ln1_w + l * Dd, ln1_b + l * Dd,
                                            att_mix_k + l * Dd, att_mix_v + l * Dd,
                                            att_mix_r + l * Dd, mixh);
        }
        // k/v/r = mix @ {Wk,Wv,Wr}
        {
            GPack pk{};
            for (int z = 0; z < 3; z++) {
                pk.g[z].A = mixh + z * MD;
                size_t wo = (z == 0 ? OFF_WK : z == 1 ? OFF_WV : OFF_WR) + (size_t)l * Dd * Dd;
                pk.g[z].W = w16 + wo;
                pk.g[z].C = kvr + z * MD;
                pk.g[z].Ng = Dd; pk.g[z].Kg = Dd; pk.g[z].kOff = 0;
                pk.g[z].lda = Dd; pk.g[z].ldb = Dd; pk.g[z].epi = 0;
            }
            gemm_h<<<dim3(Dd / BN, MM / BM, 3), 256, GSMEM>>>(pk);
        }
        // sequential WKV
        wkv_kernel<<<(Bb * Dd) / 32, 32>>>(kvr, kvr + MD, kvr + 2 * MD,
                                           time_first + l * Dd, time_decay + l * Dd, rwkvh);
        // Wo GEMM, split-K=3 -> partials
        {
            GPack pk{};
            for (int z = 0; z < 3; z++) {
                pk.g[z].A = rwkvh;
                pk.g[z].W = w16 + OFF_WO + (size_t)l * Dd * Dd;
                pk.g[z].C = part + z * MD;
                pk.g[z].Ng = Dd; pk.g[z].Kg = Dd / 3; pk.g[z].kOff = z * (Dd / 3);
                pk.g[z].lda = Dd; pk.g[z].ldb = Dd; pk.g[z].epi = 0;
            }
            gemm_h<<<dim3(Dd / BN, MM / BM, 3), 256, GSMEM>>>(pk);
        }
        // ---- channel mixing: Wo reduce + LN2 + mix2 (xa + parts -> xb) ----
        lnmix_kernel<2, 1><<<MM, 256>>>(xa, nullptr, part, part + MD, part + 2 * MD, xb,
                                        ln2_w + l * Dd, ln2_b + l * Dd,
                                        ffn_mix_k + l * Dd, nullptr, ffn_mix_r + l * Dd, mixh);
        // FK: h = sqrelu(xk2 @ ffn_Wk) -> fp16
        {
            GPack pk{};
            pk.g[0].A = mixh;
            pk.g[0].W = w16 + OFF_FK + (size_t)l * Dd * Ff;
            pk.g[0].C2 = hh;
            pk.g[0].Ng = Ff; pk.g[0].Kg = Dd; pk.g[0].kOff = 0;
            pk.g[0].lda = Dd; pk.g[0].ldb = Ff; pk.g[0].epi = 2;
            gemm_h<<<dim3(Ff / BN, MM / BM, 1), 256, GSMEM>>>(pk);
        }
        // FV split-K=3 (z=0..2) batched with FR sigmoid (z=3)
        {
            GPack pk{};
            for (int z = 0; z < 3; z++) {
                pk.g[z].A = hh;
                pk.g[z].W = w16 + OFF_FV + (size_t)l * Ff * Dd;
                pk.g[z].C = part + z * MD;
                pk.g[z].Ng = Dd; pk.g[z].Kg = Ff / 3; pk.g[z].kOff = z * (Ff / 3);
                pk.g[z].lda = Ff; pk.g[z].ldb = Dd; pk.g[z].epi = 0;
            }
            pk.g[3].A = mixh + MD;
            pk.g[3].W = w16 + OFF_FR + (size_t)l * Dd * Dd;
            pk.g[3].C = r2;
            pk.g[3].Ng = Dd; pk.g[3].Kg = Dd; pk.g[3].kOff = 0;
            pk.g[3].lda = Dd; pk.g[3].ldb = Dd; pk.g[3].epi = 3;
            gemm_h<<<dim3(Dd / BN, MM / BM, 4), 256, GSMEM>>>(pk);
        }
    }

    // out = LN_out(xb + r2*(parts))
    ln_red_kernel<<<MM, 256>>>(xb, r2, part, part + MD, part + 2 * MD,
                               lnout_w, lnout_b, out);
}